// round 1
// baseline (speedup 1.0000x reference)
#include <cuda_runtime.h>
#include <math.h>

#define N_ 4096
#define F_ 512
#define D_ 64
#define H_ 4
#define M_ 2
#define ALPHA_ 0.2f

// ---- scratch (device globals: no allocation allowed) ----
__device__ float g_Wh[(size_t)H_ * N_ * D_];           // [h][n][d]  4 MB
__device__ float g_s1[H_ * N_], g_s2[H_ * N_];
__device__ float g_E1[H_ * N_], g_E1a[H_ * N_];
__device__ float g_E2[H_ * N_], g_E2a[H_ * N_];
__device__ float g_Z[(size_t)M_ * N_ * H_ * D_];       // [m][n][h*D+d]  8 MB

// ============================================================
// Kernel 1: Wh[h] = x @ W[h]   ([4096,512] @ [512,64] per head)
// 64x64 tile per CTA, K-chunks of 32, 4x4 register tiles.
// ============================================================
__global__ __launch_bounds__(256) void wh_gemm(const float* __restrict__ x,
                                               const float* __restrict__ W) {
    __shared__ float xs[64][33];
    __shared__ float ws[32][65];
    const int h = blockIdx.y;
    const int i0 = blockIdx.x * 64;
    const int tid = threadIdx.x;
    const int tx = tid & 15, ty = tid >> 4;
    float C[4][4] = {};
    const float* Wp = W + (size_t)h * F_ * D_;

    for (int k0 = 0; k0 < F_; k0 += 32) {
        for (int t = tid; t < 64 * 32; t += 256)
            xs[t >> 5][t & 31] = x[(size_t)(i0 + (t >> 5)) * F_ + k0 + (t & 31)];
        for (int t = tid; t < 32 * 64; t += 256)
            ws[t >> 6][t & 63] = Wp[(size_t)(k0 + (t >> 6)) * D_ + (t & 63)];
        __syncthreads();
#pragma unroll 8
        for (int k = 0; k < 32; k++) {
            float a[4], b[4];
#pragma unroll
            for (int r = 0; r < 4; r++) a[r] = xs[ty * 4 + r][k];
#pragma unroll
            for (int c = 0; c < 4; c++) b[c] = ws[k][tx * 4 + c];
#pragma unroll
            for (int r = 0; r < 4; r++)
#pragma unroll
                for (int c = 0; c < 4; c++) C[r][c] += a[r] * b[c];
        }
        __syncthreads();
    }
#pragma unroll
    for (int r = 0; r < 4; r++)
#pragma unroll
        for (int c = 0; c < 4; c++)
            g_Wh[((size_t)h * N_ + i0 + ty * 4 + r) * D_ + tx * 4 + c] = C[r][c];
}

// ============================================================
// Kernel 2: s1 = Wh@a1, s2 = Wh@a2, and exp tables.
// One warp per (h,n) row.
// ============================================================
__global__ __launch_bounds__(256) void se_kernel(const float* __restrict__ a1,
                                                 const float* __restrict__ a2) {
    const int warp = (blockIdx.x * blockDim.x + threadIdx.x) >> 5;
    const int lane = threadIdx.x & 31;
    if (warp >= H_ * N_) return;
    const int h = warp / N_;
    const float* row = g_Wh + (size_t)warp * D_;
    float v0 = row[lane], v1 = row[lane + 32];
    float p1 = v0 * a1[h * D_ + lane] + v1 * a1[h * D_ + lane + 32];
    float p2 = v0 * a2[h * D_ + lane] + v1 * a2[h * D_ + lane + 32];
#pragma unroll
    for (int o = 16; o; o >>= 1) {
        p1 += __shfl_xor_sync(0xffffffffu, p1, o);
        p2 += __shfl_xor_sync(0xffffffffu, p2, o);
    }
    if (lane == 0) {
        g_s1[warp] = p1;
        g_s2[warp] = p2;
        g_E1[warp]  = expf(p1);
        g_E1a[warp] = expf(ALPHA_ * p1);
        g_E2[warp]  = expf(p2);
        g_E2a[warp] = expf(ALPHA_ * p2);
    }
}

// ============================================================
// Kernel 3: fused masked-attention. One CTA = (m, h, 64-row tile).
// exp(lrelu(s1+s2)) = sel(E1*E2, E1a*E2a); one pass over j:
//   num[i,d] += w * Wh[j,d];  den[i] += w
// Epilogue: Z[m][i][h*D+d] = num/den   (elu + sum-over-m done later)
// ============================================================
__global__ __launch_bounds__(256) void att_kernel(const int* __restrict__ adj) {
    __shared__ float sw[64][65];       // w tile [i][j]
    __shared__ float sv[64][68];       // Wh tile [j][d], padded for float4
    __shared__ float s1s[64], e1s[64], e1as[64];
    __shared__ float s2s[64], e2s[64], e2as[64];
    __shared__ float den[64];

    const int i0 = blockIdx.x * 64;
    const int h  = blockIdx.y;
    const int m  = blockIdx.z;
    const int tid = threadIdx.x;
    const int tx = tid & 15, ty = tid >> 4;

    if (tid < 64) {
        int g = h * N_ + i0 + tid;
        s1s[tid] = g_s1[g];
        e1s[tid] = g_E1[g];
        e1as[tid] = g_E1a[g];
        den[tid] = 0.f;
    }
    float C[4][4] = {};
    const int* adjm = adj + (size_t)m * N_ * N_;

    for (int j0 = 0; j0 < N_; j0 += 64) {
        __syncthreads();   // prev-iter readers of sv/s2s done
        if (tid < 64) {
            int g = h * N_ + j0 + tid;
            s2s[tid] = g_s2[g];
            e2s[tid] = g_E2[g];
            e2as[tid] = g_E2a[g];
        }
        // load Wh tile [64 j][64 d] (vectorized)
        for (int t = tid; t < 64 * 16; t += 256) {
            int r = t >> 4, c4 = t & 15;
            float4 v = reinterpret_cast<const float4*>(
                g_Wh + ((size_t)h * N_ + j0 + r) * D_)[c4];
            reinterpret_cast<float4*>(&sv[r][0])[c4] = v;
        }
        __syncthreads();
        // w tile generation
        const int jl = tid & 63;
        const int ib = tid >> 6;
#pragma unroll
        for (int rr = 0; rr < 16; rr++) {
            int il = rr * 4 + ib;
            int aj = adjm[(size_t)(i0 + il) * N_ + j0 + jl];
            float s = s1s[il] + s2s[jl];
            float w = 0.f;
            if (aj) w = (s > 0.f) ? e1s[il] * e2s[jl] : e1as[il] * e2as[jl];
            sw[il][jl] = w;
        }
        __syncthreads();
        // row sums (2 warps) -- others proceed to GEMM
        if (tid < 64) {
            float rs = 0.f;
#pragma unroll 8
            for (int jj = 0; jj < 64; jj++) rs += sw[tid][jj];
            den[tid] += rs;
        }
        // GEMM: C[i][d] += w[i][k] * V[k][d]
#pragma unroll 8
        for (int k = 0; k < 64; k++) {
            float a[4];
#pragma unroll
            for (int r = 0; r < 4; r++) a[r] = sw[ty * 4 + r][k];
            float4 b = *reinterpret_cast<const float4*>(&sv[k][tx * 4]);
            C[0][0] += a[0] * b.x; C[0][1] += a[0] * b.y; C[0][2] += a[0] * b.z; C[0][3] += a[0] * b.w;
            C[1][0] += a[1] * b.x; C[1][1] += a[1] * b.y; C[1][2] += a[1] * b.z; C[1][3] += a[1] * b.w;
            C[2][0] += a[2] * b.x; C[2][1] += a[2] * b.y; C[2][2] += a[2] * b.z; C[2][3] += a[2] * b.w;
            C[3][0] += a[3] * b.x; C[3][1] += a[3] * b.y; C[3][2] += a[3] * b.z; C[3][3] += a[3] * b.w;
        }
    }
    __syncthreads();
#pragma unroll
    for (int r = 0; r < 4; r++) {
        float dinv = 1.f / den[ty * 4 + r];
        float4 o;
        o.x = C[r][0] * dinv; o.y = C[r][1] * dinv;
        o.z = C[r][2] * dinv; o.w = C[r][3] * dinv;
        size_t base = ((size_t)m * N_ + i0 + ty * 4 + r) * (H_ * D_) + h * D_ + tx * 4;
        *reinterpret_cast<float4*>(&g_Z[base]) = o;
    }
}

// ============================================================
// Kernel 4: out[n,f] = elu(Z[0,n,f]) + elu(Z[1,n,f])
// (semantic-attention softmax over a singleton axis => beta == 1)
// ============================================================
__device__ __forceinline__ float elu1(float v) {
    return v > 0.f ? v : expm1f(v);
}
__global__ __launch_bounds__(256) void combine_kernel(float* __restrict__ out) {
    int idx = blockIdx.x * blockDim.x + threadIdx.x;
    const int total = N_ * H_ * D_;
    if (idx < total) {
        float z0 = g_Z[idx];
        float z1 = g_Z[(size_t)total + idx];
        out[idx] = elu1(z0) + elu1(z1);
    }
}

extern "C" void kernel_launch(void* const* d_in, const int* in_sizes, int n_in,
                              void* d_out, int out_size) {
    const float* x  = (const float*)d_in[0];
    const int*   adj = (const int*)d_in[1];
    const float* W  = (const float*)d_in[2];
    const float* a1 = (const float*)d_in[3];
    const float* a2 = (const float*)d_in[4];
    // d_in[5..7] (Ws, bs, q_sem) are dead code: softmax over singleton axis -> beta == 1
    float* out = (float*)d_out;

    wh_gemm<<<dim3(N_ / 64, H_), 256>>>(x, W);
    se_kernel<<<(H_ * N_) / 8, 256>>>(a1, a2);
    att_kernel<<<dim3(N_ / 64, H_, M_), 256>>>(adj);
    combine_kernel<<<(N_ * H_ * D_ + 255) / 256, 256>>>(out);
}

// round 4
// speedup vs baseline: 1.6014x; 1.6014x over previous
#include <cuda_runtime.h>
#include <math.h>
#include <cstdint>

#define N_ 4096
#define F_ 512
#define D_ 64
#define H_ 4
#define M_ 2
#define ALPHA_ 0.2f

// ---- scratch (device globals: no allocation allowed) ----
__device__ float g_Wh[(size_t)H_ * N_ * D_];           // [h][n][d]
__device__ float g_s1[H_ * N_], g_s2[H_ * N_];
__device__ float g_E1[H_ * N_], g_E1a[H_ * N_];
__device__ float g_E2[H_ * N_], g_E2a[H_ * N_];
__device__ float g_Z[(size_t)M_ * N_ * H_ * D_];       // [m][n][h*D+d]

__device__ __forceinline__ uint32_t f2tf32(float f) {
    uint32_t u;
    asm("cvt.rna.tf32.f32 %0, %1;" : "=r"(u) : "f"(f));
    return u;
}

// ============================================================
// Kernel 1: Wh[h] = x @ W[h]   (fp32, exact)
// ============================================================
__global__ __launch_bounds__(256) void wh_gemm(const float* __restrict__ x,
                                               const float* __restrict__ W) {
    __shared__ float xs[64][33];
    __shared__ float ws[32][65];
    const int h = blockIdx.y;
    const int i0 = blockIdx.x * 64;
    const int tid = threadIdx.x;
    const int tx = tid & 15, ty = tid >> 4;
    float C[4][4] = {};
    const float* Wp = W + (size_t)h * F_ * D_;

    for (int k0 = 0; k0 < F_; k0 += 32) {
        for (int t = tid; t < 64 * 32; t += 256)
            xs[t >> 5][t & 31] = x[(size_t)(i0 + (t >> 5)) * F_ + k0 + (t & 31)];
        for (int t = tid; t < 32 * 64; t += 256)
            ws[t >> 6][t & 63] = Wp[(size_t)(k0 + (t >> 6)) * D_ + (t & 63)];
        __syncthreads();
#pragma unroll 8
        for (int k = 0; k < 32; k++) {
            float a[4], b[4];
#pragma unroll
            for (int r = 0; r < 4; r++) a[r] = xs[ty * 4 + r][k];
#pragma unroll
            for (int c = 0; c < 4; c++) b[c] = ws[k][tx * 4 + c];
#pragma unroll
            for (int r = 0; r < 4; r++)
#pragma unroll
                for (int c = 0; c < 4; c++) C[r][c] += a[r] * b[c];
        }
        __syncthreads();
    }
#pragma unroll
    for (int r = 0; r < 4; r++)
#pragma unroll
        for (int c = 0; c < 4; c++)
            g_Wh[((size_t)h * N_ + i0 + ty * 4 + r) * D_ + tx * 4 + c] = C[r][c];
}

// ============================================================
// Kernel 2: s1/s2 and factorized exp tables
// ============================================================
__global__ __launch_bounds__(256) void se_kernel(const float* __restrict__ a1,
                                                 const float* __restrict__ a2) {
    const int warp = (blockIdx.x * blockDim.x + threadIdx.x) >> 5;
    const int lane = threadIdx.x & 31;
    if (warp >= H_ * N_) return;
    const int h = warp / N_;
    const float* row = g_Wh + (size_t)warp * D_;
    float v0 = row[lane], v1 = row[lane + 32];
    float p1 = v0 * a1[h * D_ + lane] + v1 * a1[h * D_ + lane + 32];
    float p2 = v0 * a2[h * D_ + lane] + v1 * a2[h * D_ + lane + 32];
#pragma unroll
    for (int o = 16; o; o >>= 1) {
        p1 += __shfl_xor_sync(0xffffffffu, p1, o);
        p2 += __shfl_xor_sync(0xffffffffu, p2, o);
    }
    if (lane == 0) {
        g_s1[warp] = p1;  g_s2[warp] = p2;
        g_E1[warp]  = expf(p1);  g_E1a[warp] = expf(ALPHA_ * p1);
        g_E2[warp]  = expf(p2);  g_E2a[warp] = expf(ALPHA_ * p2);
    }
}

// ============================================================
// Kernel 3: masked attention via mma.sync tf32 (baseline PTX).
// CTA = (128-row i-tile, h, m), 128 threads / 4 warps.
// Warp w: rows wbase=32w .. +31 (2 m-frags), full d=64 (8 n-frags).
// A fragments generated in registers (adj + factorized exp);
// den accumulates the SAME tf32-rounded w values (consistency).
// ============================================================
__global__ __launch_bounds__(128) void att_mma(const int* __restrict__ adj) {
    __shared__ float4 tbl[64];          // (s2, e2, e2a, -) per j
    __shared__ float  sB[4096];         // B tile in fragment order (tf32 bits)
    __shared__ float  sden[128];

    const int i0 = blockIdx.x * 128;
    const int h  = blockIdx.y;
    const int m  = blockIdx.z;
    const int tid = threadIdx.x;
    const int wid = tid >> 5, lane = tid & 31;
    const int g = lane >> 2, tg = lane & 3;
    const int wbase = wid * 32;

    // per-thread row constants: q = mf*2+half -> row = wbase + g + 8q
    float s1v[4], e1v[4], e1av[4];
    const int* aptr[4];
    const int* adjm = adj + (size_t)m * N_ * N_;
#pragma unroll
    for (int q = 0; q < 4; q++) {
        int row = i0 + wbase + g + q * 8;
        int gg = h * N_ + row;
        s1v[q] = g_s1[gg]; e1v[q] = g_E1[gg]; e1av[q] = g_E1a[gg];
        aptr[q] = adjm + (size_t)row * N_ + tg;
    }

    float acc[2][8][4];
#pragma unroll
    for (int a = 0; a < 2; a++)
#pragma unroll
        for (int b = 0; b < 8; b++)
#pragma unroll
            for (int c = 0; c < 4; c++) acc[a][b][c] = 0.f;
    float den[4] = {0.f, 0.f, 0.f, 0.f};

    for (int jt = 0; jt < N_ / 64; jt++) {
        const int j0 = jt * 64;
        __syncthreads();
        if (tid < 64) {
            int gg = h * N_ + j0 + tid;
            tbl[tid] = make_float4(g_s2[gg], g_E2[gg], g_E2a[gg], 0.f);
        }
        // stage B = Wh[j0..j0+63][0..63] into fragment order, tf32-rounded.
        // element B[k][n]: ks=k>>3, reg=(k&7)>>2, lane=(n&7)*4+(k&3), nf=n>>3
        for (int t = tid; t < 2048; t += 128) {
            int k = t >> 5, n2 = t & 31;
            float2 v = *(const float2*)(g_Wh + ((size_t)(h * N_ + j0 + k)) * D_ + n2 * 2);
            uint32_t ux = f2tf32(v.x), uy = f2tf32(v.y);
            int ks = k >> 3, kr = k & 7, reg = kr >> 2;
            int n = n2 * 2;
            int off0 = ((ks * 8 + (n >> 3)) * 32 + ((n & 7) * 4 + (kr & 3))) * 2 + reg;
            n++;
            int off1 = ((ks * 8 + (n >> 3)) * 32 + ((n & 7) * 4 + (kr & 3))) * 2 + reg;
            ((uint32_t*)sB)[off0] = ux;
            ((uint32_t*)sB)[off1] = uy;
        }
        __syncthreads();

#pragma unroll
        for (int ks = 0; ks < 8; ks++) {
            float4 t0 = tbl[ks * 8 + tg];        // col c0 = ks*8+tg
            float4 t1 = tbl[ks * 8 + tg + 4];    // col c1 = c0+4
            uint32_t A[2][4];
#pragma unroll
            for (int mf = 0; mf < 2; mf++) {
#pragma unroll
                for (int half = 0; half < 2; half++) {
                    int q = mf * 2 + half;
                    int a0 = aptr[q][j0 + ks * 8];
                    int a1 = aptr[q][j0 + ks * 8 + 4];
                    float w0 = 0.f, w1 = 0.f;
                    if (a0) w0 = (s1v[q] + t0.x > 0.f) ? e1v[q] * t0.y : e1av[q] * t0.z;
                    if (a1) w1 = (s1v[q] + t1.x > 0.f) ? e1v[q] * t1.y : e1av[q] * t1.z;
                    uint32_t u0 = f2tf32(w0), u1 = f2tf32(w1);
                    A[mf][half]     = u0;   // a0/a1: col tg
                    A[mf][half + 2] = u1;   // a2/a3: col tg+4
                    den[q] += __uint_as_float(u0) + __uint_as_float(u1);
                }
            }
#pragma unroll
            for (int nf = 0; nf < 8; nf++) {
                float2 b = *(const float2*)(sB + ((ks * 8 + nf) * 32 + lane) * 2);
                uint32_t b0 = __float_as_uint(b.x), b1 = __float_as_uint(b.y);
#pragma unroll
                for (int mf = 0; mf < 2; mf++) {
                    asm volatile(
                        "mma.sync.aligned.m16n8k8.row.col.f32.tf32.tf32.f32 "
                        "{%0,%1,%2,%3}, {%4,%5,%6,%7}, {%8,%9}, {%0,%1,%2,%3};"
                        : "+f"(acc[mf][nf][0]), "+f"(acc[mf][nf][1]),
                          "+f"(acc[mf][nf][2]), "+f"(acc[mf][nf][3])
                        : "r"(A[mf][0]), "r"(A[mf][1]), "r"(A[mf][2]), "r"(A[mf][3]),
                          "r"(b0), "r"(b1));
                }
            }
        }
    }

    // denominator: reduce over quad lanes (cols), stash per row
#pragma unroll
    for (int q = 0; q < 4; q++) {
        den[q] += __shfl_xor_sync(0xffffffffu, den[q], 1);
        den[q] += __shfl_xor_sync(0xffffffffu, den[q], 2);
    }
    if (tg == 0)
#pragma unroll
        for (int q = 0; q < 4; q++) sden[wbase + g + q * 8] = den[q];
    __syncwarp();

    // epilogue: divide, store Z[m][i][h*64+d]
#pragma unroll
    for (int mf = 0; mf < 2; mf++) {
        float d0 = 1.f / sden[wbase + mf * 16 + g];
        float d1 = 1.f / sden[wbase + mf * 16 + 8 + g];
        int r0 = i0 + wbase + mf * 16 + g;
        int r1 = r0 + 8;
#pragma unroll
        for (int nf = 0; nf < 8; nf++) {
            int col = h * D_ + nf * 8 + tg * 2;
            *(float2*)(g_Z + ((size_t)m * N_ + r0) * (H_ * D_) + col) =
                make_float2(acc[mf][nf][0] * d0, acc[mf][nf][1] * d0);
            *(float2*)(g_Z + ((size_t)m * N_ + r1) * (H_ * D_) + col) =
                make_float2(acc[mf][nf][2] * d1, acc[mf][nf][3] * d1);
        }
    }
}

// ============================================================
// Kernel 4: out = elu(Z[0]) + elu(Z[1])   (beta == 1)
// ============================================================
__device__ __forceinline__ float elu1(float v) { return v > 0.f ? v : expm1f(v); }
__global__ __launch_bounds__(256) void combine_kernel(float* __restrict__ out) {
    int idx = blockIdx.x * blockDim.x + threadIdx.x;
    const int total = N_ * H_ * D_;
    if (idx < total) {
        float z0 = g_Z[idx];
        float z1 = g_Z[(size_t)total + idx];
        out[idx] = elu1(z0) + elu1(z1);
    }
}

extern "C" void kernel_launch(void* const* d_in, const int* in_sizes, int n_in,
                              void* d_out, int out_size) {
    const float* x   = (const float*)d_in[0];
    const int*   adj = (const int*)d_in[1];
    const float* W   = (const float*)d_in[2];
    const float* a1  = (const float*)d_in[3];
    const float* a2  = (const float*)d_in[4];
    // d_in[5..7] (Ws, bs, q_sem) are dead: softmax over singleton axis -> beta == 1
    float* out = (float*)d_out;

    wh_gemm<<<dim3(N_ / 64, H_), 256>>>(x, W);
    se_kernel<<<(H_ * N_) / 8, 256>>>(a1, a2);
    att_mma<<<dim3(N_ / 128, H_, M_), 128>>>(adj);
    combine_kernel<<<(N_ * H_ * D_ + 255) / 256, 256>>>(out);
}

// round 5
// speedup vs baseline: 2.9409x; 1.8364x over previous
#include <cuda_runtime.h>
#include <math.h>
#include <cstdint>

#define N_ 4096
#define F_ 512
#define D_ 64
#define H_ 4
#define M_ 2
#define ALPHA_ 0.2f

// ---- device scratch (no allocation allowed) ----
__device__ float   g_Wh[(size_t)H_ * N_ * D_];                 // [h][n][d]
__device__ float   g_s1[H_ * N_], g_E1[H_ * N_], g_E1a[H_ * N_];
__device__ float4  g_tbl[H_ * N_];                             // (s2, e2, e2a, 0)
__device__ uint32_t g_adjbits[(size_t)M_ * N_ * (N_ / 32)];    // [m][row][word]
__device__ float   g_Bfrag[(size_t)H_ * (N_ / 64) * 4096];     // frag-ordered tf32 bits
__device__ float   g_Z[(size_t)M_ * N_ * H_ * D_];             // [m][n][h*D+d]

__device__ __forceinline__ uint32_t f2tf32(float f) {
    uint32_t u;
    asm("cvt.rna.tf32.f32 %0, %1;" : "=r"(u) : "f"(f));
    return u;
}
__device__ __forceinline__ uint32_t smem_u32(const void* p) {
    uint32_t a;
    asm("{ .reg .u64 t; cvta.to.shared.u64 t, %1; cvt.u32.u64 %0, t; }" : "=r"(a) : "l"(p));
    return a;
}
__device__ __forceinline__ void cp16(uint32_t dst, const void* src) {
    asm volatile("cp.async.cg.shared.global [%0], [%1], 16;" :: "r"(dst), "l"(src));
}
#define CP_COMMIT() asm volatile("cp.async.commit_group;" ::: "memory")
#define CP_WAIT1()  asm volatile("cp.async.wait_group 1;" ::: "memory")
#define CP_WAIT0()  asm volatile("cp.async.wait_group 0;" ::: "memory")

// ============================================================
// Kernel 0: pack adj into bitmask (warp ballots, coalesced)
// ============================================================
__global__ __launch_bounds__(256) void pack_adj(const int* __restrict__ adj) {
    const int r = (blockIdx.x * blockDim.x + threadIdx.x) >> 5;   // [m*N + row]
    const int lane = threadIdx.x & 31;
    if (r >= M_ * N_) return;
    const int* src = adj + (size_t)r * N_;
#pragma unroll 4
    for (int w = 0; w < N_ / 32; w++) {
        int a = src[w * 32 + lane];
        uint32_t msk = __ballot_sync(0xffffffffu, a != 0);
        if (lane == 0) g_adjbits[(size_t)r * (N_ / 32) + w] = msk;
    }
}

// ============================================================
// Kernel 1: Wh[h] = x @ W[h]   (fp32, exact)
// ============================================================
__global__ __launch_bounds__(256) void wh_gemm(const float* __restrict__ x,
                                               const float* __restrict__ W) {
    __shared__ float xs[64][33];
    __shared__ float ws[32][65];
    const int h = blockIdx.y;
    const int i0 = blockIdx.x * 64;
    const int tid = threadIdx.x;
    const int tx = tid & 15, ty = tid >> 4;
    float C[4][4] = {};
    const float* Wp = W + (size_t)h * F_ * D_;

    for (int k0 = 0; k0 < F_; k0 += 32) {
        for (int t = tid; t < 64 * 32; t += 256)
            xs[t >> 5][t & 31] = x[(size_t)(i0 + (t >> 5)) * F_ + k0 + (t & 31)];
        for (int t = tid; t < 32 * 64; t += 256)
            ws[t >> 6][t & 63] = Wp[(size_t)(k0 + (t >> 6)) * D_ + (t & 63)];
        __syncthreads();
#pragma unroll 8
        for (int k = 0; k < 32; k++) {
            float a[4], b[4];
#pragma unroll
            for (int r = 0; r < 4; r++) a[r] = xs[ty * 4 + r][k];
#pragma unroll
            for (int c = 0; c < 4; c++) b[c] = ws[k][tx * 4 + c];
#pragma unroll
            for (int r = 0; r < 4; r++)
#pragma unroll
                for (int c = 0; c < 4; c++) C[r][c] += a[r] * b[c];
        }
        __syncthreads();
    }
#pragma unroll
    for (int r = 0; r < 4; r++)
#pragma unroll
        for (int c = 0; c < 4; c++)
            g_Wh[((size_t)h * N_ + i0 + ty * 4 + r) * D_ + tx * 4 + c] = C[r][c];
}

// ============================================================
// Kernel 2: s1 tables + packed (s2,e2,e2a) float4 table
// ============================================================
__global__ __launch_bounds__(256) void se_kernel(const float* __restrict__ a1,
                                                 const float* __restrict__ a2) {
    const int warp = (blockIdx.x * blockDim.x + threadIdx.x) >> 5;
    const int lane = threadIdx.x & 31;
    if (warp >= H_ * N_) return;
    const int h = warp / N_;
    const float* row = g_Wh + (size_t)warp * D_;
    float v0 = row[lane], v1 = row[lane + 32];
    float p1 = v0 * a1[h * D_ + lane] + v1 * a1[h * D_ + lane + 32];
    float p2 = v0 * a2[h * D_ + lane] + v1 * a2[h * D_ + lane + 32];
#pragma unroll
    for (int o = 16; o; o >>= 1) {
        p1 += __shfl_xor_sync(0xffffffffu, p1, o);
        p2 += __shfl_xor_sync(0xffffffffu, p2, o);
    }
    if (lane == 0) {
        g_s1[warp] = p1;
        g_E1[warp]  = expf(p1);
        g_E1a[warp] = expf(ALPHA_ * p1);
        g_tbl[warp] = make_float4(p2, expf(p2), expf(ALPHA_ * p2), 0.f);
    }
}

// ============================================================
// Kernel 2b: pre-pack B = Wh tiles into mma fragment order (tf32)
// out float2 index o in [0,2048) per (h,jt) tile:
//   frag=o>>5, lane=o&31, ks=frag>>3, nf=frag&7,
//   n = nf*8 + (lane>>2), k0 = ks*8 + (lane&3), k1 = k0+4
// ============================================================
__global__ __launch_bounds__(128) void prep_B() {
    const int jt = blockIdx.x, h = blockIdx.y;
    const int j0 = jt * 64;
    float* dst = g_Bfrag + ((size_t)(h * (N_ / 64) + jt)) * 4096;
    const float* src = g_Wh + (size_t)h * N_ * D_;
#pragma unroll
    for (int it = 0; it < 16; it++) {
        int o = threadIdx.x + it * 128;
        int frag = o >> 5, lane = o & 31;
        int ks = frag >> 3, nf = frag & 7;
        int n = nf * 8 + (lane >> 2);
        int k0 = ks * 8 + (lane & 3);
        float v0 = src[(size_t)(j0 + k0) * D_ + n];
        float v1 = src[(size_t)(j0 + k0 + 4) * D_ + n];
        *(float2*)(dst + o * 2) = make_float2(__uint_as_float(f2tf32(v0)),
                                              __uint_as_float(f2tf32(v1)));
    }
}

// ============================================================
// Kernel 3: masked attention, mma.sync tf32.
// CTA = (128-row i-tile, h, m), 128 thr. Bitmask tile in SMEM,
// cp.async double-buffered prepacked B + tbl. Zero inner-loop LDG.
// ============================================================
#define OFF_B   67584            // bits: 128 rows * 132 words * 4B
#define OFF_T   (OFF_B + 32768)  // sB: 2 * 16KB
#define OFF_DEN (OFF_T + 2048)   // tbl: 2 * 1KB
#define SMEM_ATT (OFF_DEN + 512)

__global__ __launch_bounds__(128, 2) void att_mma() {
    extern __shared__ char dsm[];
    const uint32_t sb = smem_u32(dsm);

    const int i0 = blockIdx.x * 128;
    const int h  = blockIdx.y;
    const int m  = blockIdx.z;
    const int tid = threadIdx.x;
    const int wid = tid >> 5, lane = tid & 31;
    const int g = lane >> 2, tg = lane & 3;
    const int wbase = wid * 32;

    // ---- stage bitmask tile (group 0 part 1): 4096 uint4, coalesced
    {
        const uint4* bsrc = (const uint4*)(g_adjbits + ((size_t)m * N_ + i0) * (N_ / 32));
#pragma unroll
        for (int it = 0; it < 32; it++) {
            int q = tid + it * 128;
            int row = q >> 5, w4 = q & 31;
            cp16(sb + row * 528 + w4 * 16, bsrc + q);
        }
    }
    // ---- stage tile jt=0
    {
        const float4* bs = (const float4*)(g_Bfrag + ((size_t)(h * (N_ / 64))) * 4096);
#pragma unroll
        for (int r = 0; r < 8; r++) cp16(sb + OFF_B + (tid + r * 128) * 16, bs + tid + r * 128);
        if (tid < 64) cp16(sb + OFF_T + tid * 16, g_tbl + h * N_ + tid);
    }
    CP_COMMIT();

    // per-thread row constants
    float s1v[4], e1v[4], e1av[4];
#pragma unroll
    for (int q = 0; q < 4; q++) {
        int gg = h * N_ + i0 + wbase + g + q * 8;
        s1v[q] = g_s1[gg]; e1v[q] = g_E1[gg]; e1av[q] = g_E1a[gg];
    }

    float acc[2][8][4];
#pragma unroll
    for (int a = 0; a < 2; a++)
#pragma unroll
        for (int b = 0; b < 8; b++)
#pragma unroll
            for (int c = 0; c < 4; c++) acc[a][b][c] = 0.f;
    float den[4] = {0.f, 0.f, 0.f, 0.f};

    int buf = 0;
    for (int jt = 0; jt < N_ / 64; jt++) {
        if (jt + 1 < N_ / 64) {   // prefetch next tile into buf^1
            const float4* bs = (const float4*)(g_Bfrag +
                ((size_t)(h * (N_ / 64) + jt + 1)) * 4096);
            uint32_t dB = sb + OFF_B + (buf ^ 1) * 16384;
#pragma unroll
            for (int r = 0; r < 8; r++) cp16(dB + (tid + r * 128) * 16, bs + tid + r * 128);
            if (tid < 64)
                cp16(sb + OFF_T + (buf ^ 1) * 1024 + tid * 16,
                     g_tbl + h * N_ + (jt + 1) * 64 + tid);
            CP_COMMIT();
            CP_WAIT1();
        } else {
            CP_WAIT0();
        }
        __syncthreads();

        const float4* tb = (const float4*)(dsm + OFF_T + buf * 1024);
        const float*  Bp = (const float*)(dsm + OFF_B + buf * 16384);
        const uint32_t* bt = (const uint32_t*)dsm;

        uint32_t u0[4], u1[4];
#pragma unroll
        for (int q = 0; q < 4; q++) {
            int rl = wbase + g + q * 8;
            u0[q] = bt[rl * 132 + jt * 2];
            u1[q] = bt[rl * 132 + jt * 2 + 1];
        }
#pragma unroll
        for (int ks = 0; ks < 8; ks++) {
            float4 t0 = tb[ks * 8 + tg];
            float4 t1 = tb[ks * 8 + tg + 4];
            uint32_t A[2][4];
#pragma unroll
            for (int q = 0; q < 4; q++) {
                uint32_t uw = (ks < 4) ? u0[q] : u1[q];
                uint32_t b0 = (uw >> ((ks * 8 + tg) & 31)) & 1u;
                uint32_t b1 = (uw >> ((ks * 8 + tg + 4) & 31)) & 1u;
                float w0v = 0.f, w1v = 0.f;
                if (b0) w0v = (s1v[q] + t0.x > 0.f) ? e1v[q] * t0.y : e1av[q] * t0.z;
                if (b1) w1v = (s1v[q] + t1.x > 0.f) ? e1v[q] * t1.y : e1av[q] * t1.z;
                uint32_t x0 = f2tf32(w0v), x1 = f2tf32(w1v);
                A[q >> 1][q & 1]       = x0;
                A[q >> 1][(q & 1) + 2] = x1;
                den[q] += __uint_as_float(x0) + __uint_as_float(x1);
            }
#pragma unroll
            for (int nf = 0; nf < 8; nf++) {
                float2 b = *(const float2*)(Bp + ((ks * 8 + nf) * 32 + lane) * 2);
                uint32_t b0 = __float_as_uint(b.x), b1 = __float_as_uint(b.y);
#pragma unroll
                for (int mf = 0; mf < 2; mf++) {
                    asm volatile(
                        "mma.sync.aligned.m16n8k8.row.col.f32.tf32.tf32.f32 "
                        "{%0,%1,%2,%3}, {%4,%5,%6,%7}, {%8,%9}, {%0,%1,%2,%3};"
                        : "+f"(acc[mf][nf][0]), "+f"(acc[mf][nf][1]),
                          "+f"(acc[mf][nf][2]), "+f"(acc[mf][nf][3])
                        : "r"(A[mf][0]), "r"(A[mf][1]), "r"(A[mf][2]), "r"(A[mf][3]),
                          "r"(b0), "r"(b1));
                }
            }
        }
        buf ^= 1;
        __syncthreads();   // all reads of old buf done before next prefetch writes it
    }

    // denominator: reduce over quad lanes (cols)
    float* sden = (float*)(dsm + OFF_DEN);
#pragma unroll
    for (int q = 0; q < 4; q++) {
        den[q] += __shfl_xor_sync(0xffffffffu, den[q], 1);
        den[q] += __shfl_xor_sync(0xffffffffu, den[q], 2);
    }
    if (tg == 0)
#pragma unroll
        for (int q = 0; q < 4; q++) sden[wbase + g + q * 8] = den[q];
    __syncwarp();

    // epilogue: divide, store Z[m][i][h*64+d]
#pragma unroll
    for (int mf = 0; mf < 2; mf++) {
        float d0 = 1.f / sden[wbase + mf * 16 + g];
        float d1 = 1.f / sden[wbase + mf * 16 + 8 + g];
        int r0 = i0 + wbase + mf * 16 + g;
        int r1 = r0 + 8;
#pragma unroll
        for (int nf = 0; nf < 8; nf++) {
            int col = h * D_ + nf * 8 + tg * 2;
            *(float2*)(g_Z + ((size_t)m * N_ + r0) * (H_ * D_) + col) =
                make_float2(acc[mf][nf][0] * d0, acc[mf][nf][1] * d0);
            *(float2*)(g_Z + ((size_t)m * N_ + r1) * (H_ * D_) + col) =
                make_float2(acc[mf][nf][2] * d1, acc[mf][nf][3] * d1);
        }
    }
}

// ============================================================
// Kernel 4: out = elu(Z[0]) + elu(Z[1])   (beta == 1)
// ============================================================
__device__ __forceinline__ float elu1(float v) { return v > 0.f ? v : expm1f(v); }
__global__ __launch_bounds__(256) void combine_kernel(float* __restrict__ out) {
    int idx = blockIdx.x * blockDim.x + threadIdx.x;
    const int total = N_ * H_ * D_;
    if (idx < total) {
        float z0 = g_Z[idx];
        float z1 = g_Z[(size_t)total + idx];
        out[idx] = elu1(z0) + elu1(z1);
    }
}

extern "C" void kernel_launch(void* const* d_in, const int* in_sizes, int n_in,
                              void* d_out, int out_size) {
    const float* x   = (const float*)d_in[0];
    const int*   adj = (const int*)d_in[1];
    const float* W   = (const float*)d_in[2];
    const float* a1  = (const float*)d_in[3];
    const float* a2  = (const float*)d_in[4];
    // d_in[5..7] (Ws, bs, q_sem) are dead: softmax over singleton axis -> beta == 1
    float* out = (float*)d_out;

    cudaFuncSetAttribute(att_mma, cudaFuncAttributeMaxDynamicSharedMemorySize, SMEM_ATT);

    pack_adj<<<(M_ * N_) / 8, 256>>>(adj);
    wh_gemm<<<dim3(N_ / 64, H_), 256>>>(x, W);
    se_kernel<<<(H_ * N_) / 8, 256>>>(a1, a2);
    prep_B<<<dim3(N_ / 64, H_), 128>>>();
    att_mma<<<dim3(N_ / 128, H_, M_), 128, SMEM_ATT>>>();
    combine_kernel<<<(N_ * H_ * D_ + 255) / 256, 256>>>(out);
}

// round 7
// speedup vs baseline: 3.2019x; 1.0888x over previous
#include <cuda_runtime.h>
#include <cuda_fp16.h>
#include <math.h>
#include <cstdint>

#define N_ 4096
#define F_ 512
#define D_ 64
#define H_ 4
#define M_ 2
#define ALPHA_ 0.2f
#define L2E_ 1.44269504f

// ---- device scratch (no allocation allowed) ----
__device__ float   g_Wh[(size_t)H_ * N_ * D_];                 // [h][n][d]
__device__ float   g_s1[H_ * N_], g_E1[H_ * N_], g_E1a[H_ * N_];
__device__ float4  g_tbl[H_ * N_];                             // (s2, e2, e2a, 0)
__device__ float   g_S2M[H_];
__device__ uint32_t g_adjbits[(size_t)M_ * N_ * (N_ / 32)];    // [m][row][word]
__device__ uint2   g_Bf16[(size_t)H_ * (N_ / 64) * 1024];      // fp16 frag tiles (8KB/tile)
__device__ float   g_Z[(size_t)M_ * N_ * H_ * D_];             // [m][n][h*D+d]

__device__ __forceinline__ uint32_t smem_u32(const void* p) {
    uint32_t a;
    asm("{ .reg .u64 t; cvta.to.shared.u64 t, %1; cvt.u32.u64 %0, t; }" : "=r"(a) : "l"(p));
    return a;
}
__device__ __forceinline__ void cp16(uint32_t dst, const void* src) {
    asm volatile("cp.async.cg.shared.global [%0], [%1], 16;" :: "r"(dst), "l"(src));
}
#define CP_COMMIT() asm volatile("cp.async.commit_group;" ::: "memory")
#define CP_WAIT1()  asm volatile("cp.async.wait_group 1;" ::: "memory")
#define CP_WAIT0()  asm volatile("cp.async.wait_group 0;" ::: "memory")

// ============================================================
// Kernel 0: pack adj into bitmask
// ============================================================
__global__ __launch_bounds__(256) void pack_adj(const int* __restrict__ adj) {
    const int r = (blockIdx.x * blockDim.x + threadIdx.x) >> 5;
    const int lane = threadIdx.x & 31;
    if (r >= M_ * N_) return;
    const int* src = adj + (size_t)r * N_;
#pragma unroll 8
    for (int w = 0; w < N_ / 32; w++) {
        int a = src[w * 32 + lane];
        uint32_t msk = __ballot_sync(0xffffffffu, a != 0);
        if (lane == 0) g_adjbits[(size_t)r * (N_ / 32) + w] = msk;
    }
}

// ============================================================
// Kernel 1: Wh[h] = x @ W[h]  (fp32) + emit fp16 mma-frag tile
// CTA covers rows i0..i0+63 of head h == B tile jt=i0/64.
// ============================================================
__global__ __launch_bounds__(256) void wh_gemm(const float* __restrict__ x,
                                               const float* __restrict__ W) {
    __shared__ float xs[64][33];
    __shared__ float ws[32][65];
    __shared__ float sC[64][68];
    const int h = blockIdx.y;
    const int i0 = blockIdx.x * 64;
    const int tid = threadIdx.x;
    const int tx = tid & 15, ty = tid >> 4;
    float C[4][4] = {};
    const float* Wp = W + (size_t)h * F_ * D_;

    for (int k0 = 0; k0 < F_; k0 += 32) {
        for (int t = tid; t < 64 * 32; t += 256)
            xs[t >> 5][t & 31] = x[(size_t)(i0 + (t >> 5)) * F_ + k0 + (t & 31)];
        for (int t = tid; t < 32 * 64; t += 256)
            ws[t >> 6][t & 63] = Wp[(size_t)(k0 + (t >> 6)) * D_ + (t & 63)];
        __syncthreads();
#pragma unroll 8
        for (int k = 0; k < 32; k++) {
            float a[4], b[4];
#pragma unroll
            for (int r = 0; r < 4; r++) a[r] = xs[ty * 4 + r][k];
#pragma unroll
            for (int c = 0; c < 4; c++) b[c] = ws[k][tx * 4 + c];
#pragma unroll
            for (int r = 0; r < 4; r++)
#pragma unroll
                for (int c = 0; c < 4; c++) C[r][c] += a[r] * b[c];
        }
        __syncthreads();
    }
#pragma unroll
    for (int r = 0; r < 4; r++)
#pragma unroll
        for (int c = 0; c < 4; c++) {
            g_Wh[((size_t)h * N_ + i0 + ty * 4 + r) * D_ + tx * 4 + c] = C[r][c];
            sC[ty * 4 + r][tx * 4 + c] = C[r][c];
        }
    __syncthreads();
    // fragment emit for mma.m16n8k16 B: 32 frags (ks*8+nf) x 32 lanes, uint2
    uint2* dst = g_Bf16 + ((size_t)(h * (N_ / 64) + blockIdx.x)) * 1024;
#pragma unroll
    for (int it = 0; it < 4; it++) {
        int o = tid + it * 256;
        int frag = o >> 5, lane = o & 31;
        int ks = frag >> 3, nf = frag & 7;
        int g = lane >> 2, tg = lane & 3;
        int jlo = ks * 16 + tg * 2;
        int n = nf * 8 + g;
        __half2 lo = __floats2half2_rn(sC[jlo][n],     sC[jlo + 1][n]);
        __half2 hi = __floats2half2_rn(sC[jlo + 8][n], sC[jlo + 9][n]);
        uint2 v;
        v.x = *reinterpret_cast<uint32_t*>(&lo);
        v.y = *reinterpret_cast<uint32_t*>(&hi);
        dst[o] = v;
    }
}

// ============================================================
// Kernel 2: s1, s2 tables
// ============================================================
__global__ __launch_bounds__(256) void se_kernel(const float* __restrict__ a1,
                                                 const float* __restrict__ a2) {
    const int warp = (blockIdx.x * blockDim.x + threadIdx.x) >> 5;
    const int lane = threadIdx.x & 31;
    if (warp >= H_ * N_) return;
    const int h = warp / N_;
    const float* row = g_Wh + (size_t)warp * D_;
    float v0 = row[lane], v1 = row[lane + 32];
    float p1 = v0 * a1[h * D_ + lane] + v1 * a1[h * D_ + lane + 32];
    float p2 = v0 * a2[h * D_ + lane] + v1 * a2[h * D_ + lane + 32];
#pragma unroll
    for (int o = 16; o; o >>= 1) {
        p1 += __shfl_xor_sync(0xffffffffu, p1, o);
        p2 += __shfl_xor_sync(0xffffffffu, p2, o);
    }
    if (lane == 0) {
        g_s1[warp] = p1;
        g_tbl[warp] = make_float4(p2, expf(p2), expf(ALPHA_ * p2), 0.f);
    }
}

// Kernel 2b: per-h max of s2
__global__ __launch_bounds__(256) void s2max_kernel() {
    __shared__ float sm[256];
    const int h = blockIdx.x;
    float mx = -1e30f;
    for (int n = threadIdx.x; n < N_; n += 256)
        mx = fmaxf(mx, g_tbl[h * N_ + n].x);
    sm[threadIdx.x] = mx;
    __syncthreads();
    for (int s = 128; s; s >>= 1) {
        if (threadIdx.x < s) sm[threadIdx.x] = fmaxf(sm[threadIdx.x], sm[threadIdx.x + s]);
        __syncthreads();
    }
    if (threadIdx.x == 0) g_S2M[h] = sm[0];
}

// Kernel 2c: row scaling — exact power-of-2 per row so max w ~ [512,1024]
__global__ __launch_bounds__(256) void scale_kernel() {
    int idx = blockIdx.x * blockDim.x + threadIdx.x;
    if (idx >= H_ * N_) return;
    int h = idx / N_;
    float s1 = g_s1[idx];
    float t = s1 + g_S2M[h];
    float b = t > 0.f ? t : ALPHA_ * t;            // log(max w bound)
    float e = 9.f - floorf(b * L2E_);              // 2^e scale
    g_E1[idx]  = exp2f(s1 * L2E_ + e);
    g_E1a[idx] = exp2f(ALPHA_ * s1 * L2E_ + e);
}

// ============================================================
// Kernel 3: masked attention, mma.m16n8k16 fp16 (fp32 accum).
// CTA = (128-row i-tile, h, m), 128 thr. Bitmask in SMEM,
// double-buffered prepacked fp16 B + tables. Zero inner-loop LDG.
// ============================================================
#define OFF_B   67584              // bitmask: 128 rows * 132 words * 4B
#define OFF_T   (OFF_B + 16384)    // B: 2 * 8KB
#define OFF_DEN (OFF_T + 2048)     // tbl: 2 * 1KB
#define SMEM_ATT (OFF_DEN + 512)

__global__ __launch_bounds__(128, 2) void att_mma() {
    extern __shared__ char dsm[];
    const uint32_t sb = smem_u32(dsm);

    const int i0 = blockIdx.x * 128;
    const int h  = blockIdx.y;
    const int m  = blockIdx.z;
    const int tid = threadIdx.x;
    const int wid = tid >> 5, lane = tid & 31;
    const int g = lane >> 2, tg = lane & 3;
    const int wbase = wid * 32;

    // stage bitmask tile: 4096 uint4
    {
        const uint4* bsrc = (const uint4*)(g_adjbits + ((size_t)m * N_ + i0) * (N_ / 32));
#pragma unroll
        for (int it = 0; it < 32; it++) {
            int q = tid + it * 128;
            cp16(sb + (q >> 5) * 528 + (q & 31) * 16, bsrc + q);
        }
    }
    // stage tile jt=0 (512 uint4 B + 64 uint4 tbl)
    {
        const uint4* bs = (const uint4*)(g_Bf16 + ((size_t)(h * (N_ / 64))) * 1024);
#pragma unroll
        for (int r = 0; r < 4; r++) cp16(sb + OFF_B + (tid + r * 128) * 16, bs + tid + r * 128);
        if (tid < 64) cp16(sb + OFF_T + tid * 16, g_tbl + h * N_ + tid);
    }
    CP_COMMIT();

    float s1v[4], e1v[4], e1av[4];
#pragma unroll
    for (int q = 0; q < 4; q++) {
        int gg = h * N_ + i0 + wbase + g + q * 8;
        s1v[q] = g_s1[gg]; e1v[q] = g_E1[gg]; e1av[q] = g_E1a[gg];
    }

    float acc[2][8][4];
#pragma unroll
    for (int a = 0; a < 2; a++)
#pragma unroll
        for (int b = 0; b < 8; b++)
#pragma unroll
            for (int c = 0; c < 4; c++) acc[a][b][c] = 0.f;
    float den[4] = {0.f, 0.f, 0.f, 0.f};

    int buf = 0;
    for (int jt = 0; jt < N_ / 64; jt++) {
        if (jt + 1 < N_ / 64) {
            const uint4* bs = (const uint4*)(g_Bf16 +
                ((size_t)(h * (N_ / 64) + jt + 1)) * 1024);
            uint32_t dB = sb + OFF_B + (buf ^ 1) * 8192;
#pragma unroll
            for (int r = 0; r < 4; r++) cp16(dB + (tid + r * 128) * 16, bs + tid + r * 128);
            if (tid < 64)
                cp16(sb + OFF_T + (buf ^ 1) * 1024 + tid * 16,
                     g_tbl + h * N_ + (jt + 1) * 64 + tid);
            CP_COMMIT();
            CP_WAIT1();
        } else {
            CP_WAIT0();
        }
        __syncthreads();

        const float4* tb = (const float4*)(dsm + OFF_T + buf * 1024);
        const uint2*  Bp = (const uint2*)(dsm + OFF_B + buf * 8192);
        const uint32_t* bt = (const uint32_t*)dsm;

        uint32_t u0[4], u1[4];
#pragma unroll
        for (int q = 0; q < 4; q++) {
            int rl = wbase + g + q * 8;
            u0[q] = bt[rl * 132 + jt * 2];
            u1[q] = bt[rl * 132 + jt * 2 + 1];
        }
#pragma unroll
        for (int ks = 0; ks < 4; ks++) {
            const int kk = ks * 16;
            float4 tA0 = tb[kk + tg * 2];
            float4 tA1 = tb[kk + tg * 2 + 1];
            float4 tB0 = tb[kk + tg * 2 + 8];
            float4 tB1 = tb[kk + tg * 2 + 9];
            uint32_t A[2][4];
#pragma unroll
            for (int q = 0; q < 4; q++) {
                uint32_t uw = (ks < 2) ? u0[q] : u1[q];
                int sh = (kk & 31) + tg * 2;
                float w0 = 0.f, w1 = 0.f, w2 = 0.f, w3 = 0.f;
                if ((uw >> sh) & 1u)
                    w0 = (s1v[q] + tA0.x > 0.f) ? e1v[q] * tA0.y : e1av[q] * tA0.z;
                if ((uw >> (sh + 1)) & 1u)
                    w1 = (s1v[q] + tA1.x > 0.f) ? e1v[q] * tA1.y : e1av[q] * tA1.z;
                if ((uw >> (sh + 8)) & 1u)
                    w2 = (s1v[q] + tB0.x > 0.f) ? e1v[q] * tB0.y : e1av[q] * tB0.z;
                if ((uw >> (sh + 9)) & 1u)
                    w3 = (s1v[q] + tB1.x > 0.f) ? e1v[q] * tB1.y : e1av[q] * tB1.z;
                __half2 lo = __floats2half2_rn(w0, w1);
                __half2 hi = __floats2half2_rn(w2, w3);
                A[q >> 1][q & 1]       = *reinterpret_cast<uint32_t*>(&lo);
                A[q >> 1][2 + (q & 1)] = *reinterpret_cast<uint32_t*>(&hi);
                float2 f0 = __half22float2(lo);
                float2 f1 = __half22float2(hi);
                den[q] += (f0.x + f0.y) + (f1.x + f1.y);
            }
#pragma unroll
            for (int nf = 0; nf < 8; nf++) {
                uint2 b = Bp[(ks * 8 + nf) * 32 + lane];
#pragma unroll
                for (int mf = 0; mf < 2; mf++) {
                    asm volatile(
                        "mma.sync.aligned.m16n8k16.row.col.f32.f16.f16.f32 "
                        "{%0,%1,%2,%3}, {%4,%5,%6,%7}, {%8,%9}, {%0,%1,%2,%3};"
                        : "+f"(acc[mf][nf][0]), "+f"(acc[mf][nf][1]),
                          "+f"(acc[mf][nf][2]), "+f"(acc[mf][nf][3])
                        : "r"(A[mf][0]), "r"(A[mf][1]), "r"(A[mf][2]), "r"(A[mf][3]),
                          "r"(b.x), "r"(b.y));
                }
            }
        }
        buf ^= 1;
        __syncthreads();
    }

    float* sden = (float*)(dsm + OFF_DEN);
#pragma unroll
    for (int q = 0; q < 4; q++) {
        den[q] += __shfl_xor_sync(0xffffffffu, den[q], 1);
        den[q] += __shfl_xor_sync(0xffffffffu, den[q], 2);
    }
    if (tg == 0)
#pragma unroll
        for (int q = 0; q < 4; q++) sden[wbase + g + q * 8] = den[q];
    __syncwarp();

#pragma unroll
    for (int mf = 0; mf < 2; mf++) {
        float d0 = 1.f / sden[wbase + mf * 16 + g];
        float d1 = 1.f / sden[wbase + mf * 16 + 8 + g];
        int r0 = i0 + wbase + mf * 16 + g;
        int r1 = r0 + 8;
#pragma unroll
        for (int nf = 0; nf < 8; nf++) {
            int col = h * D_ + nf * 8 + tg * 2;
            *(float2*)(g_Z + ((size_t)m * N_ + r0) * (H_ * D_) + col) =
                make_float2(acc[mf][nf][0] * d0, acc[mf][nf][1] * d0);
            *(float2*)(g_Z + ((size_t)m * N_ + r1) * (H_ * D_) + col) =
                make_float2(acc[mf][nf][2] * d1, acc[mf][nf][3] * d1);
        }
    }
}

// ============================================================
// Kernel 4: out = elu(Z[0]) + elu(Z[1])   (beta == 1)
// ============================================================
__device__ __forceinline__ float elu1(float v) { return v > 0.f ? v : expm1f(v); }
__global__ __launch_bounds__(256) void combine_kernel(float* __restrict__ out) {
    int idx = blockIdx.x * blockDim.x + threadIdx.x;
    const int total = N_ * H_ * D_;
    if (idx < total) {
        float z0 = g_Z[idx];
        float z1 = g_Z[(size_t)total + idx];
        out[idx] = elu1(z0) + elu1(z1);
    }
}

extern "C" void kernel_launch(void* const* d_in, const int* in_sizes, int n_in,
                              void* d_out, int out_size) {
    const float* x   = (const float*)d_in[0];
    const int*   adj = (const int*)d_in[1];
    const float* W   = (const float*)d_in[2];
    const float* a1  = (const float*)d_in[3];
    const float* a2  = (const float*)d_in[4];
    // d_in[5..7] (Ws, bs, q_sem) dead: softmax over singleton axis -> beta == 1
    float* out = (float*)d_out;

    cudaFuncSetAttribute(att_mma, cudaFuncAttributeMaxDynamicSharedMemorySize, SMEM_ATT);

    pack_adj<<<(M_ * N_) / 8, 256>>>(adj);
    wh_gemm<<<dim3(N_ / 64, H_), 256>>>(x, W);
    se_kernel<<<(H_ * N_) / 8, 256>>>(a1, a2);
    s2max_kernel<<<H_, 256>>>();
    scale_kernel<<<(H_ * N_) / 256, 256>>>();
    att_mma<<<dim3(N_ / 128, H_, M_), 128, SMEM_ATT>>>();
    combine_kernel<<<(N_ * H_ * D_ + 255) / 256, 256>>>(out);
}

// round 8
// speedup vs baseline: 3.7846x; 1.1820x over previous
#include <cuda_runtime.h>
#include <cuda_fp16.h>
#include <math.h>
#include <cstdint>

#define N_ 4096
#define F_ 512
#define D_ 64
#define H_ 4
#define M_ 2
#define JS_ 4
#define JT_PER_ 16            // (N_/64)/JS_
#define ALPHA_ 0.2f
#define L2E_ 1.44269504f

// ---- device scratch (no allocation allowed) ----
__device__ float    g_Wh[(size_t)H_ * N_ * D_];
__device__ float    g_s1[H_ * N_], g_E1[H_ * N_], g_E1a[H_ * N_];
__device__ float4   g_tbl[H_ * N_];                            // (s2, e2s, e2as, 0)
__device__ float    g_S2M[H_];
__device__ uint32_t g_adjbits[(size_t)M_ * N_ * (N_ / 32)];
__device__ uint2    g_Bf16[(size_t)H_ * (N_ / 64) * 1024];     // fp16 frag tiles
__device__ float    g_pnum[(size_t)JS_ * M_ * N_ * H_ * D_];   // [js][m][n][h*64+d]
__device__ float    g_pden[(size_t)JS_ * M_ * H_ * N_];        // [js][m][h][n]

__device__ __forceinline__ uint32_t smem_u32(const void* p) {
    uint32_t a;
    asm("{ .reg .u64 t; cvta.to.shared.u64 t, %1; cvt.u32.u64 %0, t; }" : "=r"(a) : "l"(p));
    return a;
}
__device__ __forceinline__ void cp16(uint32_t dst, const void* src) {
    asm volatile("cp.async.cg.shared.global [%0], [%1], 16;" :: "r"(dst), "l"(src));
}
#define CP_COMMIT() asm volatile("cp.async.commit_group;" ::: "memory")
#define CP_WAIT1()  asm volatile("cp.async.wait_group 1;" ::: "memory")
#define CP_WAIT0()  asm volatile("cp.async.wait_group 0;" ::: "memory")

// ============================================================
// Kernel 0: pack adj into bitmask
// ============================================================
__global__ __launch_bounds__(256) void pack_adj(const int* __restrict__ adj) {
    const int r = (blockIdx.x * blockDim.x + threadIdx.x) >> 5;
    const int lane = threadIdx.x & 31;
    if (r >= M_ * N_) return;
    const int* src = adj + (size_t)r * N_;
#pragma unroll 8
    for (int w = 0; w < N_ / 32; w++) {
        int a = src[w * 32 + lane];
        uint32_t msk = __ballot_sync(0xffffffffu, a != 0);
        if (lane == 0) g_adjbits[(size_t)r * (N_ / 32) + w] = msk;
    }
}

// ============================================================
// Kernel 1: Wh = x @ W  (fp32) + emit fp16 mma B-frag tiles
// ============================================================
__global__ __launch_bounds__(256) void wh_gemm(const float* __restrict__ x,
                                               const float* __restrict__ W) {
    __shared__ float xs[64][33];
    __shared__ float ws[32][65];
    __shared__ float sC[64][68];
    const int h = blockIdx.y;
    const int i0 = blockIdx.x * 64;
    const int tid = threadIdx.x;
    const int tx = tid & 15, ty = tid >> 4;
    float C[4][4] = {};
    const float* Wp = W + (size_t)h * F_ * D_;

    for (int k0 = 0; k0 < F_; k0 += 32) {
        for (int t = tid; t < 64 * 32; t += 256)
            xs[t >> 5][t & 31] = x[(size_t)(i0 + (t >> 5)) * F_ + k0 + (t & 31)];
        for (int t = tid; t < 32 * 64; t += 256)
            ws[t >> 6][t & 63] = Wp[(size_t)(k0 + (t >> 6)) * D_ + (t & 63)];
        __syncthreads();
#pragma unroll 8
        for (int k = 0; k < 32; k++) {
            float a[4], b[4];
#pragma unroll
            for (int r = 0; r < 4; r++) a[r] = xs[ty * 4 + r][k];
#pragma unroll
            for (int c = 0; c < 4; c++) b[c] = ws[k][tx * 4 + c];
#pragma unroll
            for (int r = 0; r < 4; r++)
#pragma unroll
                for (int c = 0; c < 4; c++) C[r][c] += a[r] * b[c];
        }
        __syncthreads();
    }
#pragma unroll
    for (int r = 0; r < 4; r++)
#pragma unroll
        for (int c = 0; c < 4; c++) {
            g_Wh[((size_t)h * N_ + i0 + ty * 4 + r) * D_ + tx * 4 + c] = C[r][c];
            sC[ty * 4 + r][tx * 4 + c] = C[r][c];
        }
    __syncthreads();
    uint2* dst = g_Bf16 + ((size_t)(h * (N_ / 64) + blockIdx.x)) * 1024;
#pragma unroll
    for (int it = 0; it < 4; it++) {
        int o = tid + it * 256;
        int frag = o >> 5, lane = o & 31;
        int ks = frag >> 3, nf = frag & 7;
        int g = lane >> 2, tg = lane & 3;
        int jlo = ks * 16 + tg * 2;
        int n = nf * 8 + g;
        __half2 lo = __floats2half2_rn(sC[jlo][n],     sC[jlo + 1][n]);
        __half2 hi = __floats2half2_rn(sC[jlo + 8][n], sC[jlo + 9][n]);
        uint2 v;
        v.x = *reinterpret_cast<uint32_t*>(&lo);
        v.y = *reinterpret_cast<uint32_t*>(&hi);
        dst[o] = v;
    }
}

// ============================================================
// Kernel 2: s1, s2 tables
// ============================================================
__global__ __launch_bounds__(256) void se_kernel(const float* __restrict__ a1,
                                                 const float* __restrict__ a2) {
    const int warp = (blockIdx.x * blockDim.x + threadIdx.x) >> 5;
    const int lane = threadIdx.x & 31;
    if (warp >= H_ * N_) return;
    const int h = warp / N_;
    const float* row = g_Wh + (size_t)warp * D_;
    float v0 = row[lane], v1 = row[lane + 32];
    float p1 = v0 * a1[h * D_ + lane] + v1 * a1[h * D_ + lane + 32];
    float p2 = v0 * a2[h * D_ + lane] + v1 * a2[h * D_ + lane + 32];
#pragma unroll
    for (int o = 16; o; o >>= 1) {
        p1 += __shfl_xor_sync(0xffffffffu, p1, o);
        p2 += __shfl_xor_sync(0xffffffffu, p2, o);
    }
    if (lane == 0) {
        g_s1[warp] = p1;
        g_tbl[warp] = make_float4(p2, expf(p2), expf(ALPHA_ * p2), 0.f);
    }
}

// Kernel 2b: per-h max of s2 (fast: 1024 thr, shuffle reduce)
__global__ __launch_bounds__(1024) void s2max_kernel() {
    __shared__ float sm[32];
    const int h = blockIdx.x;
    const int tid = threadIdx.x;
    float mx = -1e30f;
#pragma unroll
    for (int it = 0; it < N_ / 1024; it++)
        mx = fmaxf(mx, g_tbl[h * N_ + tid + it * 1024].x);
#pragma unroll
    for (int o = 16; o; o >>= 1)
        mx = fmaxf(mx, __shfl_xor_sync(0xffffffffu, mx, o));
    if ((tid & 31) == 0) sm[tid >> 5] = mx;
    __syncthreads();
    if (tid < 32) {
        mx = sm[tid];
#pragma unroll
        for (int o = 16; o; o >>= 1)
            mx = fmaxf(mx, __shfl_xor_sync(0xffffffffu, mx, o));
        if (tid == 0) g_S2M[h] = mx;
    }
}

// Kernel 2c: per-row power-of-2 scaling so max w in [512,1024]
__global__ __launch_bounds__(256) void scale_kernel() {
    int idx = blockIdx.x * blockDim.x + threadIdx.x;
    if (idx >= H_ * N_) return;
    int h = idx / N_;
    float s1 = g_s1[idx];
    float t = s1 + g_S2M[h];
    float b = t > 0.f ? t : ALPHA_ * t;
    float e = 9.f - floorf(b * L2E_);
    g_E1[idx]  = exp2f(s1 * L2E_ + e);
    g_E1a[idx] = exp2f(ALPHA_ * s1 * L2E_ + e);
}

// ============================================================
// Kernel 3: masked attention, mma.m16n8k16 fp16, j-split.
// CTA = (128-row i-tile, h, js, m), 128 thr, 16 j-tiles.
// den via ones-column (9th n-frag). Zero inner-loop LDG.
// ============================================================
#define BPITCH  36               // bitmask row pitch (words)
#define OFF_B   18432            // bitmask: 128 * 36 * 4
#define OFF_T   (OFF_B + 16384)  // B: 2 * 8KB
#define SMEM_ATT (OFF_T + 2048)  // tbl: 2 * 1KB

__global__ __launch_bounds__(128, 3) void att_mma() {
    extern __shared__ char dsm[];
    const uint32_t sb = smem_u32(dsm);

    const int i0 = blockIdx.x * 128;
    const int h  = blockIdx.y & (H_ - 1);
    const int js = blockIdx.y >> 2;
    const int m  = blockIdx.z;
    const int tid = threadIdx.x;
    const int wid = tid >> 5, lane = tid & 31;
    const int g = lane >> 2, tg = lane & 3;
    const int wbase = wid * 32;

    // stage bitmask slice: 128 rows x 32 words (this js range)
    {
        const uint32_t* bsrc = g_adjbits + ((size_t)m * N_ + i0) * (N_ / 32) + js * 32;
#pragma unroll
        for (int it = 0; it < 8; it++) {
            int q = tid + it * 128;           // q = row*8 + w4
            int row = q >> 3, w4 = q & 7;
            cp16(sb + row * (BPITCH * 4) + w4 * 16,
                 bsrc + (size_t)row * (N_ / 32) + w4 * 4);
        }
    }
    // stage first B tile + tbl
    {
        const int jt0 = js * JT_PER_;
        const uint4* bs = (const uint4*)(g_Bf16 + ((size_t)(h * (N_ / 64) + jt0)) * 1024);
#pragma unroll
        for (int r = 0; r < 4; r++) cp16(sb + OFF_B + (tid + r * 128) * 16, bs + tid + r * 128);
        if (tid < 64) cp16(sb + OFF_T + tid * 16, g_tbl + h * N_ + jt0 * 64 + tid);
    }
    CP_COMMIT();

    float s1v[4], e1v[4], e1av[4];
#pragma unroll
    for (int q = 0; q < 4; q++) {
        int gg = h * N_ + i0 + wbase + g + q * 8;
        s1v[q] = g_s1[gg]; e1v[q] = g_E1[gg]; e1av[q] = g_E1a[gg];
    }
    const uint32_t bones = (g == 0) ? 0x3C003C00u : 0u;   // ones-column B frag

    float acc[2][9][4];
#pragma unroll
    for (int a = 0; a < 2; a++)
#pragma unroll
        for (int b = 0; b < 9; b++)
#pragma unroll
            for (int c = 0; c < 4; c++) acc[a][b][c] = 0.f;

    int buf = 0;
    for (int l = 0; l < JT_PER_; l++) {
        if (l + 1 < JT_PER_) {
            const int jt = js * JT_PER_ + l + 1;
            const uint4* bs = (const uint4*)(g_Bf16 + ((size_t)(h * (N_ / 64) + jt)) * 1024);
            uint32_t dB = sb + OFF_B + (buf ^ 1) * 8192;
#pragma unroll
            for (int r = 0; r < 4; r++) cp16(dB + (tid + r * 128) * 16, bs + tid + r * 128);
            if (tid < 64)
                cp16(sb + OFF_T + (buf ^ 1) * 1024 + tid * 16,
                     g_tbl + h * N_ + jt * 64 + tid);
            CP_COMMIT();
            CP_WAIT1();
        } else {
            CP_WAIT0();
        }
        __syncthreads();

        const float4* tb = (const float4*)(dsm + OFF_T + buf * 1024);
        const uint2*  Bp = (const uint2*)(dsm + OFF_B + buf * 8192);
        const uint32_t* bt = (const uint32_t*)dsm;

        uint32_t u0[4], u1[4];
#pragma unroll
        for (int q = 0; q < 4; q++) {
            int rl = wbase + g + q * 8;
            u0[q] = bt[rl * BPITCH + l * 2];
            u1[q] = bt[rl * BPITCH + l * 2 + 1];
        }
#pragma unroll
        for (int ks = 0; ks < 4; ks++) {
            const int kk = ks * 16;
            float4 tA0 = tb[kk + tg * 2];
            float4 tA1 = tb[kk + tg * 2 + 1];
            float4 tB0 = tb[kk + tg * 2 + 8];
            float4 tB1 = tb[kk + tg * 2 + 9];
            uint32_t A[2][4];
#pragma unroll
            for (int q = 0; q < 4; q++) {
                uint32_t uw = (ks < 2) ? u0[q] : u1[q];
                int sh = (kk & 31) + tg * 2;
                float w0 = 0.f, w1 = 0.f, w2 = 0.f, w3 = 0.f;
                if ((uw >> sh) & 1u)
                    w0 = (s1v[q] + tA0.x > 0.f) ? e1v[q] * tA0.y : e1av[q] * tA0.z;
                if ((uw >> (sh + 1)) & 1u)
                    w1 = (s1v[q] + tA1.x > 0.f) ? e1v[q] * tA1.y : e1av[q] * tA1.z;
                if ((uw >> (sh + 8)) & 1u)
                    w2 = (s1v[q] + tB0.x > 0.f) ? e1v[q] * tB0.y : e1av[q] * tB0.z;
                if ((uw >> (sh + 9)) & 1u)
                    w3 = (s1v[q] + tB1.x > 0.f) ? e1v[q] * tB1.y : e1av[q] * tB1.z;
                __half2 lo = __floats2half2_rn(w0, w1);
                __half2 hi = __floats2half2_rn(w2, w3);
                A[q >> 1][q & 1]       = *reinterpret_cast<uint32_t*>(&lo);
                A[q >> 1][2 + (q & 1)] = *reinterpret_cast<uint32_t*>(&hi);
            }
#pragma unroll
            for (int nf = 0; nf < 8; nf++) {
                uint2 b = Bp[(ks * 8 + nf) * 32 + lane];
#pragma unroll
                for (int mf = 0; mf < 2; mf++) {
                    asm volatile(
                        "mma.sync.aligned.m16n8k16.row.col.f32.f16.f16.f32 "
                        "{%0,%1,%2,%3}, {%4,%5,%6,%7}, {%8,%9}, {%0,%1,%2,%3};"
                        : "+f"(acc[mf][nf][0]), "+f"(acc[mf][nf][1]),
                          "+f"(acc[mf][nf][2]), "+f"(acc[mf][nf][3])
                        : "r"(A[mf][0]), "r"(A[mf][1]), "r"(A[mf][2]), "r"(A[mf][3]),
                          "r"(b.x), "r"(b.y));
                }
            }
            // ones-column: row sums into acc[mf][8] (col 0)
#pragma unroll
            for (int mf = 0; mf < 2; mf++) {
                asm volatile(
                    "mma.sync.aligned.m16n8k16.row.col.f32.f16.f16.f32 "
                    "{%0,%1,%2,%3}, {%4,%5,%6,%7}, {%8,%9}, {%0,%1,%2,%3};"
                    : "+f"(acc[mf][8][0]), "+f"(acc[mf][8][1]),
                      "+f"(acc[mf][8][2]), "+f"(acc[mf][8][3])
                    : "r"(A[mf][0]), "r"(A[mf][1]), "r"(A[mf][2]), "r"(A[mf][3]),
                      "r"(bones), "r"(bones));
            }
        }
        buf ^= 1;
        __syncthreads();
    }

    // epilogue: raw partial num + den (den = acc[mf][8][0/2], tg==0 threads)
    const size_t nbase = ((size_t)(js * M_ + m) * N_);
#pragma unroll
    for (int mf = 0; mf < 2; mf++) {
        int r0 = i0 + wbase + mf * 16 + g;
        int r1 = r0 + 8;
#pragma unroll
        for (int nf = 0; nf < 8; nf++) {
            int col = h * D_ + nf * 8 + tg * 2;
            *(float2*)(g_pnum + (nbase + r0) * (H_ * D_) + col) =
                make_float2(acc[mf][nf][0], acc[mf][nf][1]);
            *(float2*)(g_pnum + (nbase + r1) * (H_ * D_) + col) =
                make_float2(acc[mf][nf][2], acc[mf][nf][3]);
        }
        if (tg == 0) {
            float* dp = g_pden + ((size_t)(js * M_ + m) * H_ + h) * N_;
            dp[r0] = acc[mf][8][0];
            dp[r1] = acc[mf][8][2];
        }
    }
}

// ============================================================
// Kernel 4: combine splits: num/den, elu, sum over m (beta==1)
// ============================================================
__device__ __forceinline__ float elu1(float v) { return v > 0.f ? v : expm1f(v); }
__global__ __launch_bounds__(256) void combine_kernel(float* __restrict__ out) {
    const int n = blockIdx.x;
    const int t = threadIdx.x;          // h*64+d
    const int h = t >> 6;
    float accv = 0.f;
#pragma unroll
    for (int m = 0; m < M_; m++) {
        float num = 0.f, den = 0.f;
#pragma unroll
        for (int js = 0; js < JS_; js++) {
            int p = js * M_ + m;
            num += g_pnum[((size_t)p * N_ + n) * (H_ * D_) + t];
            den += g_pden[((size_t)p * H_ + h) * N_ + n];
        }
        accv += elu1(num / den);
    }
    out[(size_t)n * (H_ * D_) + t] = accv;
}

extern "C" void kernel_launch(void* const* d_in, const int* in_sizes, int n_in,
                              void* d_out, int out_size) {
    const float* x   = (const float*)d_in[0];
    const int*   adj = (const int*)d_in[1];
    const float* W   = (const float*)d_in[2];
    const float* a1  = (const float*)d_in[3];
    const float* a2  = (const float*)d_in[4];
    // d_in[5..7] (Ws, bs, q_sem) dead: softmax over singleton axis -> beta == 1
    float* out = (float*)d_out;

    cudaFuncSetAttribute(att_mma, cudaFuncAttributeMaxDynamicSharedMemorySize, SMEM_ATT);

    pack_adj<<<(M_ * N_) / 8, 256>>>(adj);
    wh_gemm<<<dim3(N_ / 64, H_), 256>>>(x, W);
    se_kernel<<<(H_ * N_) / 8, 256>>>(a1, a2);
    s2max_kernel<<<H_, 1024>>>();
    scale_kernel<<<(H_ * N_) / 256, 256>>>();
    att_mma<<<dim3(N_ / 128, H_ * JS_, M_), 128, SMEM_ATT>>>();
    combine_kernel<<<N_, 256>>>(out);
}

// round 9
// speedup vs baseline: 5.4345x; 1.4360x over previous
#include <cuda_runtime.h>
#include <cuda_fp16.h>
#include <math.h>
#include <cstdint>

#define N_ 4096
#define F_ 512
#define D_ 64
#define H_ 4
#define M_ 2
#define JS_ 4
#define JT_PER_ 16            // (N_/64)/JS_
#define ALPHA_ 0.2f
#define L2E_ 1.44269504f

// ---- device scratch (no allocation allowed) ----
__device__ float    g_Wh[(size_t)H_ * N_ * D_];
__device__ float    g_s1[H_ * N_], g_s2[H_ * N_];
__device__ float    g_E1[H_ * N_], g_E1a[H_ * N_];
__device__ float2   g_tbl[H_ * N_];                            // (e2, e2a)
__device__ float    g_S2M[H_];
__device__ uint32_t g_adjbits[(size_t)M_ * N_ * (N_ / 32)];
__device__ uint2    g_Bf16[(size_t)H_ * (N_ / 64) * 1024];     // fp16 frag tiles
__device__ float    g_pnum[(size_t)JS_ * M_ * N_ * H_ * D_];   // [js][m][n][h*64+d]
__device__ float    g_pden[(size_t)JS_ * M_ * H_ * N_];        // [js][m][h][n]

__device__ __forceinline__ uint32_t smem_u32(const void* p) {
    uint32_t a;
    asm("{ .reg .u64 t; cvta.to.shared.u64 t, %1; cvt.u32.u64 %0, t; }" : "=r"(a) : "l"(p));
    return a;
}
__device__ __forceinline__ void cp16(uint32_t dst, const void* src) {
    asm volatile("cp.async.cg.shared.global [%0], [%1], 16;" :: "r"(dst), "l"(src));
}
#define CP_COMMIT() asm volatile("cp.async.commit_group;" ::: "memory")
#define CP_WAIT0()  asm volatile("cp.async.wait_group 0;" ::: "memory")

// ============================================================
// Kernel 0: pack adj into bitmask
// ============================================================
__global__ __launch_bounds__(256) void pack_adj(const int* __restrict__ adj) {
    const int r = (blockIdx.x * blockDim.x + threadIdx.x) >> 5;
    const int lane = threadIdx.x & 31;
    if (r >= M_ * N_) return;
    const int* src = adj + (size_t)r * N_;
#pragma unroll 8
    for (int w = 0; w < N_ / 32; w++) {
        int a = src[w * 32 + lane];
        uint32_t msk = __ballot_sync(0xffffffffu, a != 0);
        if (lane == 0) g_adjbits[(size_t)r * (N_ / 32) + w] = msk;
    }
}

// ============================================================
// Kernel 1: Wh = x @ W  (fp32) + emit fp16 mma B-frag tiles
// ============================================================
__global__ __launch_bounds__(256) void wh_gemm(const float* __restrict__ x,
                                               const float* __restrict__ W) {
    __shared__ float xs[64][33];
    __shared__ float ws[32][65];
    __shared__ float sC[64][68];
    const int h = blockIdx.y;
    const int i0 = blockIdx.x * 64;
    const int tid = threadIdx.x;
    const int tx = tid & 15, ty = tid >> 4;
    float C[4][4] = {};
    const float* Wp = W + (size_t)h * F_ * D_;

    for (int k0 = 0; k0 < F_; k0 += 32) {
        for (int t = tid; t < 64 * 32; t += 256)
            xs[t >> 5][t & 31] = x[(size_t)(i0 + (t >> 5)) * F_ + k0 + (t & 31)];
        for (int t = tid; t < 32 * 64; t += 256)
            ws[t >> 6][t & 63] = Wp[(size_t)(k0 + (t >> 6)) * D_ + (t & 63)];
        __syncthreads();
#pragma unroll 8
        for (int k = 0; k < 32; k++) {
            float a[4], b[4];
#pragma unroll
            for (int r = 0; r < 4; r++) a[r] = xs[ty * 4 + r][k];
#pragma unroll
            for (int c = 0; c < 4; c++) b[c] = ws[k][tx * 4 + c];
#pragma unroll
            for (int r = 0; r < 4; r++)
#pragma unroll
                for (int c = 0; c < 4; c++) C[r][c] += a[r] * b[c];
        }
        __syncthreads();
    }
#pragma unroll
    for (int r = 0; r < 4; r++)
#pragma unroll
        for (int c = 0; c < 4; c++) {
            g_Wh[((size_t)h * N_ + i0 + ty * 4 + r) * D_ + tx * 4 + c] = C[r][c];
            sC[ty * 4 + r][tx * 4 + c] = C[r][c];
        }
    __syncthreads();
    uint2* dst = g_Bf16 + ((size_t)(h * (N_ / 64) + blockIdx.x)) * 1024;
#pragma unroll
    for (int it = 0; it < 4; it++) {
        int o = tid + it * 256;
        int frag = o >> 5, lane = o & 31;
        int ks = frag >> 3, nf = frag & 7;
        int g = lane >> 2, tg = lane & 3;
        int jlo = ks * 16 + tg * 2;
        int n = nf * 8 + g;
        __half2 lo = __floats2half2_rn(sC[jlo][n],     sC[jlo + 1][n]);
        __half2 hi = __floats2half2_rn(sC[jlo + 8][n], sC[jlo + 9][n]);
        uint2 v;
        v.x = *reinterpret_cast<uint32_t*>(&lo);
        v.y = *reinterpret_cast<uint32_t*>(&hi);
        dst[o] = v;
    }
}

// ============================================================
// Kernel 2: s1, s2 and (e2, e2a) table
// ============================================================
__global__ __launch_bounds__(256) void se_kernel(const float* __restrict__ a1,
                                                 const float* __restrict__ a2) {
    const int warp = (blockIdx.x * blockDim.x + threadIdx.x) >> 5;
    const int lane = threadIdx.x & 31;
    if (warp >= H_ * N_) return;
    const int h = warp / N_;
    const float* row = g_Wh + (size_t)warp * D_;
    float v0 = row[lane], v1 = row[lane + 32];
    float p1 = v0 * a1[h * D_ + lane] + v1 * a1[h * D_ + lane + 32];
    float p2 = v0 * a2[h * D_ + lane] + v1 * a2[h * D_ + lane + 32];
#pragma unroll
    for (int o = 16; o; o >>= 1) {
        p1 += __shfl_xor_sync(0xffffffffu, p1, o);
        p2 += __shfl_xor_sync(0xffffffffu, p2, o);
    }
    if (lane == 0) {
        g_s1[warp] = p1;
        g_s2[warp] = p2;
        g_tbl[warp] = make_float2(expf(p2), expf(ALPHA_ * p2));
    }
}

// Kernel 2b: per-h max of s2
__global__ __launch_bounds__(1024) void s2max_kernel() {
    __shared__ float sm[32];
    const int h = blockIdx.x;
    const int tid = threadIdx.x;
    float mx = -1e30f;
#pragma unroll
    for (int it = 0; it < N_ / 1024; it++)
        mx = fmaxf(mx, g_s2[h * N_ + tid + it * 1024]);
#pragma unroll
    for (int o = 16; o; o >>= 1)
        mx = fmaxf(mx, __shfl_xor_sync(0xffffffffu, mx, o));
    if ((tid & 31) == 0) sm[tid >> 5] = mx;
    __syncthreads();
    if (tid < 32) {
        mx = sm[tid];
#pragma unroll
        for (int o = 16; o; o >>= 1)
            mx = fmaxf(mx, __shfl_xor_sync(0xffffffffu, mx, o));
        if (tid == 0) g_S2M[h] = mx;
    }
}

// Kernel 2c: per-row power-of-2 scaling so max w in [512,1024]
__global__ __launch_bounds__(256) void scale_kernel() {
    int idx = blockIdx.x * blockDim.x + threadIdx.x;
    if (idx >= H_ * N_) return;
    int h = idx / N_;
    float s1 = g_s1[idx];
    float t = s1 + g_S2M[h];
    float b = t > 0.f ? t : ALPHA_ * t;
    float e = 9.f - floorf(b * L2E_);
    g_E1[idx]  = exp2f(s1 * L2E_ + e);
    g_E1a[idx] = exp2f(ALPHA_ * s1 * L2E_ + e);
}

// ============================================================
// Kernel 3: masked attention, mma.m16n8k16 fp16, j-split.
// w = bit ? max(e1*e2, e1a*e2a) : 0   (exact lrelu-exp identity)
// ============================================================
#define BPITCH  36               // bitmask row pitch (words)
#define OFF_B   18432            // bitmask: 128 * 36 * 4
#define OFF_T   (OFF_B + 16384)  // B: 2 * 8KB
#define SMEM_ATT (OFF_T + 1024)  // tbl: 2 * 512B

__global__ __launch_bounds__(128, 4) void att_mma() {
    extern __shared__ char dsm[];
    const uint32_t sb = smem_u32(dsm);

    const int i0 = blockIdx.x * 128;
    const int h  = blockIdx.y & (H_ - 1);
    const int js = blockIdx.y >> 2;
    const int m  = blockIdx.z;
    const int tid = threadIdx.x;
    const int wid = tid >> 5, lane = tid & 31;
    const int g = lane >> 2, tg = lane & 3;
    const int wbase = wid * 32;

    // stage bitmask slice: 128 rows x 32 words
    {
        const uint32_t* bsrc = g_adjbits + ((size_t)m * N_ + i0) * (N_ / 32) + js * 32;
#pragma unroll
        for (int it = 0; it < 8; it++) {
            int q = tid + it * 128;
            int row = q >> 3, w4 = q & 7;
            cp16(sb + row * (BPITCH * 4) + w4 * 16,
                 bsrc + (size_t)row * (N_ / 32) + w4 * 4);
        }
    }
    // stage first B tile + tbl
    {
        const int jt0 = js * JT_PER_;
        const uint4* bs = (const uint4*)(g_Bf16 + ((size_t)(h * (N_ / 64) + jt0)) * 1024);
#pragma unroll
        for (int r = 0; r < 4; r++) cp16(sb + OFF_B + (tid + r * 128) * 16, bs + tid + r * 128);
        if (tid < 32) cp16(sb + OFF_T + tid * 16, g_tbl + h * N_ + jt0 * 64 + tid * 2);
    }
    CP_COMMIT();

    float e1v[4], e1av[4];
#pragma unroll
    for (int q = 0; q < 4; q++) {
        int gg = h * N_ + i0 + wbase + g + q * 8;
        e1v[q] = g_E1[gg]; e1av[q] = g_E1a[gg];
    }
    const uint32_t bones = (g == 0) ? 0x3C003C00u : 0u;

    float acc[2][9][4];
#pragma unroll
    for (int a = 0; a < 2; a++)
#pragma unroll
        for (int b = 0; b < 9; b++)
#pragma unroll
            for (int c = 0; c < 4; c++) acc[a][b][c] = 0.f;

    int buf = 0;
    for (int l = 0; l < JT_PER_; l++) {
        CP_WAIT0();          // data for buf landed
        __syncthreads();     // all warps done reading buf^1
        if (l + 1 < JT_PER_) {
            const int jt = js * JT_PER_ + l + 1;
            const uint4* bs = (const uint4*)(g_Bf16 + ((size_t)(h * (N_ / 64) + jt)) * 1024);
            uint32_t dB = sb + OFF_B + (buf ^ 1) * 8192;
#pragma unroll
            for (int r = 0; r < 4; r++) cp16(dB + (tid + r * 128) * 16, bs + tid + r * 128);
            if (tid < 32)
                cp16(sb + OFF_T + (buf ^ 1) * 512 + tid * 16,
                     g_tbl + h * N_ + jt * 64 + tid * 2);
            CP_COMMIT();
        }

        const float2* tb = (const float2*)(dsm + OFF_T + buf * 512);
        const uint2*  Bp = (const uint2*)(dsm + OFF_B + buf * 8192);
        const uint32_t* bt = (const uint32_t*)dsm;

        uint32_t u0[4], u1[4];
#pragma unroll
        for (int q = 0; q < 4; q++) {
            int rl = wbase + g + q * 8;
            u0[q] = bt[rl * BPITCH + l * 2];
            u1[q] = bt[rl * BPITCH + l * 2 + 1];
        }
#pragma unroll
        for (int ks = 0; ks < 4; ks++) {
            const int kk = ks * 16;
            float2 tA0 = tb[kk + tg * 2];
            float2 tA1 = tb[kk + tg * 2 + 1];
            float2 tB0 = tb[kk + tg * 2 + 8];
            float2 tB1 = tb[kk + tg * 2 + 9];
            uint32_t A[2][4];
#pragma unroll
            for (int q = 0; q < 4; q++) {
                uint32_t uw = (ks < 2) ? u0[q] : u1[q];
                int sh = (kk & 31) + tg * 2;
                float w0 = fmaxf(e1v[q] * tA0.x, e1av[q] * tA0.y);
                float w1 = fmaxf(e1v[q] * tA1.x, e1av[q] * tA1.y);
                float w2 = fmaxf(e1v[q] * tB0.x, e1av[q] * tB0.y);
                float w3 = fmaxf(e1v[q] * tB1.x, e1av[q] * tB1.y);
                if (!((uw >> sh) & 1u))       w0 = 0.f;
                if (!((uw >> (sh + 1)) & 1u)) w1 = 0.f;
                if (!((uw >> (sh + 8)) & 1u)) w2 = 0.f;
                if (!((uw >> (sh + 9)) & 1u)) w3 = 0.f;
                __half2 lo = __floats2half2_rn(w0, w1);
                __half2 hi = __floats2half2_rn(w2, w3);
                A[q >> 1][q & 1]       = *reinterpret_cast<uint32_t*>(&lo);
                A[q >> 1][2 + (q & 1)] = *reinterpret_cast<uint32_t*>(&hi);
            }
#pragma unroll
            for (int nf = 0; nf < 8; nf++) {
                uint2 b = Bp[(ks * 8 + nf) * 32 + lane];
#pragma unroll
                for (int mf = 0; mf < 2; mf++) {
                    asm volatile(
                        "mma.sync.aligned.m16n8k16.row.col.f32.f16.f16.f32 "
                        "{%0,%1,%2,%3}, {%4,%5,%6,%7}, {%8,%9}, {%0,%1,%2,%3};"
                        : "+f"(acc[mf][nf][0]), "+f"(acc[mf][nf][1]),
                          "+f"(acc[mf][nf][2]), "+f"(acc[mf][nf][3])
                        : "r"(A[mf][0]), "r"(A[mf][1]), "r"(A[mf][2]), "r"(A[mf][3]),
                          "r"(b.x), "r"(b.y));
                }
            }
#pragma unroll
            for (int mf = 0; mf < 2; mf++) {
                asm volatile(
                    "mma.sync.aligned.m16n8k16.row.col.f32.f16.f16.f32 "
                    "{%0,%1,%2,%3}, {%4,%5,%6,%7}, {%8,%9}, {%0,%1,%2,%3};"
                    : "+f"(acc[mf][8][0]), "+f"(acc[mf][8][1]),
                      "+f"(acc[mf][8][2]), "+f"(acc[mf][8][3])
                    : "r"(A[mf][0]), "r"(A[mf][1]), "r"(A[mf][2]), "r"(A[mf][3]),
                      "r"(bones), "r"(bones));
            }
        }
        buf ^= 1;
    }

    // epilogue: raw partial num + den
    const size_t nbase = ((size_t)(js * M_ + m) * N_);
#pragma unroll
    for (int mf = 0; mf < 2; mf++) {
        int r0 = i0 + wbase + mf * 16 + g;
        int r1 = r0 + 8;
#pragma unroll
        for (int nf = 0; nf < 8; nf++) {
            int col = h * D_ + nf * 8 + tg * 2;
            *(float2*)(g_pnum + (nbase + r0) * (H_ * D_) + col) =
                make_float2(acc[mf][nf][0], acc[mf][nf][1]);
            *(float2*)(g_pnum + (nbase + r1) * (H_ * D_) + col) =
                make_float2(acc[mf][nf][2], acc[mf][nf][3]);
        }
        if (tg == 0) {
            float* dp = g_pden + ((size_t)(js * M_ + m) * H_ + h) * N_;
            dp[r0] = acc[mf][8][0];
            dp[r1] = acc[mf][8][2];
        }
    }
}

// ============================================================
// Kernel 4: combine splits: num/den, elu, sum over m (beta==1)
// ============================================================
__device__ __forceinline__ float elu1(float v) { return v > 0.f ? v : expm1f(v); }
__global__ __launch_bounds__(256) void combine_kernel(float* __restrict__ out) {
    const int n = blockIdx.x;
    const int t = threadIdx.x;
    const int h = t >> 6;
    float accv = 0.f;
#pragma unroll
    for (int m = 0; m < M_; m++) {
        float num = 0.f, den = 0.f;
#pragma unroll
        for (int js = 0; js < JS_; js++) {
            int p = js * M_ + m;
            num += g_pnum[((size_t)p * N_ + n) * (H_ * D_) + t];
            den += g_pden[((size_t)p * H_ + h) * N_ + n];
        }
        accv += elu1(num / den);
    }
    out[(size_t)n * (H_ * D_) + t] = accv;
}

extern "C" void kernel_launch(void* const* d_in, const int* in_sizes, int n_in,
                              void* d_out, int out_size) {
    const float* x   = (const float*)d_in[0];
    const int*   adj = (const int*)d_in[1];
    const float* W   = (const float*)d_in[2];
    const float* a1  = (const float*)d_in[3];
    const float* a2  = (const float*)d_in[4];
    // d_in[5..7] (Ws, bs, q_sem) dead: softmax over singleton axis -> beta == 1
    float* out = (float*)d_out;

    cudaFuncSetAttribute(att_mma, cudaFuncAttributeMaxDynamicSharedMemorySize, SMEM_ATT);

    pack_adj<<<(M_ * N_) / 8, 256>>>(adj);
    wh_gemm<<<dim3(N_ / 64, H_), 256>>>(x, W);
    se_kernel<<<(H_ * N_) / 8, 256>>>(a1, a2);
    s2max_kernel<<<H_, 1024>>>();
    scale_kernel<<<(H_ * N_) / 256, 256>>>();
    att_mma<<<dim3(N_ / 128, H_ * JS_, M_), 128, SMEM_ATT>>>();
    combine_kernel<<<N_, 256>>>(out);
}

// round 10
// speedup vs baseline: 5.5723x; 1.0253x over previous
#include <cuda_runtime.h>
#include <cuda_fp16.h>
#include <math.h>
#include <cstdint>

#define N_ 4096
#define F_ 512
#define D_ 64
#define H_ 4
#define M_ 2
#define JS_ 4
#define JT_PER_ 16            // (N_/64)/JS_
#define ALPHA_ 0.2f
#define L2E_ 1.44269504f

// ---- device scratch (no allocation allowed) ----
__device__ float    g_Wh[(size_t)H_ * N_ * D_];
__device__ float    g_s1[H_ * N_];
__device__ float2   g_tbl[H_ * N_];                            // (e2, e2a) fp32
__device__ unsigned g_S2Mu[H_];                                // flipped-float atomic max
__device__ uint32_t g_adjbits[(size_t)M_ * N_ * (N_ / 32)];
__device__ uint2    g_Bf16[(size_t)H_ * (N_ / 64) * 1024];     // fp16 frag tiles
__device__ float    g_pnum[(size_t)JS_ * M_ * N_ * H_ * D_];   // [js][m][n][h*64+d]
__device__ float    g_pden[(size_t)JS_ * M_ * H_ * N_];        // [js][m][h][n]

__device__ __forceinline__ uint32_t smem_u32(const void* p) {
    uint32_t a;
    asm("{ .reg .u64 t; cvta.to.shared.u64 t, %1; cvt.u32.u64 %0, t; }" : "=r"(a) : "l"(p));
    return a;
}
__device__ __forceinline__ void cp16(uint32_t dst, const void* src) {
    asm volatile("cp.async.cg.shared.global [%0], [%1], 16;" :: "r"(dst), "l"(src));
}
#define CP_COMMIT() asm volatile("cp.async.commit_group;" ::: "memory")
#define CP_WAIT0()  asm volatile("cp.async.wait_group 0;" ::: "memory")

// order-preserving float<->uint for deterministic atomicMax
__device__ __forceinline__ unsigned flipf(float f) {
    unsigned u = __float_as_uint(f);
    return (u & 0x80000000u) ? ~u : (u | 0x80000000u);
}
__device__ __forceinline__ float unflipf(unsigned v) {
    return (v & 0x80000000u) ? __uint_as_float(v & 0x7FFFFFFFu)
                             : __uint_as_float(~v);
}

// ============================================================
// Kernel 0: pack adj into bitmask (+ init S2M accumulators)
// ============================================================
__global__ __launch_bounds__(256) void pack_adj(const int* __restrict__ adj) {
    if (blockIdx.x == 0 && threadIdx.x < H_) g_S2Mu[threadIdx.x] = 0u;
    const int r = (blockIdx.x * blockDim.x + threadIdx.x) >> 5;
    const int lane = threadIdx.x & 31;
    if (r >= M_ * N_) return;
    const int* src = adj + (size_t)r * N_;
#pragma unroll 8
    for (int w = 0; w < N_ / 32; w++) {
        int a = src[w * 32 + lane];
        uint32_t msk = __ballot_sync(0xffffffffu, a != 0);
        if (lane == 0) g_adjbits[(size_t)r * (N_ / 32) + w] = msk;
    }
}

// ============================================================
// Kernel 1: Wh = x @ W  (fp32) + emit fp16 mma B-frag tiles
// ============================================================
__global__ __launch_bounds__(256) void wh_gemm(const float* __restrict__ x,
                                               const float* __restrict__ W) {
    __shared__ float xs[64][33];
    __shared__ float ws[32][65];
    __shared__ float sC[64][68];
    const int h = blockIdx.y;
    const int i0 = blockIdx.x * 64;
    const int tid = threadIdx.x;
    const int tx = tid & 15, ty = tid >> 4;
    float C[4][4] = {};
    const float* Wp = W + (size_t)h * F_ * D_;

    for (int k0 = 0; k0 < F_; k0 += 32) {
        for (int t = tid; t < 64 * 32; t += 256)
            xs[t >> 5][t & 31] = x[(size_t)(i0 + (t >> 5)) * F_ + k0 + (t & 31)];
        for (int t = tid; t < 32 * 64; t += 256)
            ws[t >> 6][t & 63] = Wp[(size_t)(k0 + (t >> 6)) * D_ + (t & 63)];
        __syncthreads();
#pragma unroll 8
        for (int k = 0; k < 32; k++) {
            float a[4], b[4];
#pragma unroll
            for (int r = 0; r < 4; r++) a[r] = xs[ty * 4 + r][k];
#pragma unroll
            for (int c = 0; c < 4; c++) b[c] = ws[k][tx * 4 + c];
#pragma unroll
            for (int r = 0; r < 4; r++)
#pragma unroll
                for (int c = 0; c < 4; c++) C[r][c] += a[r] * b[c];
        }
        __syncthreads();
    }
#pragma unroll
    for (int r = 0; r < 4; r++)
#pragma unroll
        for (int c = 0; c < 4; c++) {
            g_Wh[((size_t)h * N_ + i0 + ty * 4 + r) * D_ + tx * 4 + c] = C[r][c];
            sC[ty * 4 + r][tx * 4 + c] = C[r][c];
        }
    __syncthreads();
    uint2* dst = g_Bf16 + ((size_t)(h * (N_ / 64) + blockIdx.x)) * 1024;
#pragma unroll
    for (int it = 0; it < 4; it++) {
        int o = tid + it * 256;
        int frag = o >> 5, lane = o & 31;
        int ks = frag >> 3, nf = frag & 7;
        int g = lane >> 2, tg = lane & 3;
        int jlo = ks * 16 + tg * 2;
        int n = nf * 8 + g;
        __half2 lo = __floats2half2_rn(sC[jlo][n],     sC[jlo + 1][n]);
        __half2 hi = __floats2half2_rn(sC[jlo + 8][n], sC[jlo + 9][n]);
        uint2 v;
        v.x = *reinterpret_cast<uint32_t*>(&lo);
        v.y = *reinterpret_cast<uint32_t*>(&hi);
        dst[o] = v;
    }
}

// ============================================================
// Kernel 2: s1, (e2,e2a) table, and per-h max(s2) via atomicMax
// ============================================================
__global__ __launch_bounds__(256) void se_kernel(const float* __restrict__ a1,
                                                 const float* __restrict__ a2) {
    const int warp = (blockIdx.x * blockDim.x + threadIdx.x) >> 5;
    const int lane = threadIdx.x & 31;
    if (warp >= H_ * N_) return;
    const int h = warp / N_;
    const float* row = g_Wh + (size_t)warp * D_;
    float v0 = row[lane], v1 = row[lane + 32];
    float p1 = v0 * a1[h * D_ + lane] + v1 * a1[h * D_ + lane + 32];
    float p2 = v0 * a2[h * D_ + lane] + v1 * a2[h * D_ + lane + 32];
#pragma unroll
    for (int o = 16; o; o >>= 1) {
        p1 += __shfl_xor_sync(0xffffffffu, p1, o);
        p2 += __shfl_xor_sync(0xffffffffu, p2, o);
    }
    if (lane == 0) {
        g_s1[warp] = p1;
        g_tbl[warp] = make_float2(expf(p2), expf(ALPHA_ * p2));
        atomicMax(&g_S2Mu[h], flipf(p2));
    }
}

// ============================================================
// Kernel 3: masked attention, mma.m16n8k16 fp16, j-split.
// A operands generated in packed half2; e1/e1a computed in-prologue;
// j-table persistent in SMEM as packed half2 pairs.
// ============================================================
#define BPITCH  36                 // bitmask row pitch (words)
#define OFF_B   18432              // bitmask: 128 * 36 * 4
#define OFF_TH  (OFF_B + 16384)    // B: 2 * 8KB
#define OFF_E   (OFF_TH + 4096)    // tblh: 1024 j * 4B
#define SMEM_ATT (OFF_E + 1024)    // e1 staging: 128 * float2

__global__ __launch_bounds__(128, 4) void att_mma() {
    extern __shared__ char dsm[];
    const uint32_t sb = smem_u32(dsm);

    const int i0 = blockIdx.x * 128;
    const int h  = blockIdx.y & (H_ - 1);
    const int js = blockIdx.y >> 2;
    const int m  = blockIdx.z;
    const int tid = threadIdx.x;
    const int wid = tid >> 5, lane = tid & 31;
    const int g = lane >> 2, tg = lane & 3;
    const int wbase = wid * 32;
    const int jb = js * (N_ / JS_);          // 1024-j slice base

    // stage bitmask slice (128 rows x 32 words) + first B tile
    {
        const uint32_t* bsrc = g_adjbits + ((size_t)m * N_ + i0) * (N_ / 32) + js * 32;
#pragma unroll
        for (int it = 0; it < 8; it++) {
            int q = tid + it * 128;
            int row = q >> 3, w4 = q & 7;
            cp16(sb + row * (BPITCH * 4) + w4 * 16,
                 bsrc + (size_t)row * (N_ / 32) + w4 * 4);
        }
        const uint4* bs = (const uint4*)(g_Bf16 +
            ((size_t)(h * (N_ / 64) + js * JT_PER_)) * 1024);
#pragma unroll
        for (int r = 0; r < 4; r++)
            cp16(sb + OFF_B + (tid + r * 128) * 16, bs + tid + r * 128);
    }
    CP_COMMIT();

    // convert j-table to packed half2 pairs in SMEM (persistent)
    {
        __half* th = (__half*)(dsm + OFF_TH);
#pragma unroll
        for (int it = 0; it < 8; it++) {
            int jl = tid + it * 128;
            float2 t = g_tbl[h * N_ + jb + jl];
            int base = (jl >> 1) * 4 + (jl & 1);   // {e2pair, e2apair} interleave
            th[base]     = __float2half_rn(t.x);
            th[base + 2] = __float2half_rn(t.y);
        }
    }
    // per-row e1/e1a with power-of-2 softmax-invariant scaling
    {
        float s1 = g_s1[h * N_ + i0 + tid];
        float s2m = unflipf(g_S2Mu[h]);
        float t = s1 + s2m;
        float b = t > 0.f ? t : ALPHA_ * t;
        float e = 9.f - floorf(b * L2E_);
        float2* se1 = (float2*)(dsm + OFF_E);
        se1[tid] = make_float2(exp2f(s1 * L2E_ + e), exp2f(ALPHA_ * s1 * L2E_ + e));
    }
    __syncthreads();

    __half2 e1b[4], e1ab[4];
#pragma unroll
    for (int q = 0; q < 4; q++) {
        float2 v = ((const float2*)(dsm + OFF_E))[wbase + g + q * 8];
        e1b[q]  = __float2half2_rn(v.x);
        e1ab[q] = __float2half2_rn(v.y);
    }
    const uint32_t bones = (g == 0) ? 0x3C003C00u : 0u;

    float acc[2][9][4];
#pragma unroll
    for (int a = 0; a < 2; a++)
#pragma unroll
        for (int b = 0; b < 9; b++)
#pragma unroll
            for (int c = 0; c < 4; c++) acc[a][b][c] = 0.f;

    int buf = 0;
    for (int l = 0; l < JT_PER_; l++) {
        CP_WAIT0();
        __syncthreads();
        if (l + 1 < JT_PER_) {
            const int jt = js * JT_PER_ + l + 1;
            const uint4* bs = (const uint4*)(g_Bf16 + ((size_t)(h * (N_ / 64) + jt)) * 1024);
            uint32_t dB = sb + OFF_B + (buf ^ 1) * 8192;
#pragma unroll
            for (int r = 0; r < 4; r++) cp16(dB + (tid + r * 128) * 16, bs + tid + r * 128);
            CP_COMMIT();
        }

        const uint2*    Bp = (const uint2*)(dsm + OFF_B + buf * 8192);
        const uint2*    th = (const uint2*)(dsm + OFF_TH);   // per pair: {e2x2, e2ax2}
        const uint32_t* bt = (const uint32_t*)dsm;

        uint32_t v0[4], v1[4];
#pragma unroll
        for (int q = 0; q < 4; q++) {
            int rl = wbase + g + q * 8;
            v0[q] = bt[rl * BPITCH + l * 2]     >> (tg * 2);
            v1[q] = bt[rl * BPITCH + l * 2 + 1] >> (tg * 2);
        }
#pragma unroll
        for (int ks = 0; ks < 4; ks++) {
            uint2 T0 = th[l * 32 + ks * 8 + tg];       // cols kk+tg*2, +1
            uint2 T1 = th[l * 32 + ks * 8 + tg + 4];   // cols kk+8+tg*2, +1
            __half2 t0e2  = *reinterpret_cast<__half2*>(&T0.x);
            __half2 t0e2a = *reinterpret_cast<__half2*>(&T0.y);
            __half2 t1e2  = *reinterpret_cast<__half2*>(&T1.x);
            __half2 t1e2a = *reinterpret_cast<__half2*>(&T1.y);
            const int s = (ks & 1) * 16;
            uint32_t A[2][4];
#pragma unroll
            for (int q = 0; q < 4; q++) {
                uint32_t v = (ks < 2) ? v0[q] : v1[q];
                uint32_t xlo = v >> s;
                uint32_t xhi = v >> (s + 8);
                uint32_t mlo = (xlo & 1u) * 0xFFFFu + (xlo & 2u) * 0x7FFF8000u;
                uint32_t mhi = (xhi & 1u) * 0xFFFFu + (xhi & 2u) * 0x7FFF8000u;
                __half2 wlo = __hmax2(__hmul2(e1b[q], t0e2), __hmul2(e1ab[q], t0e2a));
                __half2 whi = __hmax2(__hmul2(e1b[q], t1e2), __hmul2(e1ab[q], t1e2a));
                A[q >> 1][q & 1]       = *reinterpret_cast<uint32_t*>(&wlo) & mlo;
                A[q >> 1][2 + (q & 1)] = *reinterpret_cast<uint32_t*>(&whi) & mhi;
            }
#pragma unroll
            for (int nf = 0; nf < 8; nf++) {
                uint2 b = Bp[(ks * 8 + nf) * 32 + lane];
#pragma unroll
                for (int mf = 0; mf < 2; mf++) {
                    asm volatile(
                        "mma.sync.aligned.m16n8k16.row.col.f32.f16.f16.f32 "
                        "{%0,%1,%2,%3}, {%4,%5,%6,%7}, {%8,%9}, {%0,%1,%2,%3};"
                        : "+f"(acc[mf][nf][0]), "+f"(acc[mf][nf][1]),
                          "+f"(acc[mf][nf][2]), "+f"(acc[mf][nf][3])
                        : "r"(A[mf][0]), "r"(A[mf][1]), "r"(A[mf][2]), "r"(A[mf][3]),
                          "r"(b.x), "r"(b.y));
                }
            }
#pragma unroll
            for (int mf = 0; mf < 2; mf++) {
                asm volatile(
                    "mma.sync.aligned.m16n8k16.row.col.f32.f16.f16.f32 "
                    "{%0,%1,%2,%3}, {%4,%5,%6,%7}, {%8,%9}, {%0,%1,%2,%3};"
                    : "+f"(acc[mf][8][0]), "+f"(acc[mf][8][1]),
                      "+f"(acc[mf][8][2]), "+f"(acc[mf][8][3])
                    : "r"(A[mf][0]), "r"(A[mf][1]), "r"(A[mf][2]), "r"(A[mf][3]),
                      "r"(bones), "r"(bones));
            }
        }
        buf ^= 1;
    }

    // epilogue: raw partial num + den
    const size_t nbase = ((size_t)(js * M_ + m) * N_);
#pragma unroll
    for (int mf = 0; mf < 2; mf++) {
        int r0 = i0 + wbase + mf * 16 + g;
        int r1 = r0 + 8;
#pragma unroll
        for (int nf = 0; nf < 8; nf++) {
            int col = h * D_ + nf * 8 + tg * 2;
            *(float2*)(g_pnum + (nbase + r0) * (H_ * D_) + col) =
                make_float2(acc[mf][nf][0], acc[mf][nf][1]);
            *(float2*)(g_pnum + (nbase + r1) * (H_ * D_) + col) =
                make_float2(acc[mf][nf][2], acc[mf][nf][3]);
        }
        if (tg == 0) {
            float* dp = g_pden + ((size_t)(js * M_ + m) * H_ + h) * N_;
            dp[r0] = acc[mf][8][0];
            dp[r1] = acc[mf][8][2];
        }
    }
}

// ============================================================
// Kernel 4: combine splits: num/den, elu, sum over m (beta==1)
// ============================================================
__device__ __forceinline__ float elu1(float v) { return v > 0.f ? v : expm1f(v); }
__global__ __launch_bounds__(256) void combine_kernel(float* __restrict__ out) {
    const int n = blockIdx.x;
    const int t = threadIdx.x;
    const int h = t >> 6;
    float accv = 0.f;
#pragma unroll
    for (int m = 0; m < M_; m++) {
        float num = 0.f, den = 0.f;
#pragma unroll
        for (int js = 0; js < JS_; js++) {
            int p = js * M_ + m;
            num += g_pnum[((size_t)p * N_ + n) * (H_ * D_) + t];
            den += g_pden[((size_t)p * H_ + h) * N_ + n];
        }
        accv += elu1(num / den);
    }
    out[(size_t)n * (H_ * D_) + t] = accv;
}

extern "C" void kernel_launch(void* const* d_in, const int* in_sizes, int n_in,
                              void* d_out, int out_size) {
    const float* x   = (const float*)d_in[0];
    const int*   adj = (const int*)d_in[1];
    const float* W   = (const float*)d_in[2];
    const float* a1  = (const float*)d_in[3];
    const float* a2  = (const float*)d_in[4];
    // d_in[5..7] (Ws, bs, q_sem) dead: softmax over singleton axis -> beta == 1
    float* out = (float*)d_out;

    cudaFuncSetAttribute(att_mma, cudaFuncAttributeMaxDynamicSharedMemorySize, SMEM_ATT);

    pack_adj<<<(M_ * N_) / 8, 256>>>(adj);
    wh_gemm<<<dim3(N_ / 64, H_), 256>>>(x, W);
    se_kernel<<<(H_ * N_) / 8, 256>>>(a1, a2);
    att_mma<<<dim3(N_ / 128, H_ * JS_, M_), 128, SMEM_ATT>>>();
    combine_kernel<<<N_, 256>>>(out);
}

// round 11
// speedup vs baseline: 7.2708x; 1.3048x over previous
#include <cuda_runtime.h>
#include <cuda_fp16.h>
#include <math.h>
#include <cstdint>

#define N_ 4096
#define F_ 512
#define D_ 64
#define H_ 4
#define M_ 2
#define JS_ 4
#define JT_PER_ 16            // (N_/64)/JS_
#define ALPHA_ 0.2f
#define L2E_ 1.44269504f

// ---- device scratch (no allocation allowed) ----
__device__ float    g_Wh[(size_t)H_ * N_ * D_];
__device__ float    g_s1[H_ * N_];
__device__ float2   g_tbl[H_ * N_];                            // (e2, e2a) fp32
__device__ unsigned g_S2Mu[H_];                                // flipped-float atomic max
__device__ uint32_t g_adjbits[(size_t)M_ * N_ * (N_ / 32)];
__device__ uint2    g_Bf16[(size_t)H_ * (N_ / 64) * 1024];     // fp16 frag tiles
__device__ float    g_pnum[(size_t)JS_ * M_ * N_ * H_ * D_];   // [js][m][n][h*64+d]
__device__ float    g_pden[(size_t)JS_ * M_ * H_ * N_];        // [js][m][h][n]
// split-fp16 operands for whmm
__device__ __half   g_xh[(size_t)N_ * F_], g_xl[(size_t)N_ * F_];
__device__ __half   g_wth[(size_t)H_ * D_ * F_], g_wtl[(size_t)H_ * D_ * F_];

__device__ __forceinline__ uint32_t smem_u32(const void* p) {
    uint32_t a;
    asm("{ .reg .u64 t; cvta.to.shared.u64 t, %1; cvt.u32.u64 %0, t; }" : "=r"(a) : "l"(p));
    return a;
}
__device__ __forceinline__ void cp16(uint32_t dst, const void* src) {
    asm volatile("cp.async.cg.shared.global [%0], [%1], 16;" :: "r"(dst), "l"(src));
}
#define CP_COMMIT() asm volatile("cp.async.commit_group;" ::: "memory")
#define CP_WAIT0()  asm volatile("cp.async.wait_group 0;" ::: "memory")

__device__ __forceinline__ unsigned flipf(float f) {
    unsigned u = __float_as_uint(f);
    return (u & 0x80000000u) ? ~u : (u | 0x80000000u);
}
__device__ __forceinline__ float unflipf(unsigned v) {
    return (v & 0x80000000u) ? __uint_as_float(v & 0x7FFFFFFFu)
                             : __uint_as_float(~v);
}
__device__ __forceinline__ void mma16816(float* c, const uint32_t* a,
                                         uint32_t b0, uint32_t b1) {
    asm volatile(
        "mma.sync.aligned.m16n8k16.row.col.f32.f16.f16.f32 "
        "{%0,%1,%2,%3}, {%4,%5,%6,%7}, {%8,%9}, {%0,%1,%2,%3};"
        : "+f"(c[0]), "+f"(c[1]), "+f"(c[2]), "+f"(c[3])
        : "r"(a[0]), "r"(a[1]), "r"(a[2]), "r"(a[3]), "r"(b0), "r"(b1));
}

// ============================================================
// Kernel 0: pack adj into bitmask (int4 loads + shfl-OR words)
// ============================================================
__global__ __launch_bounds__(256) void pack_adj(const int* __restrict__ adj) {
    if (blockIdx.x == 0 && threadIdx.x < H_) g_S2Mu[threadIdx.x] = 0u;
    const int r = (blockIdx.x * 256 + threadIdx.x) >> 5;
    const int lane = threadIdx.x & 31;
    if (r >= M_ * N_) return;
    const int4* src = (const int4*)(adj + (size_t)r * N_);
#pragma unroll 4
    for (int i = 0; i < 32; i++) {
        int4 a = src[i * 32 + lane];
        uint32_t nib = (a.x != 0 ? 1u : 0u) | (a.y != 0 ? 2u : 0u)
                     | (a.z != 0 ? 4u : 0u) | (a.w != 0 ? 8u : 0u);
        uint32_t val = nib << ((lane & 7) * 4);
        val |= __shfl_xor_sync(0xffffffffu, val, 1);
        val |= __shfl_xor_sync(0xffffffffu, val, 2);
        val |= __shfl_xor_sync(0xffffffffu, val, 4);
        if ((lane & 7) == 0)
            g_adjbits[(size_t)r * 128 + i * 4 + (lane >> 3)] = val;
    }
}

// ============================================================
// Kernel 0b: split x and W into fp16 hi/lo (W also transposed)
// ============================================================
__global__ __launch_bounds__(256) void split_kernel(const float* __restrict__ x,
                                                    const float* __restrict__ W) {
    const int bid = blockIdx.x;
    if (bid < (N_ * F_ / 4) / 256) {                       // x path: float4
        int i4 = bid * 256 + threadIdx.x;
        float4 v = ((const float4*)x)[i4];
        __half2 h01 = __floats2half2_rn(v.x, v.y);
        __half2 h23 = __floats2half2_rn(v.z, v.w);
        float2 f01 = __half22float2(h01), f23 = __half22float2(h23);
        __half2 l01 = __floats2half2_rn(v.x - f01.x, v.y - f01.y);
        __half2 l23 = __floats2half2_rn(v.z - f23.x, v.w - f23.y);
        uint2 uh, ul;
        uh.x = *reinterpret_cast<uint32_t*>(&h01);
        uh.y = *reinterpret_cast<uint32_t*>(&h23);
        ul.x = *reinterpret_cast<uint32_t*>(&l01);
        ul.y = *reinterpret_cast<uint32_t*>(&l23);
        ((uint2*)g_xh)[i4] = uh;
        ((uint2*)g_xl)[i4] = ul;
    } else {                                               // W path: scalar + transpose
        int idx = (bid - (N_ * F_ / 4) / 256) * 256 + threadIdx.x;
        if (idx < H_ * F_ * D_) {
            int hh = idx >> 15, rem = idx & 32767;
            int f = rem >> 6, d = rem & 63;
            float v = W[idx];
            __half hv = __float2half_rn(v);
            __half lv = __float2half_rn(v - __half2float(hv));
            int o = ((hh << 6) + d) * F_ + f;
            g_wth[o] = hv;
            g_wtl[o] = lv;
        }
    }
}

// ============================================================
// Kernel 1: whmm — Wh = x @ W via split-fp16 tensor mma.
// CTA = (64-row tile jt, head h), 128 thr; emits g_Wh + g_Bf16.
// ============================================================
#define WSM_BUF 36864          // 4 tiles * 64*72 halves
#define SMEM_WH (2 * WSM_BUF)

__global__ __launch_bounds__(128) void whmm() {
    extern __shared__ char dsm[];
    const uint32_t sb = smem_u32(dsm);
    const int jt = blockIdx.x, h = blockIdx.y;
    const int i0 = jt * 64;
    const int tid = threadIdx.x;
    const int wid = tid >> 5, lane = tid & 31;
    const int g = lane >> 2, tg = lane & 3;
    const int wrow = wid * 16;

    auto stage = [&](int buf, int kc) {
        uint32_t base = sb + buf * WSM_BUF;
        const size_t xoff = (size_t)i0 * F_ + kc * 64;
        const size_t woff = (size_t)(h * 64) * F_ + kc * 64;
#pragma unroll
        for (int it = 0; it < 4; it++) {
            int q = tid + it * 128;
            int row = q >> 3, seg = q & 7;
            uint32_t d = (uint32_t)(row * 144 + seg * 16);
            cp16(base + d,         g_xh  + xoff + (size_t)row * F_ + seg * 8);
            cp16(base + 9216 + d,  g_xl  + xoff + (size_t)row * F_ + seg * 8);
            cp16(base + 18432 + d, g_wth + woff + (size_t)row * F_ + seg * 8);
            cp16(base + 27648 + d, g_wtl + woff + (size_t)row * F_ + seg * 8);
        }
        CP_COMMIT();
    };

    stage(0, 0);
    float acc[8][4] = {};

    int buf = 0;
    for (int kc = 0; kc < 8; kc++) {
        CP_WAIT0();
        __syncthreads();
        if (kc < 7) stage(buf ^ 1, kc + 1);
        const __half* sxh = (const __half*)(dsm + buf * WSM_BUF);
        const __half* sxl = sxh + 4608;
        const __half* swh = sxh + 9216;
        const __half* swl = sxh + 13824;
#pragma unroll
        for (int ks = 0; ks < 4; ks++) {
            const int c0 = ks * 16 + tg * 2, c1 = c0 + 8;
            const int r0 = (wrow + g) * 72, r1 = (wrow + g + 8) * 72;
            uint32_t ah[4], al[4];
            ah[0] = *(const uint32_t*)(sxh + r0 + c0);
            ah[1] = *(const uint32_t*)(sxh + r1 + c0);
            ah[2] = *(const uint32_t*)(sxh + r0 + c1);
            ah[3] = *(const uint32_t*)(sxh + r1 + c1);
            al[0] = *(const uint32_t*)(sxl + r0 + c0);
            al[1] = *(const uint32_t*)(sxl + r1 + c0);
            al[2] = *(const uint32_t*)(sxl + r0 + c1);
            al[3] = *(const uint32_t*)(sxl + r1 + c1);
#pragma unroll
            for (int nf = 0; nf < 8; nf++) {
                const int n = (nf * 8 + g) * 72;
                uint32_t bh0 = *(const uint32_t*)(swh + n + c0);
                uint32_t bh1 = *(const uint32_t*)(swh + n + c1);
                uint32_t bl0 = *(const uint32_t*)(swl + n + c0);
                uint32_t bl1 = *(const uint32_t*)(swl + n + c1);
                mma16816(acc[nf], ah, bh0, bh1);
                mma16816(acc[nf], ah, bl0, bl1);
                mma16816(acc[nf], al, bh0, bh1);
            }
        }
        buf ^= 1;
        __syncthreads();
    }

    // direct fp32 Wh stores
    const int rg = i0 + wrow + g;
#pragma unroll
    for (int nf = 0; nf < 8; nf++) {
        int c = nf * 8 + tg * 2;
        *(float2*)(g_Wh + ((size_t)h * N_ + rg) * D_ + c) =
            make_float2(acc[nf][0], acc[nf][1]);
        *(float2*)(g_Wh + ((size_t)h * N_ + rg + 8) * D_ + c) =
            make_float2(acc[nf][2], acc[nf][3]);
    }
    // restage to smem for B-frag emit
    float* sC = (float*)dsm;
#pragma unroll
    for (int nf = 0; nf < 8; nf++) {
        int c = nf * 8 + tg * 2;
        int rr = wrow + g;
        sC[rr * 68 + c]           = acc[nf][0];
        sC[rr * 68 + c + 1]       = acc[nf][1];
        sC[(rr + 8) * 68 + c]     = acc[nf][2];
        sC[(rr + 8) * 68 + c + 1] = acc[nf][3];
    }
    __syncthreads();
    uint2* dst = g_Bf16 + ((size_t)(h * (N_ / 64) + jt)) * 1024;
#pragma unroll
    for (int it = 0; it < 8; it++) {
        int o = tid + it * 128;
        int frag = o >> 5, ln = o & 31;
        int ks = frag >> 3, nf = frag & 7;
        int g2 = ln >> 2, tg2 = ln & 3;
        int jlo = ks * 16 + tg2 * 2;
        int n = nf * 8 + g2;
        __half2 lo = __floats2half2_rn(sC[jlo * 68 + n],       sC[(jlo + 1) * 68 + n]);
        __half2 hi = __floats2half2_rn(sC[(jlo + 8) * 68 + n], sC[(jlo + 9) * 68 + n]);
        uint2 v;
        v.x = *reinterpret_cast<uint32_t*>(&lo);
        v.y = *reinterpret_cast<uint32_t*>(&hi);
        dst[o] = v;
    }
}

// ============================================================
// Kernel 2: s1, (e2,e2a) table, per-h max(s2) via atomicMax
// ============================================================
__global__ __launch_bounds__(256) void se_kernel(const float* __restrict__ a1,
                                                 const float* __restrict__ a2) {
    const int warp = (blockIdx.x * blockDim.x + threadIdx.x) >> 5;
    const int lane = threadIdx.x & 31;
    if (warp >= H_ * N_) return;
    const int h = warp / N_;
    const float* row = g_Wh + (size_t)warp * D_;
    float v0 = row[lane], v1 = row[lane + 32];
    float p1 = v0 * a1[h * D_ + lane] + v1 * a1[h * D_ + lane + 32];
    float p2 = v0 * a2[h * D_ + lane] + v1 * a2[h * D_ + lane + 32];
#pragma unroll
    for (int o = 16; o; o >>= 1) {
        p1 += __shfl_xor_sync(0xffffffffu, p1, o);
        p2 += __shfl_xor_sync(0xffffffffu, p2, o);
    }
    if (lane == 0) {
        g_s1[warp] = p1;
        g_tbl[warp] = make_float2(expf(p2), expf(ALPHA_ * p2));
        atomicMax(&g_S2Mu[h], flipf(p2));
    }
}

// ============================================================
// Kernel 3: masked attention, mma.m16n8k16 fp16, j-split.
// ============================================================
#define BPITCH  36
#define OFF_B   18432
#define OFF_TH  (OFF_B + 16384)
#define OFF_E   (OFF_TH + 4096)
#define SMEM_ATT (OFF_E + 1024)

__global__ __launch_bounds__(128, 4) void att_mma() {
    extern __shared__ char dsm[];
    const uint32_t sb = smem_u32(dsm);

    const int i0 = blockIdx.x * 128;
    const int h  = blockIdx.y & (H_ - 1);
    const int js = blockIdx.y >> 2;
    const int m  = blockIdx.z;
    const int tid = threadIdx.x;
    const int wid = tid >> 5, lane = tid & 31;
    const int g = lane >> 2, tg = lane & 3;
    const int wbase = wid * 32;
    const int jb = js * (N_ / JS_);

    {
        const uint32_t* bsrc = g_adjbits + ((size_t)m * N_ + i0) * (N_ / 32) + js * 32;
#pragma unroll
        for (int it = 0; it < 8; it++) {
            int q = tid + it * 128;
            int row = q >> 3, w4 = q & 7;
            cp16(sb + row * (BPITCH * 4) + w4 * 16,
                 bsrc + (size_t)row * (N_ / 32) + w4 * 4);
        }
        const uint4* bs = (const uint4*)(g_Bf16 +
            ((size_t)(h * (N_ / 64) + js * JT_PER_)) * 1024);
#pragma unroll
        for (int r = 0; r < 4; r++)
            cp16(sb + OFF_B + (tid + r * 128) * 16, bs + tid + r * 128);
    }
    CP_COMMIT();

    {
        __half* th = (__half*)(dsm + OFF_TH);
#pragma unroll
        for (int it = 0; it < 8; it++) {
            int jl = tid + it * 128;
            float2 t = g_tbl[h * N_ + jb + jl];
            int base = (jl >> 1) * 4 + (jl & 1);
            th[base]     = __float2half_rn(t.x);
            th[base + 2] = __float2half_rn(t.y);
        }
    }
    {
        float s1 = g_s1[h * N_ + i0 + tid];
        float s2m = unflipf(g_S2Mu[h]);
        float t = s1 + s2m;
        float b = t > 0.f ? t : ALPHA_ * t;
        float e = 9.f - floorf(b * L2E_);
        float2* se1 = (float2*)(dsm + OFF_E);
        se1[tid] = make_float2(exp2f(s1 * L2E_ + e), exp2f(ALPHA_ * s1 * L2E_ + e));
    }
    __syncthreads();

    __half2 e1b[4], e1ab[4];
#pragma unroll
    for (int q = 0; q < 4; q++) {
        float2 v = ((const float2*)(dsm + OFF_E))[wbase + g + q * 8];
        e1b[q]  = __float2half2_rn(v.x);
        e1ab[q] = __float2half2_rn(v.y);
    }
    const uint32_t bones = (g == 0) ? 0x3C003C00u : 0u;

    float acc[2][9][4];
#pragma unroll
    for (int a = 0; a < 2; a++)
#pragma unroll
        for (int b = 0; b < 9; b++)
#pragma unroll
            for (int c = 0; c < 4; c++) acc[a][b][c] = 0.f;

    int buf = 0;
    for (int l = 0; l < JT_PER_; l++) {
        CP_WAIT0();
        __syncthreads();
        if (l + 1 < JT_PER_) {
            const int jt = js * JT_PER_ + l + 1;
            const uint4* bs = (const uint4*)(g_Bf16 + ((size_t)(h * (N_ / 64) + jt)) * 1024);
            uint32_t dB = sb + OFF_B + (buf ^ 1) * 8192;
#pragma unroll
            for (int r = 0; r < 4; r++) cp16(dB + (tid + r * 128) * 16, bs + tid + r * 128);
            CP_COMMIT();
        }

        const uint2*    Bp = (const uint2*)(dsm + OFF_B + buf * 8192);
        const uint2*    th = (const uint2*)(dsm + OFF_TH);
        const uint32_t* bt = (const uint32_t*)dsm;

        uint32_t v0[4], v1[4];
#pragma unroll
        for (int q = 0; q < 4; q++) {
            int rl = wbase + g + q * 8;
            v0[q] = bt[rl * BPITCH + l * 2]     >> (tg * 2);
            v1[q] = bt[rl * BPITCH + l * 2 + 1] >> (tg * 2);
        }
#pragma unroll
        for (int ks = 0; ks < 4; ks++) {
            uint2 T0 = th[l * 32 + ks * 8 + tg];
            uint2 T1 = th[l * 32 + ks * 8 + tg + 4];
            __half2 t0e2  = *reinterpret_cast<__half2*>(&T0.x);
            __half2 t0e2a = *reinterpret_cast<__half2*>(&T0.y);
            __half2 t1e2  = *reinterpret_cast<__half2*>(&T1.x);
            __half2 t1e2a = *reinterpret_cast<__half2*>(&T1.y);
            const int s = (ks & 1) * 16;
            uint32_t A[2][4];
#pragma unroll
            for (int q = 0; q < 4; q++) {
                uint32_t v = (ks < 2) ? v0[q] : v1[q];
                uint32_t xlo = v >> s;
                uint32_t xhi = v >> (s + 8);
                uint32_t mlo = (xlo & 1u) * 0xFFFFu + (xlo & 2u) * 0x7FFF8000u;
                uint32_t mhi = (xhi & 1u) * 0xFFFFu + (xhi & 2u) * 0x7FFF8000u;
                __half2 wlo = __hmax2(__hmul2(e1b[q], t0e2), __hmul2(e1ab[q], t0e2a));
                __half2 whi = __hmax2(__hmul2(e1b[q], t1e2), __hmul2(e1ab[q], t1e2a));
                A[q >> 1][q & 1]       = *reinterpret_cast<uint32_t*>(&wlo) & mlo;
                A[q >> 1][2 + (q & 1)] = *reinterpret_cast<uint32_t*>(&whi) & mhi;
            }
#pragma unroll
            for (int nf = 0; nf < 8; nf++) {
                uint2 b = Bp[(ks * 8 + nf) * 32 + lane];
#pragma unroll
                for (int mf = 0; mf < 2; mf++)
                    mma16816(acc[mf][nf], A[mf], b.x, b.y);
            }
#pragma unroll
            for (int mf = 0; mf < 2; mf++)
                mma16816(acc[mf][8], A[mf], bones, bones);
        }
        buf ^= 1;
    }

    const size_t nbase = ((size_t)(js * M_ + m) * N_);
#pragma unroll
    for (int mf = 0; mf < 2; mf++) {
        int r0 = i0 + wbase + mf * 16 + g;
        int r1 = r0 + 8;
#pragma unroll
        for (int nf = 0; nf < 8; nf++) {
            int col = h * D_ + nf * 8 + tg * 2;
            *(float2*)(g_pnum + (nbase + r0) * (H_ * D_) + col) =
                make_float2(acc[mf][nf][0], acc[mf][nf][1]);
            *(float2*)(g_pnum + (nbase + r1) * (H_ * D_) + col) =
                make_float2(acc[mf][nf][2], acc[mf][nf][3]);
        }
        if (tg == 0) {
            float* dp = g_pden + ((size_t)(js * M_ + m) * H_ + h) * N_;
            dp[r0] = acc[mf][8][0];
            dp[r1] = acc[mf][8][2];
        }
    }
}

// ============================================================
// Kernel 4: combine splits: num/den, elu, sum over m (beta==1)
// ============================================================
__device__ __forceinline__ float elu1(float v) { return v > 0.f ? v : expm1f(v); }
__global__ __launch_bounds__(256) void combine_kernel(float* __restrict__ out) {
    const int n = blockIdx.x;
    const int t = threadIdx.x;
    const int h = t >> 6;
    float accv = 0.f;
#pragma unroll
    for (int m = 0; m < M_; m++) {
        float num = 0.f, den = 0.f;
#pragma unroll
        for (int js = 0; js < JS_; js++) {
            int p = js * M_ + m;
            num += g_pnum[((size_t)p * N_ + n) * (H_ * D_) + t];
            den += g_pden[((size_t)p * H_ + h) * N_ + n];
        }
        accv += elu1(num / den);
    }
    out[(size_t)n * (H_ * D_) + t] = accv;
}

extern "C" void kernel_launch(void* const* d_in, const int* in_sizes, int n_in,
                              void* d_out, int out_size) {
    const float* x   = (const float*)d_in[0];
    const int*   adj = (const int*)d_in[1];
    const float* W   = (const float*)d_in[2];
    const float* a1  = (const float*)d_in[3];
    const float* a2  = (const float*)d_in[4];
    // d_in[5..7] (Ws, bs, q_sem) dead: softmax over singleton axis -> beta == 1
    float* out = (float*)d_out;

    cudaFuncSetAttribute(att_mma, cudaFuncAttributeMaxDynamicSharedMemorySize, SMEM_ATT);
    cudaFuncSetAttribute(whmm, cudaFuncAttributeMaxDynamicSharedMemorySize, SMEM_WH);

    pack_adj<<<(M_ * N_) / 8, 256>>>(adj);
    split_kernel<<<(N_ * F_ / 4) / 256 + (H_ * F_ * D_ + 255) / 256, 256>>>(x, W);
    whmm<<<dim3(N_ / 64, H_), 128, SMEM_WH>>>();
    se_kernel<<<(H_ * N_) / 8, 256>>>(a1, a2);
    att_mma<<<dim3(N_ / 128, H_ * JS_, M_), 128, SMEM_ATT>>>();
    combine_kernel<<<N_, 256>>>(out);
}

// round 12
// speedup vs baseline: 8.0310x; 1.1046x over previous
#include <cuda_runtime.h>
#include <cuda_fp16.h>
#include <math.h>
#include <cstdint>

#define N_ 4096
#define F_ 512
#define D_ 64
#define H_ 4
#define M_ 2
#define JS_ 4
#define JT_PER_ 16            // (N_/64)/JS_
#define ALPHA_ 0.2f
#define L2E_ 1.44269504f

// ---- device scratch (no allocation allowed) ----
__device__ float    g_Wh[(size_t)H_ * N_ * D_];
__device__ float    g_s1[H_ * N_];
__device__ float2   g_tbl[H_ * N_];                            // (e2, e2a) fp32
__device__ unsigned g_S2Mu[H_];                                // flipped-float atomic max
__device__ uint32_t g_adjbits[(size_t)M_ * N_ * (N_ / 32)];
__device__ uint2    g_Bf16[(size_t)H_ * (N_ / 64) * 1024];     // fp16 frag tiles
__device__ float    g_pnum[(size_t)JS_ * M_ * N_ * H_ * D_];   // [js][m][n][h*64+d]
__device__ float    g_pden[(size_t)JS_ * M_ * H_ * N_];        // [js][m][h][n]
// split-fp16 operands for whmm
__device__ __half   g_xh[(size_t)N_ * F_], g_xl[(size_t)N_ * F_];
__device__ __half   g_wth[(size_t)H_ * D_ * F_], g_wtl[(size_t)H_ * D_ * F_];

__device__ __forceinline__ uint32_t smem_u32(const void* p) {
    uint32_t a;
    asm("{ .reg .u64 t; cvta.to.shared.u64 t, %1; cvt.u32.u64 %0, t; }" : "=r"(a) : "l"(p));
    return a;
}
__device__ __forceinline__ void cp16(uint32_t dst, const void* src) {
    asm volatile("cp.async.cg.shared.global [%0], [%1], 16;" :: "r"(dst), "l"(src));
}
#define CP_COMMIT() asm volatile("cp.async.commit_group;" ::: "memory")
#define CP_WAIT0()  asm volatile("cp.async.wait_group 0;" ::: "memory")

__device__ __forceinline__ unsigned flipf(float f) {
    unsigned u = __float_as_uint(f);
    return (u & 0x80000000u) ? ~u : (u | 0x80000000u);
}
__device__ __forceinline__ float unflipf(unsigned v) {
    return (v & 0x80000000u) ? __uint_as_float(v & 0x7FFFFFFFu)
                             : __uint_as_float(~v);
}
__device__ __forceinline__ void mma16816(float* c, const uint32_t* a,
                                         uint32_t b0, uint32_t b1) {
    asm volatile(
        "mma.sync.aligned.m16n8k16.row.col.f32.f16.f16.f32 "
        "{%0,%1,%2,%3}, {%4,%5,%6,%7}, {%8,%9}, {%0,%1,%2,%3};"
        : "+f"(c[0]), "+f"(c[1]), "+f"(c[2]), "+f"(c[3])
        : "r"(a[0]), "r"(a[1]), "r"(a[2]), "r"(a[3]), "r"(b0), "r"(b1));
}

// ============================================================
// Kernel 0: pack adj into bitmask (int4 loads + shfl-OR words)
// ============================================================
__global__ __launch_bounds__(256) void pack_adj(const int* __restrict__ adj) {
    if (blockIdx.x == 0 && threadIdx.x < H_) g_S2Mu[threadIdx.x] = 0u;
    const int r = (blockIdx.x * 256 + threadIdx.x) >> 5;
    const int lane = threadIdx.x & 31;
    if (r >= M_ * N_) return;
    const int4* src = (const int4*)(adj + (size_t)r * N_);
#pragma unroll 4
    for (int i = 0; i < 32; i++) {
        int4 a = src[i * 32 + lane];
        uint32_t nib = (a.x != 0 ? 1u : 0u) | (a.y != 0 ? 2u : 0u)
                     | (a.z != 0 ? 4u : 0u) | (a.w != 0 ? 8u : 0u);
        uint32_t val = nib << ((lane & 7) * 4);
        val |= __shfl_xor_sync(0xffffffffu, val, 1);
        val |= __shfl_xor_sync(0xffffffffu, val, 2);
        val |= __shfl_xor_sync(0xffffffffu, val, 4);
        if ((lane & 7) == 0)
            g_adjbits[(size_t)r * 128 + i * 4 + (lane >> 3)] = val;
    }
}

// ============================================================
// Kernel 0b: split x and W into fp16 hi/lo (W also transposed)
// ============================================================
__global__ __launch_bounds__(256) void split_kernel(const float* __restrict__ x,
                                                    const float* __restrict__ W) {
    const int bid = blockIdx.x;
    if (bid < (N_ * F_ / 4) / 256) {                       // x path: float4
        int i4 = bid * 256 + threadIdx.x;
        float4 v = ((const float4*)x)[i4];
        __half2 h01 = __floats2half2_rn(v.x, v.y);
        __half2 h23 = __floats2half2_rn(v.z, v.w);
        float2 f01 = __half22float2(h01), f23 = __half22float2(h23);
        __half2 l01 = __floats2half2_rn(v.x - f01.x, v.y - f01.y);
        __half2 l23 = __floats2half2_rn(v.z - f23.x, v.w - f23.y);
        uint2 uh, ul;
        uh.x = *reinterpret_cast<uint32_t*>(&h01);
        uh.y = *reinterpret_cast<uint32_t*>(&h23);
        ul.x = *reinterpret_cast<uint32_t*>(&l01);
        ul.y = *reinterpret_cast<uint32_t*>(&l23);
        ((uint2*)g_xh)[i4] = uh;
        ((uint2*)g_xl)[i4] = ul;
    } else {                                               // W path: scalar + transpose
        int idx = (bid - (N_ * F_ / 4) / 256) * 256 + threadIdx.x;
        if (idx < H_ * F_ * D_) {
            int hh = idx >> 15, rem = idx & 32767;
            int f = rem >> 6, d = rem & 63;
            float v = W[idx];
            __half hv = __float2half_rn(v);
            __half lv = __float2half_rn(v - __half2float(hv));
            int o = ((hh << 6) + d) * F_ + f;
            g_wth[o] = hv;
            g_wtl[o] = lv;
        }
    }
}

// ============================================================
// Kernel 1: whmm — Wh = x @ W via split-fp16 tensor mma.
// CTA = (64-row tile jt, head h), 128 thr.
// Epilogue: g_Wh stores, B-frag emit, AND fused s1/s2/exp tables.
// ============================================================
#define WSM_BUF 36864          // 4 tiles * 64*72 halves
#define OFF_A1  18432          // within buffer 0 (free after main loop): a1 staging
#define OFF_A2  (OFF_A1 + 256)
#define SMEM_WH (2 * WSM_BUF)

__global__ __launch_bounds__(128) void whmm(const float* __restrict__ a1,
                                            const float* __restrict__ a2) {
    extern __shared__ char dsm[];
    const uint32_t sb = smem_u32(dsm);
    const int jt = blockIdx.x, h = blockIdx.y;
    const int i0 = jt * 64;
    const int tid = threadIdx.x;
    const int wid = tid >> 5, lane = tid & 31;
    const int g = lane >> 2, tg = lane & 3;
    const int wrow = wid * 16;

    auto stage = [&](int buf, int kc) {
        uint32_t base = sb + buf * WSM_BUF;
        const size_t xoff = (size_t)i0 * F_ + kc * 64;
        const size_t woff = (size_t)(h * 64) * F_ + kc * 64;
#pragma unroll
        for (int it = 0; it < 4; it++) {
            int q = tid + it * 128;
            int row = q >> 3, seg = q & 7;
            uint32_t d = (uint32_t)(row * 144 + seg * 16);
            cp16(base + d,         g_xh  + xoff + (size_t)row * F_ + seg * 8);
            cp16(base + 9216 + d,  g_xl  + xoff + (size_t)row * F_ + seg * 8);
            cp16(base + 18432 + d, g_wth + woff + (size_t)row * F_ + seg * 8);
            cp16(base + 27648 + d, g_wtl + woff + (size_t)row * F_ + seg * 8);
        }
        CP_COMMIT();
    };

    stage(0, 0);
    float acc[8][4] = {};

    int buf = 0;
    for (int kc = 0; kc < 8; kc++) {
        CP_WAIT0();
        __syncthreads();
        if (kc < 7) stage(buf ^ 1, kc + 1);
        const __half* sxh = (const __half*)(dsm + buf * WSM_BUF);
        const __half* sxl = sxh + 4608;
        const __half* swh = sxh + 9216;
        const __half* swl = sxh + 13824;
#pragma unroll
        for (int ks = 0; ks < 4; ks++) {
            const int c0 = ks * 16 + tg * 2, c1 = c0 + 8;
            const int r0 = (wrow + g) * 72, r1 = (wrow + g + 8) * 72;
            uint32_t ah[4], al[4];
            ah[0] = *(const uint32_t*)(sxh + r0 + c0);
            ah[1] = *(const uint32_t*)(sxh + r1 + c0);
            ah[2] = *(const uint32_t*)(sxh + r0 + c1);
            ah[3] = *(const uint32_t*)(sxh + r1 + c1);
            al[0] = *(const uint32_t*)(sxl + r0 + c0);
            al[1] = *(const uint32_t*)(sxl + r1 + c0);
            al[2] = *(const uint32_t*)(sxl + r0 + c1);
            al[3] = *(const uint32_t*)(sxl + r1 + c1);
#pragma unroll
            for (int nf = 0; nf < 8; nf++) {
                const int n = (nf * 8 + g) * 72;
                uint32_t bh0 = *(const uint32_t*)(swh + n + c0);
                uint32_t bh1 = *(const uint32_t*)(swh + n + c1);
                uint32_t bl0 = *(const uint32_t*)(swl + n + c0);
                uint32_t bl1 = *(const uint32_t*)(swl + n + c1);
                mma16816(acc[nf], ah, bh0, bh1);
                mma16816(acc[nf], ah, bl0, bl1);
                mma16816(acc[nf], al, bh0, bh1);
            }
        }
        buf ^= 1;
        __syncthreads();
    }

    // ---- epilogue part 1: direct fp32 Wh stores
    const int rg = i0 + wrow + g;
#pragma unroll
    for (int nf = 0; nf < 8; nf++) {
        int c = nf * 8 + tg * 2;
        *(float2*)(g_Wh + ((size_t)h * N_ + rg) * D_ + c) =
            make_float2(acc[nf][0], acc[nf][1]);
        *(float2*)(g_Wh + ((size_t)h * N_ + rg + 8) * D_ + c) =
            make_float2(acc[nf][2], acc[nf][3]);
    }
    // ---- restage tile to smem; stage a1/a2
    float* sC = (float*)dsm;
#pragma unroll
    for (int nf = 0; nf < 8; nf++) {
        int c = nf * 8 + tg * 2;
        int rr = wrow + g;
        sC[rr * 68 + c]           = acc[nf][0];
        sC[rr * 68 + c + 1]       = acc[nf][1];
        sC[(rr + 8) * 68 + c]     = acc[nf][2];
        sC[(rr + 8) * 68 + c + 1] = acc[nf][3];
    }
    float* a1s = (float*)(dsm + OFF_A1);
    float* a2s = (float*)(dsm + OFF_A2);
    if (tid < 64) {
        a1s[tid] = a1[h * D_ + tid];
        a2s[tid] = a2[h * D_ + tid];
    }
    __syncthreads();

    // ---- epilogue part 2: B-frag emit
    uint2* dst = g_Bf16 + ((size_t)(h * (N_ / 64) + jt)) * 1024;
#pragma unroll
    for (int it = 0; it < 8; it++) {
        int o = tid + it * 128;
        int frag = o >> 5, ln = o & 31;
        int ks = frag >> 3, nf = frag & 7;
        int g2 = ln >> 2, tg2 = ln & 3;
        int jlo = ks * 16 + tg2 * 2;
        int n = nf * 8 + g2;
        __half2 lo = __floats2half2_rn(sC[jlo * 68 + n],       sC[(jlo + 1) * 68 + n]);
        __half2 hi = __floats2half2_rn(sC[(jlo + 8) * 68 + n], sC[(jlo + 9) * 68 + n]);
        uint2 v;
        v.x = *reinterpret_cast<uint32_t*>(&lo);
        v.y = *reinterpret_cast<uint32_t*>(&hi);
        dst[o] = v;
    }

    // ---- epilogue part 3 (fused se): s1/s2 per row, exp tables, s2 max
    {
        const int row  = tid >> 1;           // 0..63
        const int half = tid & 1;
        const float* rp = sC + row * 68 + half * 32;
        const float* ap1 = a1s + half * 32;
        const float* ap2 = a2s + half * 32;
        float p1 = 0.f, p2 = 0.f;
#pragma unroll
        for (int d = 0; d < 32; d++) {
            float v = rp[d];
            p1 += v * ap1[d];
            p2 += v * ap2[d];
        }
        p1 += __shfl_xor_sync(0xffffffffu, p1, 1);
        p2 += __shfl_xor_sync(0xffffffffu, p2, 1);
        if (half == 0) {
            int gg = h * N_ + i0 + row;
            g_s1[gg] = p1;
            g_tbl[gg] = make_float2(expf(p2), expf(ALPHA_ * p2));
        }
        // warp-level max of p2 (all lanes hold a valid row value)
        float mx = p2;
#pragma unroll
        for (int o = 16; o; o >>= 1)
            mx = fmaxf(mx, __shfl_xor_sync(0xffffffffu, mx, o));
        if (lane == 0) atomicMax(&g_S2Mu[h], flipf(mx));
    }
}

// ============================================================
// Kernel 3: masked attention, mma.m16n8k16 fp16, j-split.
// ============================================================
#define BPITCH  36
#define OFF_B   18432
#define OFF_TH  (OFF_B + 16384)
#define OFF_E   (OFF_TH + 4096)
#define SMEM_ATT (OFF_E + 1024)

__global__ __launch_bounds__(128, 4) void att_mma() {
    extern __shared__ char dsm[];
    const uint32_t sb = smem_u32(dsm);

    const int i0 = blockIdx.x * 128;
    const int h  = blockIdx.y & (H_ - 1);
    const int js = blockIdx.y >> 2;
    const int m  = blockIdx.z;
    const int tid = threadIdx.x;
    const int wid = tid >> 5, lane = tid & 31;
    const int g = lane >> 2, tg = lane & 3;
    const int wbase = wid * 32;
    const int jb = js * (N_ / JS_);

    {
        const uint32_t* bsrc = g_adjbits + ((size_t)m * N_ + i0) * (N_ / 32) + js * 32;
#pragma unroll
        for (int it = 0; it < 8; it++) {
            int q = tid + it * 128;
            int row = q >> 3, w4 = q & 7;
            cp16(sb + row * (BPITCH * 4) + w4 * 16,
                 bsrc + (size_t)row * (N_ / 32) + w4 * 4);
        }
        const uint4* bs = (const uint4*)(g_Bf16 +
            ((size_t)(h * (N_ / 64) + js * JT_PER_)) * 1024);
#pragma unroll
        for (int r = 0; r < 4; r++)
            cp16(sb + OFF_B + (tid + r * 128) * 16, bs + tid + r * 128);
    }
    CP_COMMIT();

    {
        __half* th = (__half*)(dsm + OFF_TH);
#pragma unroll
        for (int it = 0; it < 8; it++) {
            int jl = tid + it * 128;
            float2 t = g_tbl[h * N_ + jb + jl];
            int base = (jl >> 1) * 4 + (jl & 1);
            th[base]     = __float2half_rn(t.x);
            th[base + 2] = __float2half_rn(t.y);
        }
    }
    {
        float s1 = g_s1[h * N_ + i0 + tid];
        float s2m = unflipf(g_S2Mu[h]);
        float t = s1 + s2m;
        float b = t > 0.f ? t : ALPHA_ * t;
        float e = 9.f - floorf(b * L2E_);
        float2* se1 = (float2*)(dsm + OFF_E);
        se1[tid] = make_float2(exp2f(s1 * L2E_ + e), exp2f(ALPHA_ * s1 * L2E_ + e));
    }
    __syncthreads();

    __half2 e1b[4], e1ab[4];
#pragma unroll
    for (int q = 0; q < 4; q++) {
        float2 v = ((const float2*)(dsm + OFF_E))[wbase + g + q * 8];
        e1b[q]  = __float2half2_rn(v.x);
        e1ab[q] = __float2half2_rn(v.y);
    }
    const uint32_t bones = (g == 0) ? 0x3C003C00u : 0u;

    float acc[2][9][4];
#pragma unroll
    for (int a = 0; a < 2; a++)
#pragma unroll
        for (int b = 0; b < 9; b++)
#pragma unroll
            for (int c = 0; c < 4; c++) acc[a][b][c] = 0.f;

    int buf = 0;
    for (int l = 0; l < JT_PER_; l++) {
        CP_WAIT0();
        __syncthreads();
        if (l + 1 < JT_PER_) {
            const int jt = js * JT_PER_ + l + 1;
            const uint4* bs = (const uint4*)(g_Bf16 + ((size_t)(h * (N_ / 64) + jt)) * 1024);
            uint32_t dB = sb + OFF_B + (buf ^ 1) * 8192;
#pragma unroll
            for (int r = 0; r < 4; r++) cp16(dB + (tid + r * 128) * 16, bs + tid + r * 128);
            CP_COMMIT();
        }

        const uint2*    Bp = (const uint2*)(dsm + OFF_B + buf * 8192);
        const uint2*    th = (const uint2*)(dsm + OFF_TH);
        const uint32_t* bt = (const uint32_t*)dsm;

        uint32_t v0[4], v1[4];
#pragma unroll
        for (int q = 0; q < 4; q++) {
            int rl = wbase + g + q * 8;
            v0[q] = bt[rl * BPITCH + l * 2]     >> (tg * 2);
            v1[q] = bt[rl * BPITCH + l * 2 + 1] >> (tg * 2);
        }
#pragma unroll
        for (int ks = 0; ks < 4; ks++) {
            uint2 T0 = th[l * 32 + ks * 8 + tg];
            uint2 T1 = th[l * 32 + ks * 8 + tg + 4];
            __half2 t0e2  = *reinterpret_cast<__half2*>(&T0.x);
            __half2 t0e2a = *reinterpret_cast<__half2*>(&T0.y);
            __half2 t1e2  = *reinterpret_cast<__half2*>(&T1.x);
            __half2 t1e2a = *reinterpret_cast<__half2*>(&T1.y);
            const int s = (ks & 1) * 16;
            uint32_t A[2][4];
#pragma unroll
            for (int q = 0; q < 4; q++) {
                uint32_t v = (ks < 2) ? v0[q] : v1[q];
                uint32_t xlo = v >> s;
                uint32_t xhi = v >> (s + 8);
                uint32_t mlo = (xlo & 1u) * 0xFFFFu + (xlo & 2u) * 0x7FFF8000u;
                uint32_t mhi = (xhi & 1u) * 0xFFFFu + (xhi & 2u) * 0x7FFF8000u;
                __half2 wlo = __hmax2(__hmul2(e1b[q], t0e2), __hmul2(e1ab[q], t0e2a));
                __half2 whi = __hmax2(__hmul2(e1b[q], t1e2), __hmul2(e1ab[q], t1e2a));
                A[q >> 1][q & 1]       = *reinterpret_cast<uint32_t*>(&wlo) & mlo;
                A[q >> 1][2 + (q & 1)] = *reinterpret_cast<uint32_t*>(&whi) & mhi;
            }
#pragma unroll
            for (int nf = 0; nf < 8; nf++) {
                uint2 b = Bp[(ks * 8 + nf) * 32 + lane];
#pragma unroll
                for (int mf = 0; mf < 2; mf++)
                    mma16816(acc[mf][nf], A[mf], b.x, b.y);
            }
#pragma unroll
            for (int mf = 0; mf < 2; mf++)
                mma16816(acc[mf][8], A[mf], bones, bones);
        }
        buf ^= 1;
    }

    const size_t nbase = ((size_t)(js * M_ + m) * N_);
#pragma unroll
    for (int mf = 0; mf < 2; mf++) {
        int r0 = i0 + wbase + mf * 16 + g;
        int r1 = r0 + 8;
#pragma unroll
        for (int nf = 0; nf < 8; nf++) {
            int col = h * D_ + nf * 8 + tg * 2;
            *(float2*)(g_pnum + (nbase + r0) * (H_ * D_) + col) =
                make_float2(acc[mf][nf][0], acc[mf][nf][1]);
            *(float2*)(g_pnum + (nbase + r1) * (H_ * D_) + col) =
                make_float2(acc[mf][nf][2], acc[mf][nf][3]);
        }
        if (tg == 0) {
            float* dp = g_pden + ((size_t)(js * M_ + m) * H_ + h) * N_;
            dp[r0] = acc[mf][8][0];
            dp[r1] = acc[mf][8][2];
        }
    }
}

// ============================================================
// Kernel 4: combine splits: num/den, elu, sum over m (beta==1)
// ============================================================
__device__ __forceinline__ float elu1(float v) { return v > 0.f ? v : expm1f(v); }
__global__ __launch_bounds__(256) void combine_kernel(float* __restrict__ out) {
    const int n = blockIdx.x;
    const int t = threadIdx.x;
    const int h = t >> 6;
    float accv = 0.f;
#pragma unroll
    for (int m = 0; m < M_; m++) {
        float num = 0.f, den = 0.f;
#pragma unroll
        for (int js = 0; js < JS_; js++) {
            int p = js * M_ + m;
            num += g_pnum[((size_t)p * N_ + n) * (H_ * D_) + t];
            den += g_pden[((size_t)p * H_ + h) * N_ + n];
        }
        accv += elu1(num / den);
    }
    out[(size_t)n * (H_ * D_) + t] = accv;
}

extern "C" void kernel_launch(void* const* d_in, const int* in_sizes, int n_in,
                              void* d_out, int out_size) {
    const float* x   = (const float*)d_in[0];
    const int*   adj = (const int*)d_in[1];
    const float* W   = (const float*)d_in[2];
    const float* a1  = (const float*)d_in[3];
    const float* a2  = (const float*)d_in[4];
    // d_in[5..7] (Ws, bs, q_sem) dead: softmax over singleton axis -> beta == 1
    float* out = (float*)d_out;

    cudaFuncSetAttribute(att_mma, cudaFuncAttributeMaxDynamicSharedMemorySize, SMEM_ATT);
    cudaFuncSetAttribute(whmm, cudaFuncAttributeMaxDynamicSharedMemorySize, SMEM_WH);

    pack_adj<<<(M_ * N_) / 8, 256>>>(adj);
    split_kernel<<<(N_ * F_ / 4) / 256 + (H_ * F_ * D_ + 255) / 256, 256>>>(x, W);
    whmm<<<dim3(N_ / 64, H_), 128, SMEM_WH>>>(a1, a2);
    att_mma<<<dim3(N_ / 128, H_ * JS_, M_), 128, SMEM_ATT>>>();
    combine_kernel<<<N_, 256>>>(out);
}

// round 14
// speedup vs baseline: 8.4140x; 1.0477x over previous
#include <cuda_runtime.h>
#include <cuda_fp16.h>
#include <math.h>
#include <cstdint>

#define N_ 4096
#define F_ 512
#define D_ 64
#define H_ 4
#define M_ 2
#define JS_ 4
#define JT_PER_ 16            // (N_/64)/JS_
#define ALPHA_ 0.2f
#define L2E_ 1.44269504f

// ---- device scratch (no allocation allowed) ----
__device__ float    g_Wh[(size_t)H_ * N_ * D_];
__device__ float    g_s1[H_ * N_];
__device__ float2   g_tbl[H_ * N_];                            // (e2, e2a) fp32
__device__ unsigned g_S2Mu[H_];                                // flipped-float atomic max
__device__ uint32_t g_adjbits[(size_t)M_ * N_ * (N_ / 32)];
__device__ uint2    g_Bf16[(size_t)H_ * (N_ / 64) * 1024];     // fp16 frag tiles
__device__ float    g_pnum[(size_t)JS_ * M_ * N_ * H_ * D_];   // [js][m][n][h*64+d]
__device__ float    g_pden[(size_t)JS_ * M_ * H_ * N_];        // [js][m][h][n]
// split-fp16 operands for whmm
__device__ __half   g_xh[(size_t)N_ * F_], g_xl[(size_t)N_ * F_];
__device__ __half   g_wth[(size_t)H_ * D_ * F_], g_wtl[(size_t)H_ * D_ * F_];

__device__ __forceinline__ uint32_t smem_u32(const void* p) {
    uint32_t a;
    asm("{ .reg .u64 t; cvta.to.shared.u64 t, %1; cvt.u32.u64 %0, t; }" : "=r"(a) : "l"(p));
    return a;
}
__device__ __forceinline__ void cp16(uint32_t dst, const void* src) {
    asm volatile("cp.async.cg.shared.global [%0], [%1], 16;" :: "r"(dst), "l"(src));
}
#define CP_COMMIT() asm volatile("cp.async.commit_group;" ::: "memory")
#define CP_WAIT0()  asm volatile("cp.async.wait_group 0;" ::: "memory")

// PRMT with sign-replication mode (nibble bit3). MUST be inline asm:
// __byte_perm's documented selector range is 0..7 per nibble, so nvcc may
// constant-fold it without the sign mode. prmt.b32 default mode per PTX ISA
// replicates the selected byte's MSB when the selector nibble has bit3 set.
__device__ __forceinline__ uint32_t prmt_sign(uint32_t a, uint32_t b, uint32_t s) {
    uint32_t d;
    asm("prmt.b32 %0, %1, %2, %3;" : "=r"(d) : "r"(a), "r"(b), "r"(s));
    return d;
}

__device__ __forceinline__ unsigned flipf(float f) {
    unsigned u = __float_as_uint(f);
    return (u & 0x80000000u) ? ~u : (u | 0x80000000u);
}
__device__ __forceinline__ float unflipf(unsigned v) {
    return (v & 0x80000000u) ? __uint_as_float(v & 0x7FFFFFFFu)
                             : __uint_as_float(~v);
}
__device__ __forceinline__ void mma16816(float* c, const uint32_t* a,
                                         uint32_t b0, uint32_t b1) {
    asm volatile(
        "mma.sync.aligned.m16n8k16.row.col.f32.f16.f16.f32 "
        "{%0,%1,%2,%3}, {%4,%5,%6,%7}, {%8,%9}, {%0,%1,%2,%3};"
        : "+f"(c[0]), "+f"(c[1]), "+f"(c[2]), "+f"(c[3])
        : "r"(a[0]), "r"(a[1]), "r"(a[2]), "r"(a[3]), "r"(b0), "r"(b1));
}

// ============================================================
// Kernel 0: pack adj into bitmask (int4 loads + shfl-OR words)
// ============================================================
__global__ __launch_bounds__(256) void pack_adj(const int* __restrict__ adj) {
    if (blockIdx.x == 0 && threadIdx.x < H_) g_S2Mu[threadIdx.x] = 0u;
    const int r = (blockIdx.x * 256 + threadIdx.x) >> 5;
    const int lane = threadIdx.x & 31;
    if (r >= M_ * N_) return;
    const int4* src = (const int4*)(adj + (size_t)r * N_);
#pragma unroll 4
    for (int i = 0; i < 32; i++) {
        int4 a = src[i * 32 + lane];
        uint32_t nib = (a.x != 0 ? 1u : 0u) | (a.y != 0 ? 2u : 0u)
                     | (a.z != 0 ? 4u : 0u) | (a.w != 0 ? 8u : 0u);
        uint32_t val = nib << ((lane & 7) * 4);
        val |= __shfl_xor_sync(0xffffffffu, val, 1);
        val |= __shfl_xor_sync(0xffffffffu, val, 2);
        val |= __shfl_xor_sync(0xffffffffu, val, 4);
        if ((lane & 7) == 0)
            g_adjbits[(size_t)r * 128 + i * 4 + (lane >> 3)] = val;
    }
}

// ============================================================
// Kernel 0b: split x and W into fp16 hi/lo (W also transposed)
// ============================================================
__global__ __launch_bounds__(256) void split_kernel(const float* __restrict__ x,
                                                    const float* __restrict__ W) {
    const int bid = blockIdx.x;
    if (bid < (N_ * F_ / 4) / 256) {                       // x path: float4
        int i4 = bid * 256 + threadIdx.x;
        float4 v = ((const float4*)x)[i4];
        __half2 h01 = __floats2half2_rn(v.x, v.y);
        __half2 h23 = __floats2half2_rn(v.z, v.w);
        float2 f01 = __half22float2(h01), f23 = __half22float2(h23);
        __half2 l01 = __floats2half2_rn(v.x - f01.x, v.y - f01.y);
        __half2 l23 = __floats2half2_rn(v.z - f23.x, v.w - f23.y);
        uint2 uh, ul;
        uh.x = *reinterpret_cast<uint32_t*>(&h01);
        uh.y = *reinterpret_cast<uint32_t*>(&h23);
        ul.x = *reinterpret_cast<uint32_t*>(&l01);
        ul.y = *reinterpret_cast<uint32_t*>(&l23);
        ((uint2*)g_xh)[i4] = uh;
        ((uint2*)g_xl)[i4] = ul;
    } else {                                               // W path: scalar + transpose
        int idx = (bid - (N_ * F_ / 4) / 256) * 256 + threadIdx.x;
        if (idx < H_ * F_ * D_) {
            int hh = idx >> 15, rem = idx & 32767;
            int f = rem >> 6, d = rem & 63;
            float v = W[idx];
            __half hv = __float2half_rn(v);
            __half lv = __float2half_rn(v - __half2float(hv));
            int o = ((hh << 6) + d) * F_ + f;
            g_wth[o] = hv;
            g_wtl[o] = lv;
        }
    }
}

// ============================================================
// Kernel 1: whmm — Wh = x @ W via split-fp16 tensor mma.
// CTA = (64-row tile jt, head h), 128 thr.
// Epilogue: g_Wh stores, B-frag emit, AND fused s1/s2/exp tables.
// ============================================================
#define WSM_BUF 36864          // 4 tiles * 64*72 halves
#define OFF_A1  18432          // within buffer 0 (free after main loop): a1 staging
#define OFF_A2  (OFF_A1 + 256)
#define SMEM_WH (2 * WSM_BUF)

__global__ __launch_bounds__(128) void whmm(const float* __restrict__ a1,
                                            const float* __restrict__ a2) {
    extern __shared__ char dsm[];
    const uint32_t sb = smem_u32(dsm);
    const int jt = blockIdx.x, h = blockIdx.y;
    const int i0 = jt * 64;
    const int tid = threadIdx.x;
    const int wid = tid >> 5, lane = tid & 31;
    const int g = lane >> 2, tg = lane & 3;
    const int wrow = wid * 16;

    auto stage = [&](int buf, int kc) {
        uint32_t base = sb + buf * WSM_BUF;
        const size_t xoff = (size_t)i0 * F_ + kc * 64;
        const size_t woff = (size_t)(h * 64) * F_ + kc * 64;
#pragma unroll
        for (int it = 0; it < 4; it++) {
            int q = tid + it * 128;
            int row = q >> 3, seg = q & 7;
            uint32_t d = (uint32_t)(row * 144 + seg * 16);
            cp16(base + d,         g_xh  + xoff + (size_t)row * F_ + seg * 8);
            cp16(base + 9216 + d,  g_xl  + xoff + (size_t)row * F_ + seg * 8);
            cp16(base + 18432 + d, g_wth + woff + (size_t)row * F_ + seg * 8);
            cp16(base + 27648 + d, g_wtl + woff + (size_t)row * F_ + seg * 8);
        }
        CP_COMMIT();
    };

    stage(0, 0);
    float acc[8][4] = {};

    int buf = 0;
    for (int kc = 0; kc < 8; kc++) {
        CP_WAIT0();
        __syncthreads();
        if (kc < 7) stage(buf ^ 1, kc + 1);
        const __half* sxh = (const __half*)(dsm + buf * WSM_BUF);
        const __half* sxl = sxh + 4608;
        const __half* swh = sxh + 9216;
        const __half* swl = sxh + 13824;
#pragma unroll
        for (int ks = 0; ks < 4; ks++) {
            const int c0 = ks * 16 + tg * 2, c1 = c0 + 8;
            const int r0 = (wrow + g) * 72, r1 = (wrow + g + 8) * 72;
            uint32_t ah[4], al[4];
            ah[0] = *(const uint32_t*)(sxh + r0 + c0);
            ah[1] = *(const uint32_t*)(sxh + r1 + c0);
            ah[2] = *(const uint32_t*)(sxh + r0 + c1);
            ah[3] = *(const uint32_t*)(sxh + r1 + c1);
            al[0] = *(const uint32_t*)(sxl + r0 + c0);
            al[1] = *(const uint32_t*)(sxl + r1 + c0);
            al[2] = *(const uint32_t*)(sxl + r0 + c1);
            al[3] = *(const uint32_t*)(sxl + r1 + c1);
#pragma unroll
            for (int nf = 0; nf < 8; nf++) {
                const int n = (nf * 8 + g) * 72;
                uint32_t bh0 = *(const uint32_t*)(swh + n + c0);
                uint32_t bh1 = *(const uint32_t*)(swh + n + c1);
                uint32_t bl0 = *(const uint32_t*)(swl + n + c0);
                uint32_t bl1 = *(const uint32_t*)(swl + n + c1);
                mma16816(acc[nf], ah, bh0, bh1);
                mma16816(acc[nf], ah, bl0, bl1);
                mma16816(acc[nf], al, bh0, bh1);
            }
        }
        buf ^= 1;
        __syncthreads();
    }

    // ---- epilogue part 1: direct fp32 Wh stores
    const int rg = i0 + wrow + g;
#pragma unroll
    for (int nf = 0; nf < 8; nf++) {
        int c = nf * 8 + tg * 2;
        *(float2*)(g_Wh + ((size_t)h * N_ + rg) * D_ + c) =
            make_float2(acc[nf][0], acc[nf][1]);
        *(float2*)(g_Wh + ((size_t)h * N_ + rg + 8) * D_ + c) =
            make_float2(acc[nf][2], acc[nf][3]);
    }
    // ---- restage tile to smem; stage a1/a2
    float* sC = (float*)dsm;
#pragma unroll
    for (int nf = 0; nf < 8; nf++) {
        int c = nf * 8 + tg * 2;
        int rr = wrow + g;
        sC[rr * 68 + c]           = acc[nf][0];
        sC[rr * 68 + c + 1]       = acc[nf][1];
        sC[(rr + 8) * 68 + c]     = acc[nf][2];
        sC[(rr + 8) * 68 + c + 1] = acc[nf][3];
    }
    float* a1s = (float*)(dsm + OFF_A1);
    float* a2s = (float*)(dsm + OFF_A2);
    if (tid < 64) {
        a1s[tid] = a1[h * D_ + tid];
        a2s[tid] = a2[h * D_ + tid];
    }
    __syncthreads();

    // ---- epilogue part 2: B-frag emit
    uint2* dst = g_Bf16 + ((size_t)(h * (N_ / 64) + jt)) * 1024;
#pragma unroll
    for (int it = 0; it < 8; it++) {
        int o = tid + it * 128;
        int frag = o >> 5, ln = o & 31;
        int ks = frag >> 3, nf = frag & 7;
        int g2 = ln >> 2, tg2 = ln & 3;
        int jlo = ks * 16 + tg2 * 2;
        int n = nf * 8 + g2;
        __half2 lo = __floats2half2_rn(sC[jlo * 68 + n],       sC[(jlo + 1) * 68 + n]);
        __half2 hi = __floats2half2_rn(sC[(jlo + 8) * 68 + n], sC[(jlo + 9) * 68 + n]);
        uint2 v;
        v.x = *reinterpret_cast<uint32_t*>(&lo);
        v.y = *reinterpret_cast<uint32_t*>(&hi);
        dst[o] = v;
    }

    // ---- epilogue part 3 (fused se): s1/s2 per row, exp tables, s2 max
    {
        const int row  = tid >> 1;           // 0..63
        const int half = tid & 1;
        const float* rp = sC + row * 68 + half * 32;
        const float* ap1 = a1s + half * 32;
        const float* ap2 = a2s + half * 32;
        float p1 = 0.f, p2 = 0.f;
#pragma unroll
        for (int d = 0; d < 32; d++) {
            float v = rp[d];
            p1 += v * ap1[d];
            p2 += v * ap2[d];
        }
        p1 += __shfl_xor_sync(0xffffffffu, p1, 1);
        p2 += __shfl_xor_sync(0xffffffffu, p2, 1);
        if (half == 0) {
            int gg = h * N_ + i0 + row;
            g_s1[gg] = p1;
            g_tbl[gg] = make_float2(expf(p2), expf(ALPHA_ * p2));
        }
        float mx = p2;
#pragma unroll
        for (int o = 16; o; o >>= 1)
            mx = fmaxf(mx, __shfl_xor_sync(0xffffffffu, mx, o));
        if (lane == 0) atomicMax(&g_S2Mu[h], flipf(mx));
    }
}

// ============================================================
// Kernel 3: masked attention, mma.m16n8k16 fp16, j-split.
// Masks via asm PRMT sign-replication (bit-identical to the
// halfword-mask IMAD chain; intrinsic __byte_perm is NOT safe
// for selector nibbles >= 8).
// ============================================================
#define BPITCH  36
#define OFF_B   18432
#define OFF_TH  (OFF_B + 16384)
#define OFF_E   (OFF_TH + 4096)
#define SMEM_ATT (OFF_E + 1024)

__global__ __launch_bounds__(128, 4) void att_mma() {
    extern __shared__ char dsm[];
    const uint32_t sb = smem_u32(dsm);

    const int i0 = blockIdx.x * 128;
    const int h  = blockIdx.y & (H_ - 1);
    const int js = blockIdx.y >> 2;
    const int m  = blockIdx.z;
    const int tid = threadIdx.x;
    const int wid = tid >> 5, lane = tid & 31;
    const int g = lane >> 2, tg = lane & 3;
    const int wbase = wid * 32;
    const int jb = js * (N_ / JS_);

    {
        const uint32_t* bsrc = g_adjbits + ((size_t)m * N_ + i0) * (N_ / 32) + js * 32;
#pragma unroll
        for (int it = 0; it < 8; it++) {
            int q = tid + it * 128;
            int row = q >> 3, w4 = q & 7;
            cp16(sb + row * (BPITCH * 4) + w4 * 16,
                 bsrc + (size_t)row * (N_ / 32) + w4 * 4);
        }
        const uint4* bs = (const uint4*)(g_Bf16 +
            ((size_t)(h * (N_ / 64) + js * JT_PER_)) * 1024);
#pragma unroll
        for (int r = 0; r < 4; r++)
            cp16(sb + OFF_B + (tid + r * 128) * 16, bs + tid + r * 128);
    }
    CP_COMMIT();

    {
        __half* th = (__half*)(dsm + OFF_TH);
#pragma unroll
        for (int it = 0; it < 8; it++) {
            int jl = tid + it * 128;
            float2 t = g_tbl[h * N_ + jb + jl];
            int base = (jl >> 1) * 4 + (jl & 1);
            th[base]     = __float2half_rn(t.x);
            th[base + 2] = __float2half_rn(t.y);
        }
    }
    {
        float s1 = g_s1[h * N_ + i0 + tid];
        float s2m = unflipf(g_S2Mu[h]);
        float t = s1 + s2m;
        float b = t > 0.f ? t : ALPHA_ * t;
        float e = 9.f - floorf(b * L2E_);
        float2* se1 = (float2*)(dsm + OFF_E);
        se1[tid] = make_float2(exp2f(s1 * L2E_ + e), exp2f(ALPHA_ * s1 * L2E_ + e));
    }
    __syncthreads();

    __half2 e1b[4], e1ab[4];
#pragma unroll
    for (int q = 0; q < 4; q++) {
        float2 v = ((const float2*)(dsm + OFF_E))[wbase + g + q * 8];
        e1b[q]  = __float2half2_rn(v.x);
        e1ab[q] = __float2half2_rn(v.y);
    }
    const uint32_t bones = (g == 0) ? 0x3C003C00u : 0u;

    float acc[2][9][4];
#pragma unroll
    for (int a = 0; a < 2; a++)
#pragma unroll
        for (int b = 0; b < 9; b++)
#pragma unroll
            for (int c = 0; c < 4; c++) acc[a][b][c] = 0.f;

    int buf = 0;
    for (int l = 0; l < JT_PER_; l++) {
        CP_WAIT0();
        __syncthreads();
        if (l + 1 < JT_PER_) {
            const int jt = js * JT_PER_ + l + 1;
            const uint4* bs = (const uint4*)(g_Bf16 + ((size_t)(h * (N_ / 64) + jt)) * 1024);
            uint32_t dB = sb + OFF_B + (buf ^ 1) * 8192;
#pragma unroll
            for (int r = 0; r < 4; r++) cp16(dB + (tid + r * 128) * 16, bs + tid + r * 128);
            CP_COMMIT();
        }

        const uint2*    Bp = (const uint2*)(dsm + OFF_B + buf * 8192);
        const uint2*    th = (const uint2*)(dsm + OFF_TH);
        const uint32_t* bt = (const uint32_t*)dsm;

        // pre-shifted mask sources: byte-k MSB of U holds adjacency bit 8k,
        // byte-k MSB of T holds bit 8k+1 (after tg alignment).
        uint32_t U0[4], T0s[4], U1[4], T1s[4];
#pragma unroll
        for (int q = 0; q < 4; q++) {
            int rl = wbase + g + q * 8;
            uint32_t v0 = bt[rl * BPITCH + l * 2]     >> (tg * 2);
            uint32_t v1 = bt[rl * BPITCH + l * 2 + 1] >> (tg * 2);
            U0[q] = v0 << 7;  T0s[q] = v0 << 6;
            U1[q] = v1 << 7;  T1s[q] = v1 << 6;
        }
#pragma unroll
        for (int ks = 0; ks < 4; ks++) {
            uint2 Ta = th[l * 32 + ks * 8 + tg];
            uint2 Tb = th[l * 32 + ks * 8 + tg + 4];
            __half2 t0e2  = *reinterpret_cast<__half2*>(&Ta.x);
            __half2 t0e2a = *reinterpret_cast<__half2*>(&Ta.y);
            __half2 t1e2  = *reinterpret_cast<__half2*>(&Tb.x);
            __half2 t1e2a = *reinterpret_cast<__half2*>(&Tb.y);
            const uint32_t selLo = (ks & 1) ? 0xEEAAu : 0xCC88u;
            const uint32_t selHi = (ks & 1) ? 0xFFBBu : 0xDD99u;
            uint32_t A[2][4];
#pragma unroll
            for (int q = 0; q < 4; q++) {
                uint32_t uu = (ks < 2) ? U0[q] : U1[q];
                uint32_t tt = (ks < 2) ? T0s[q] : T1s[q];
                uint32_t mlo = prmt_sign(uu, tt, selLo);
                uint32_t mhi = prmt_sign(uu, tt, selHi);
                __half2 wlo = __hmax2(__hmul2(e1b[q], t0e2), __hmul2(e1ab[q], t0e2a));
                __half2 whi = __hmax2(__hmul2(e1b[q], t1e2), __hmul2(e1ab[q], t1e2a));
                A[q >> 1][q & 1]       = *reinterpret_cast<uint32_t*>(&wlo) & mlo;
                A[q >> 1][2 + (q & 1)] = *reinterpret_cast<uint32_t*>(&whi) & mhi;
            }
#pragma unroll
            for (int nf = 0; nf < 8; nf++) {
                uint2 b = Bp[(ks * 8 + nf) * 32 + lane];
#pragma unroll
                for (int mf = 0; mf < 2; mf++)
                    mma16816(acc[mf][nf], A[mf], b.x, b.y);
            }
#pragma unroll
            for (int mf = 0; mf < 2; mf++)
                mma16816(acc[mf][8], A[mf], bones, bones);
        }
        buf ^= 1;
    }

    const size_t nbase = ((size_t)(js * M_ + m) * N_);
#pragma unroll
    for (int mf = 0; mf < 2; mf++) {
        int r0 = i0 + wbase + mf * 16 + g;
        int r1 = r0 + 8;
#pragma unroll
        for (int nf = 0; nf < 8; nf++) {
            int col = h * D_ + nf * 8 + tg * 2;
            *(float2*)(g_pnum + (nbase + r0) * (H_ * D_) + col) =
                make_float2(acc[mf][nf][0], acc[mf][nf][1]);
            *(float2*)(g_pnum + (nbase + r1) * (H_ * D_) + col) =
                make_float2(acc[mf][nf][2], acc[mf][nf][3]);
        }
        if (tg == 0) {
            float* dp = g_pden + ((size_t)(js * M_ + m) * H_ + h) * N_;
            dp[r0] = acc[mf][8][0];
            dp[r1] = acc[mf][8][2];
        }
    }
}

// ============================================================
// Kernel 4: combine splits: num/den, elu, sum over m (beta==1)
// ============================================================
__device__ __forceinline__ float elu1(float v) { return v > 0.f ? v : expm1f(v); }
__global__ __launch_bounds__(256) void combine_kernel(float* __restrict__ out) {
    const int n = blockIdx.x;
    const int t = threadIdx.x;
    const int h = t >> 6;
    float accv = 0.f;
#pragma unroll
    for (int m = 0; m < M_; m++) {
        float num = 0.f, den = 0.f;
#pragma unroll
        for (int js = 0; js < JS_; js++) {
            int p = js * M_ + m;
            num += g_pnum[((size_t)p * N_ + n) * (H_ * D_) + t];
            den += g_pden[((size_t)p * H_ + h) * N_ + n];
        }
        accv += elu1(num / den);
    }
    out[(size_t)n * (H_ * D_) + t] = accv;
}

extern "C" void kernel_launch(void* const* d_in, const int* in_sizes, int n_in,
                              void* d_out, int out_size) {
    const float* x   = (const float*)d_in[0];
    const int*   adj = (const int*)d_in[1];
    const float* W   = (const float*)d_in[2];
    const float* a1  = (const float*)d_in[3];
    const float* a2  = (const float*)d_in[4];
    // d_in[5..7] (Ws, bs, q_sem) dead: softmax over singleton axis -> beta == 1
    float* out = (float*)d_out;

    cudaFuncSetAttribute(att_mma, cudaFuncAttributeMaxDynamicSharedMemorySize, SMEM_ATT);
    cudaFuncSetAttribute(whmm, cudaFuncAttributeMaxDynamicSharedMemorySize, SMEM_WH);

    pack_adj<<<(M_ * N_) / 8, 256>>>(adj);
    split_kernel<<<(N_ * F_ / 4) / 256 + (H_ * F_ * D_ + 255) / 256, 256>>>(x, W);
    whmm<<<dim3(N_ / 64, H_), 128, SMEM_WH>>>(a1, a2);
    att_mma<<<dim3(N_ / 128, H_ * JS_, M_), 128, SMEM_ATT>>>();
    combine_kernel<<<N_, 256>>>(out);
}

// round 15
// speedup vs baseline: 8.5806x; 1.0198x over previous
#include <cuda_runtime.h>
#include <cuda_fp16.h>
#include <math.h>
#include <cstdint>

#define N_ 4096
#define F_ 512
#define D_ 64
#define H_ 4
#define M_ 2
#define JS_ 4
#define JT_PER_ 16            // (N_/64)/JS_
#define ALPHA_ 0.2f
#define L2E_ 1.44269504f

// ---- device scratch (no allocation allowed) ----
__device__ float    g_Wh[(size_t)H_ * N_ * D_];
__device__ float    g_s1[H_ * N_];
__device__ float2   g_tbl[H_ * N_];                            // (e2, e2a) fp32
__device__ unsigned g_S2Mu[H_];                                // flipped-float atomic max
__device__ uint32_t g_adjbits[(size_t)M_ * N_ * (N_ / 32)];
__device__ uint2    g_Bf16[(size_t)H_ * (N_ / 64) * 1024];     // fp16 frag tiles
__device__ float    g_pnum[(size_t)JS_ * M_ * N_ * H_ * D_];   // [js][m][n][h*64+d]
__device__ float    g_pden[(size_t)JS_ * M_ * H_ * N_];        // [js][m][h][n]
// split-fp16 operands for whmm
__device__ __half   g_xh[(size_t)N_ * F_], g_xl[(size_t)N_ * F_];
__device__ __half   g_wth[(size_t)H_ * D_ * F_], g_wtl[(size_t)H_ * D_ * F_];

__device__ __forceinline__ uint32_t smem_u32(const void* p) {
    uint32_t a;
    asm("{ .reg .u64 t; cvta.to.shared.u64 t, %1; cvt.u32.u64 %0, t; }" : "=r"(a) : "l"(p));
    return a;
}
__device__ __forceinline__ void cp16(uint32_t dst, const void* src) {
    asm volatile("cp.async.cg.shared.global [%0], [%1], 16;" :: "r"(dst), "l"(src));
}
#define CP_COMMIT() asm volatile("cp.async.commit_group;" ::: "memory")
#define CP_WAIT0()  asm volatile("cp.async.wait_group 0;" ::: "memory")

// PRMT sign-replication via asm (intrinsic __byte_perm is unsafe for nibbles>=8)
__device__ __forceinline__ uint32_t prmt_sign(uint32_t a, uint32_t b, uint32_t s) {
    uint32_t d;
    asm("prmt.b32 %0, %1, %2, %3;" : "=r"(d) : "r"(a), "r"(b), "r"(s));
    return d;
}

__device__ __forceinline__ unsigned flipf(float f) {
    unsigned u = __float_as_uint(f);
    return (u & 0x80000000u) ? ~u : (u | 0x80000000u);
}
__device__ __forceinline__ float unflipf(unsigned v) {
    return (v & 0x80000000u) ? __uint_as_float(v & 0x7FFFFFFFu)
                             : __uint_as_float(~v);
}
__device__ __forceinline__ void mma16816(float* c, const uint32_t* a,
                                         uint32_t b0, uint32_t b1) {
    asm volatile(
        "mma.sync.aligned.m16n8k16.row.col.f32.f16.f16.f32 "
        "{%0,%1,%2,%3}, {%4,%5,%6,%7}, {%8,%9}, {%0,%1,%2,%3};"
        : "+f"(c[0]), "+f"(c[1]), "+f"(c[2]), "+f"(c[3])
        : "r"(a[0]), "r"(a[1]), "r"(a[2]), "r"(a[3]), "r"(b0), "r"(b1));
}

// ============================================================
// Kernel 0 (fused prep): pack adj bitmask || split x/W to fp16
// Grid concat: [0,1024) pack, [1024,3072) x-split, [3072,3584) W-split.
// ============================================================
#define PREP_PACK_BLKS  1024
#define PREP_X_BLKS     2048
#define PREP_W_BLKS     512
#define PREP_BLKS       (PREP_PACK_BLKS + PREP_X_BLKS + PREP_W_BLKS)

__global__ __launch_bounds__(256) void prep(const int* __restrict__ adj,
                                            const float* __restrict__ x,
                                            const float* __restrict__ W) {
    const int bid = blockIdx.x;
    if (bid < PREP_PACK_BLKS) {
        if (bid == 0 && threadIdx.x < H_) g_S2Mu[threadIdx.x] = 0u;
        const int r = (bid * 256 + threadIdx.x) >> 5;
        const int lane = threadIdx.x & 31;
        const int4* src = (const int4*)(adj + (size_t)r * N_);
#pragma unroll 4
        for (int i = 0; i < 32; i++) {
            int4 a = src[i * 32 + lane];
            uint32_t nib = (a.x != 0 ? 1u : 0u) | (a.y != 0 ? 2u : 0u)
                         | (a.z != 0 ? 4u : 0u) | (a.w != 0 ? 8u : 0u);
            uint32_t val = nib << ((lane & 7) * 4);
            val |= __shfl_xor_sync(0xffffffffu, val, 1);
            val |= __shfl_xor_sync(0xffffffffu, val, 2);
            val |= __shfl_xor_sync(0xffffffffu, val, 4);
            if ((lane & 7) == 0)
                g_adjbits[(size_t)r * 128 + i * 4 + (lane >> 3)] = val;
        }
    } else if (bid < PREP_PACK_BLKS + PREP_X_BLKS) {
        int i4 = (bid - PREP_PACK_BLKS) * 256 + threadIdx.x;
        float4 v = ((const float4*)x)[i4];
        __half2 h01 = __floats2half2_rn(v.x, v.y);
        __half2 h23 = __floats2half2_rn(v.z, v.w);
        float2 f01 = __half22float2(h01), f23 = __half22float2(h23);
        __half2 l01 = __floats2half2_rn(v.x - f01.x, v.y - f01.y);
        __half2 l23 = __floats2half2_rn(v.z - f23.x, v.w - f23.y);
        uint2 uh, ul;
        uh.x = *reinterpret_cast<uint32_t*>(&h01);
        uh.y = *reinterpret_cast<uint32_t*>(&h23);
        ul.x = *reinterpret_cast<uint32_t*>(&l01);
        ul.y = *reinterpret_cast<uint32_t*>(&l23);
        ((uint2*)g_xh)[i4] = uh;
        ((uint2*)g_xl)[i4] = ul;
    } else {
        int idx = (bid - PREP_PACK_BLKS - PREP_X_BLKS) * 256 + threadIdx.x;
        int hh = idx >> 15, rem = idx & 32767;
        int f = rem >> 6, d = rem & 63;
        float v = W[idx];
        __half hv = __float2half_rn(v);
        __half lv = __float2half_rn(v - __half2float(hv));
        int o = ((hh << 6) + d) * F_ + f;
        g_wth[o] = hv;
        g_wtl[o] = lv;
    }
}

// ============================================================
// Kernel 1: whmm — Wh = x @ W via split-fp16 tensor mma.
// CTA = (64-row tile jt, head h), 128 thr.
// Epilogue: g_Wh stores, B-frag emit, AND fused s1/s2/exp tables.
// ============================================================
#define WSM_BUF 36864
#define OFF_A1  18432
#define OFF_A2  (OFF_A1 + 256)
#define SMEM_WH (2 * WSM_BUF)

__global__ __launch_bounds__(128) void whmm(const float* __restrict__ a1,
                                            const float* __restrict__ a2) {
    extern __shared__ char dsm[];
    const uint32_t sb = smem_u32(dsm);
    const int jt = blockIdx.x, h = blockIdx.y;
    const int i0 = jt * 64;
    const int tid = threadIdx.x;
    const int wid = tid >> 5, lane = tid & 31;
    const int g = lane >> 2, tg = lane & 3;
    const int wrow = wid * 16;

    auto stage = [&](int buf, int kc) {
        uint32_t base = sb + buf * WSM_BUF;
        const size_t xoff = (size_t)i0 * F_ + kc * 64;
        const size_t woff = (size_t)(h * 64) * F_ + kc * 64;
#pragma unroll
        for (int it = 0; it < 4; it++) {
            int q = tid + it * 128;
            int row = q >> 3, seg = q & 7;
            uint32_t d = (uint32_t)(row * 144 + seg * 16);
            cp16(base + d,         g_xh  + xoff + (size_t)row * F_ + seg * 8);
            cp16(base + 9216 + d,  g_xl  + xoff + (size_t)row * F_ + seg * 8);
            cp16(base + 18432 + d, g_wth + woff + (size_t)row * F_ + seg * 8);
            cp16(base + 27648 + d, g_wtl + woff + (size_t)row * F_ + seg * 8);
        }
        CP_COMMIT();
    };

    stage(0, 0);
    float acc[8][4] = {};

    int buf = 0;
    for (int kc = 0; kc < 8; kc++) {
        CP_WAIT0();
        __syncthreads();
        if (kc < 7) stage(buf ^ 1, kc + 1);
        const __half* sxh = (const __half*)(dsm + buf * WSM_BUF);
        const __half* sxl = sxh + 4608;
        const __half* swh = sxh + 9216;
        const __half* swl = sxh + 13824;
#pragma unroll
        for (int ks = 0; ks < 4; ks++) {
            const int c0 = ks * 16 + tg * 2, c1 = c0 + 8;
            const int r0 = (wrow + g) * 72, r1 = (wrow + g + 8) * 72;
            uint32_t ah[4], al[4];
            ah[0] = *(const uint32_t*)(sxh + r0 + c0);
            ah[1] = *(const uint32_t*)(sxh + r1 + c0);
            ah[2] = *(const uint32_t*)(sxh + r0 + c1);
            ah[3] = *(const uint32_t*)(sxh + r1 + c1);
            al[0] = *(const uint32_t*)(sxl + r0 + c0);
            al[1] = *(const uint32_t*)(sxl + r1 + c0);
            al[2] = *(const uint32_t*)(sxl + r0 + c1);
            al[3] = *(const uint32_t*)(sxl + r1 + c1);
#pragma unroll
            for (int nf = 0; nf < 8; nf++) {
                const int n = (nf * 8 + g) * 72;
                uint32_t bh0 = *(const uint32_t*)(swh + n + c0);
                uint32_t bh1 = *(const uint32_t*)(swh + n + c1);
                uint32_t bl0 = *(const uint32_t*)(swl + n + c0);
                uint32_t bl1 = *(const uint32_t*)(swl + n + c1);
                mma16816(acc[nf], ah, bh0, bh1);
                mma16816(acc[nf], ah, bl0, bl1);
                mma16816(acc[nf], al, bh0, bh1);
            }
        }
        buf ^= 1;
        __syncthreads();
    }

    const int rg = i0 + wrow + g;
#pragma unroll
    for (int nf = 0; nf < 8; nf++) {
        int c = nf * 8 + tg * 2;
        *(float2*)(g_Wh + ((size_t)h * N_ + rg) * D_ + c) =
            make_float2(acc[nf][0], acc[nf][1]);
        *(float2*)(g_Wh + ((size_t)h * N_ + rg + 8) * D_ + c) =
            make_float2(acc[nf][2], acc[nf][3]);
    }
    float* sC = (float*)dsm;
#pragma unroll
    for (int nf = 0; nf < 8; nf++) {
        int c = nf * 8 + tg * 2;
        int rr = wrow + g;
        sC[rr * 68 + c]           = acc[nf][0];
        sC[rr * 68 + c + 1]       = acc[nf][1];
        sC[(rr + 8) * 68 + c]     = acc[nf][2];
        sC[(rr + 8) * 68 + c + 1] = acc[nf][3];
    }
    float* a1s = (float*)(dsm + OFF_A1);
    float* a2s = (float*)(dsm + OFF_A2);
    if (tid < 64) {
        a1s[tid] = a1[h * D_ + tid];
        a2s[tid] = a2[h * D_ + tid];
    }
    __syncthreads();

    uint2* dst = g_Bf16 + ((size_t)(h * (N_ / 64) + jt)) * 1024;
#pragma unroll
    for (int it = 0; it < 8; it++) {
        int o = tid + it * 128;
        int frag = o >> 5, ln = o & 31;
        int ks = frag >> 3, nf = frag & 7;
        int g2 = ln >> 2, tg2 = ln & 3;
        int jlo = ks * 16 + tg2 * 2;
        int n = nf * 8 + g2;
        __half2 lo = __floats2half2_rn(sC[jlo * 68 + n],       sC[(jlo + 1) * 68 + n]);
        __half2 hi = __floats2half2_rn(sC[(jlo + 8) * 68 + n], sC[(jlo + 9) * 68 + n]);
        uint2 v;
        v.x = *reinterpret_cast<uint32_t*>(&lo);
        v.y = *reinterpret_cast<uint32_t*>(&hi);
        dst[o] = v;
    }

    {
        const int row  = tid >> 1;
        const int half = tid & 1;
        const float* rp = sC + row * 68 + half * 32;
        const float* ap1 = a1s + half * 32;
        const float* ap2 = a2s + half * 32;
        float p1 = 0.f, p2 = 0.f;
#pragma unroll
        for (int d = 0; d < 32; d++) {
            float v = rp[d];
            p1 += v * ap1[d];
            p2 += v * ap2[d];
        }
        p1 += __shfl_xor_sync(0xffffffffu, p1, 1);
        p2 += __shfl_xor_sync(0xffffffffu, p2, 1);
        if (half == 0) {
            int gg = h * N_ + i0 + row;
            g_s1[gg] = p1;
            g_tbl[gg] = make_float2(expf(p2), expf(ALPHA_ * p2));
        }
        float mx = p2;
#pragma unroll
        for (int o = 16; o; o >>= 1)
            mx = fmaxf(mx, __shfl_xor_sync(0xffffffffu, mx, o));
        if (lane == 0) atomicMax(&g_S2Mu[h], flipf(mx));
    }
}

// ============================================================
// Kernel 3: masked attention, mma.m16n8k16 fp16, j-split.
// 64-row i-tile (1 m-frag/warp) for 6 CTAs/SM occupancy.
// ============================================================
#define BPITCH   36
#define OFF_BM   0
#define OFF_B    9216                 // bitmask: 64 * 36 * 4
#define OFF_TH   (OFF_B + 16384)      // B: 2 * 8KB
#define OFF_E    (OFF_TH + 4096)      // table: 1024 j * 4B
#define SMEM_ATT (OFF_E + 512)        // e1: 64 * float2

__global__ __launch_bounds__(128, 6) void att_mma() {
    extern __shared__ char dsm[];
    const uint32_t sb = smem_u32(dsm);

    const int i0 = blockIdx.x * 64;
    const int h  = blockIdx.y & (H_ - 1);
    const int js = blockIdx.y >> 2;
    const int m  = blockIdx.z;
    const int tid = threadIdx.x;
    const int wid = tid >> 5, lane = tid & 31;
    const int g = lane >> 2, tg = lane & 3;
    const int wbase = wid * 16;
    const int jb = js * (N_ / JS_);

    // stage bitmask slice (64 rows x 32 words) + first B tile
    {
        const uint32_t* bsrc = g_adjbits + ((size_t)m * N_ + i0) * (N_ / 32) + js * 32;
#pragma unroll
        for (int it = 0; it < 4; it++) {
            int q = tid + it * 128;          // 512 = 64 rows * 8 cp16
            int row = q >> 3, w4 = q & 7;
            cp16(sb + row * (BPITCH * 4) + w4 * 16,
                 bsrc + (size_t)row * (N_ / 32) + w4 * 4);
        }
        const uint4* bs = (const uint4*)(g_Bf16 +
            ((size_t)(h * (N_ / 64) + js * JT_PER_)) * 1024);
#pragma unroll
        for (int r = 0; r < 4; r++)
            cp16(sb + OFF_B + (tid + r * 128) * 16, bs + tid + r * 128);
    }
    CP_COMMIT();

    // convert j-table to packed half2 pairs in SMEM (persistent)
    {
        __half* th = (__half*)(dsm + OFF_TH);
#pragma unroll
        for (int it = 0; it < 8; it++) {
            int jl = tid + it * 128;
            float2 t = g_tbl[h * N_ + jb + jl];
            int base = (jl >> 1) * 4 + (jl & 1);
            th[base]     = __float2half_rn(t.x);
            th[base + 2] = __float2half_rn(t.y);
        }
    }
    // per-row e1/e1a with power-of-2 softmax-invariant scaling
    if (tid < 64) {
        float s1 = g_s1[h * N_ + i0 + tid];
        float s2m = unflipf(g_S2Mu[h]);
        float t = s1 + s2m;
        float b = t > 0.f ? t : ALPHA_ * t;
        float e = 9.f - floorf(b * L2E_);
        float2* se1 = (float2*)(dsm + OFF_E);
        se1[tid] = make_float2(exp2f(s1 * L2E_ + e), exp2f(ALPHA_ * s1 * L2E_ + e));
    }
    __syncthreads();

    __half2 e1b[2], e1ab[2];
#pragma unroll
    for (int q = 0; q < 2; q++) {
        float2 v = ((const float2*)(dsm + OFF_E))[wbase + g + q * 8];
        e1b[q]  = __float2half2_rn(v.x);
        e1ab[q] = __float2half2_rn(v.y);
    }
    const uint32_t bones = (g == 0) ? 0x3C003C00u : 0u;

    float acc[9][4];
#pragma unroll
    for (int b = 0; b < 9; b++)
#pragma unroll
        for (int c = 0; c < 4; c++) acc[b][c] = 0.f;

    int buf = 0;
    for (int l = 0; l < JT_PER_; l++) {
        CP_WAIT0();
        __syncthreads();
        if (l + 1 < JT_PER_) {
            const int jt = js * JT_PER_ + l + 1;
            const uint4* bs = (const uint4*)(g_Bf16 + ((size_t)(h * (N_ / 64) + jt)) * 1024);
            uint32_t dB = sb + OFF_B + (buf ^ 1) * 8192;
#pragma unroll
            for (int r = 0; r < 4; r++) cp16(dB + (tid + r * 128) * 16, bs + tid + r * 128);
            CP_COMMIT();
        }

        const uint2*    Bp = (const uint2*)(dsm + OFF_B + buf * 8192);
        const uint2*    th = (const uint2*)(dsm + OFF_TH);
        const uint32_t* bt = (const uint32_t*)dsm;

        uint32_t v0[2], v1[2];
#pragma unroll
        for (int q = 0; q < 2; q++) {
            int rl = wbase + g + q * 8;
            v0[q] = bt[rl * BPITCH + l * 2]     >> (tg * 2);
            v1[q] = bt[rl * BPITCH + l * 2 + 1] >> (tg * 2);
        }
#pragma unroll
        for (int ks = 0; ks < 4; ks++) {
            uint2 Ta = th[l * 32 + ks * 8 + tg];
            uint2 Tb = th[l * 32 + ks * 8 + tg + 4];
            __half2 t0e2  = *reinterpret_cast<__half2*>(&Ta.x);
            __half2 t0e2a = *reinterpret_cast<__half2*>(&Ta.y);
            __half2 t1e2  = *reinterpret_cast<__half2*>(&Tb.x);
            __half2 t1e2a = *reinterpret_cast<__half2*>(&Tb.y);
            const uint32_t selLo = (ks & 1) ? 0xEEAAu : 0xCC88u;
            const uint32_t selHi = (ks & 1) ? 0xFFBBu : 0xDD99u;
            uint32_t A[4];
#pragma unroll
            for (int q = 0; q < 2; q++) {
                uint32_t vv0 = (ks < 2) ? v0[q] : v1[q];
                uint32_t uu = vv0 << 7, tt = vv0 << 6;
                uint32_t mlo = prmt_sign(uu, tt, selLo);
                uint32_t mhi = prmt_sign(uu, tt, selHi);
                __half2 wlo = __hmax2(__hmul2(e1b[q], t0e2), __hmul2(e1ab[q], t0e2a));
                __half2 whi = __hmax2(__hmul2(e1b[q], t1e2), __hmul2(e1ab[q], t1e2a));
                A[q]     = *reinterpret_cast<uint32_t*>(&wlo) & mlo;
                A[2 + q] = *reinterpret_cast<uint32_t*>(&whi) & mhi;
            }
#pragma unroll
            for (int nf = 0; nf < 8; nf++) {
                uint2 b = Bp[(ks * 8 + nf) * 32 + lane];
                mma16816(acc[nf], A, b.x, b.y);
            }
            mma16816(acc[8], A, bones, bones);
        }
        buf ^= 1;
    }

    // epilogue: raw partial num + den
    const size_t nbase = ((size_t)(js * M_ + m) * N_);
    {
        int r0 = i0 + wbase + g;
        int r1 = r0 + 8;
#pragma unroll
        for (int nf = 0; nf < 8; nf++) {
            int col = h * D_ + nf * 8 + tg * 2;
            *(float2*)(g_pnum + (nbase + r0) * (H_ * D_) + col) =
                make_float2(acc[nf][0], acc[nf][1]);
            *(float2*)(g_pnum + (nbase + r1) * (H_ * D_) + col) =
                make_float2(acc[nf][2], acc[nf][3]);
        }
        if (tg == 0) {
            float* dp = g_pden + ((size_t)(js * M_ + m) * H_ + h) * N_;
            dp[r0] = acc[8][0];
            dp[r1] = acc[8][2];
        }
    }
}

// ============================================================
// Kernel 4: combine splits: num/den, elu, sum over m (beta==1)
// ============================================================
__device__ __forceinline__ float elu1(float v) { return v > 0.f ? v : expm1f(v); }
__global__ __launch_bounds__(256) void combine_kernel(float* __restrict__ out) {
    const int n = blockIdx.x;
    const int t = threadIdx.x;
    const int h = t >> 6;
    float accv = 0.f;
#pragma unroll
    for (int m = 0; m < M_; m++) {
        float num = 0.f, den = 0.f;
#pragma unroll
        for (int js = 0; js < JS_; js++) {
            int p = js * M_ + m;
            num += g_pnum[((size_t)p * N_ + n) * (H_ * D_) + t];
            den += g_pden[((size_t)p * H_ + h) * N_ + n];
        }
        accv += elu1(num / den);
    }
    out[(size_t)n * (H_ * D_) + t] = accv;
}

extern "C" void kernel_launch(void* const* d_in, const int* in_sizes, int n_in,
                              void* d_out, int out_size) {
    const float* x   = (const float*)d_in[0];
    const int*   adj = (const int*)d_in[1];
    const float* W   = (const float*)d_in[2];
    const float* a1  = (const float*)d_in[3];
    const float* a2  = (const float*)d_in[4];
    // d_in[5..7] (Ws, bs, q_sem) dead: softmax over singleton axis -> beta == 1
    float* out = (float*)d_out;

    cudaFuncSetAttribute(att_mma, cudaFuncAttributeMaxDynamicSharedMemorySize, SMEM_ATT);
    cudaFuncSetAttribute(whmm, cudaFuncAttributeMaxDynamicSharedMemorySize, SMEM_WH);

    prep<<<PREP_BLKS, 256>>>(adj, x, W);
    whmm<<<dim3(N_ / 64, H_), 128, SMEM_WH>>>(a1, a2);
    att_mma<<<dim3(N_ / 64, H_ * JS_, M_), 128, SMEM_ATT>>>();
    combine_kernel<<<N_, 256>>>(out);
}

// round 17
// speedup vs baseline: 8.7187x; 1.0161x over previous
#include <cuda_runtime.h>
#include <cuda_fp16.h>
#include <math.h>
#include <cstdint>

#define N_ 4096
#define F_ 512
#define D_ 64
#define H_ 4
#define M_ 2
#define JS_ 4
#define JT_PER_ 16            // (N_/64)/JS_
#define ALPHA_ 0.2f
#define L2E_ 1.44269504f

// ---- device scratch (no allocation allowed) ----
__device__ float    g_Wh[(size_t)H_ * N_ * D_];
__device__ float    g_s1[H_ * N_];
__device__ __half   g_tblh[(size_t)H_ * N_ * 2];               // packed {e2pair,e2apair}
__device__ unsigned g_S2Mu[H_];                                // flipped-float atomic max
__device__ uint32_t g_adjbits[(size_t)M_ * N_ * (N_ / 32)];
__device__ uint2    g_Bf16[(size_t)H_ * (N_ / 64) * 1024];     // fp16 frag tiles
__device__ float    g_pnum[(size_t)JS_ * M_ * N_ * H_ * D_];   // [js][m][n][h*64+d]
__device__ float    g_pden[(size_t)JS_ * M_ * H_ * N_];        // [js][m][h][n]
// split-fp16 operands for whmm
__device__ __half   g_xh[(size_t)N_ * F_], g_xl[(size_t)N_ * F_];
__device__ __half   g_wth[(size_t)H_ * D_ * F_], g_wtl[(size_t)H_ * D_ * F_];

__device__ __forceinline__ uint32_t smem_u32(const void* p) {
    uint32_t a;
    asm("{ .reg .u64 t; cvta.to.shared.u64 t, %1; cvt.u32.u64 %0, t; }" : "=r"(a) : "l"(p));
    return a;
}
__device__ __forceinline__ void cp16(uint32_t dst, const void* src) {
    asm volatile("cp.async.cg.shared.global [%0], [%1], 16;" :: "r"(dst), "l"(src));
}
#define CP_COMMIT() asm volatile("cp.async.commit_group;" ::: "memory")
#define CP_WAIT0()  asm volatile("cp.async.wait_group 0;" ::: "memory")

// PRMT sign-replication via asm (intrinsic __byte_perm is unsafe for nibbles>=8)
__device__ __forceinline__ uint32_t prmt_sign(uint32_t a, uint32_t b, uint32_t s) {
    uint32_t d;
    asm("prmt.b32 %0, %1, %2, %3;" : "=r"(d) : "r"(a), "r"(b), "r"(s));
    return d;
}

__device__ __forceinline__ unsigned flipf(float f) {
    unsigned u = __float_as_uint(f);
    return (u & 0x80000000u) ? ~u : (u | 0x80000000u);
}
__device__ __forceinline__ float unflipf(unsigned v) {
    return (v & 0x80000000u) ? __uint_as_float(v & 0x7FFFFFFFu)
                             : __uint_as_float(~v);
}
__device__ __forceinline__ void mma16816(float* c, const uint32_t* a,
                                         uint32_t b0, uint32_t b1) {
    asm volatile(
        "mma.sync.aligned.m16n8k16.row.col.f32.f16.f16.f32 "
        "{%0,%1,%2,%3}, {%4,%5,%6,%7}, {%8,%9}, {%0,%1,%2,%3};"
        : "+f"(c[0]), "+f"(c[1]), "+f"(c[2]), "+f"(c[3])
        : "r"(a[0]), "r"(a[1]), "r"(a[2]), "r"(a[3]), "r"(b0), "r"(b1));
}

// ============================================================
// Kernel 0 (fused prep): pack adj bitmask || split x/W to fp16
// ============================================================
#define PREP_PACK_BLKS  1024
#define PREP_X_BLKS     2048
#define PREP_W_BLKS     512
#define PREP_BLKS       (PREP_PACK_BLKS + PREP_X_BLKS + PREP_W_BLKS)

__global__ __launch_bounds__(256) void prep(const int* __restrict__ adj,
                                            const float* __restrict__ x,
                                            const float* __restrict__ W) {
    const int bid = blockIdx.x;
    if (bid < PREP_PACK_BLKS) {
        if (bid == 0 && threadIdx.x < H_) g_S2Mu[threadIdx.x] = 0u;
        const int r = (bid * 256 + threadIdx.x) >> 5;
        const int lane = threadIdx.x & 31;
        const int4* src = (const int4*)(adj + (size_t)r * N_);
#pragma unroll 4
        for (int i = 0; i < 32; i++) {
            int4 a = src[i * 32 + lane];
            uint32_t nib = (a.x != 0 ? 1u : 0u) | (a.y != 0 ? 2u : 0u)
                         | (a.z != 0 ? 4u : 0u) | (a.w != 0 ? 8u : 0u);
            uint32_t val = nib << ((lane & 7) * 4);
            val |= __shfl_xor_sync(0xffffffffu, val, 1);
            val |= __shfl_xor_sync(0xffffffffu, val, 2);
            val |= __shfl_xor_sync(0xffffffffu, val, 4);
            if ((lane & 7) == 0)
                g_adjbits[(size_t)r * 128 + i * 4 + (lane >> 3)] = val;
        }
    } else if (bid < PREP_PACK_BLKS + PREP_X_BLKS) {
        int i4 = (bid - PREP_PACK_BLKS) * 256 + threadIdx.x;
        float4 v = ((const float4*)x)[i4];
        __half2 h01 = __floats2half2_rn(v.x, v.y);
        __half2 h23 = __floats2half2_rn(v.z, v.w);
        float2 f01 = __half22float2(h01), f23 = __half22float2(h23);
        __half2 l01 = __floats2half2_rn(v.x - f01.x, v.y - f01.y);
        __half2 l23 = __floats2half2_rn(v.z - f23.x, v.w - f23.y);
        uint2 uh, ul;
        uh.x = *reinterpret_cast<uint32_t*>(&h01);
        uh.y = *reinterpret_cast<uint32_t*>(&h23);
        ul.x = *reinterpret_cast<uint32_t*>(&l01);
        ul.y = *reinterpret_cast<uint32_t*>(&l23);
        ((uint2*)g_xh)[i4] = uh;
        ((uint2*)g_xl)[i4] = ul;
    } else {
        int idx = (bid - PREP_PACK_BLKS - PREP_X_BLKS) * 256 + threadIdx.x;
        int hh = idx >> 15, rem = idx & 32767;
        int f = rem >> 6, d = rem & 63;
        float v = W[idx];
        __half hv = __float2half_rn(v);
        __half lv = __float2half_rn(v - __half2float(hv));
        int o = ((hh << 6) + d) * F_ + f;
        g_wth[o] = hv;
        g_wtl[o] = lv;
    }
}

// ============================================================
// Kernel 1: whmm — Wh = x @ W via split-fp16 tensor mma.
// Epilogue: g_Wh stores, B-frag emit, fused s1/packed-half-table/s2max.
// ============================================================
#define WSM_BUF 36864
#define OFF_A1  18432
#define OFF_A2  (OFF_A1 + 256)
#define SMEM_WH (2 * WSM_BUF)

__global__ __launch_bounds__(128) void whmm(const float* __restrict__ a1,
                                            const float* __restrict__ a2) {
    extern __shared__ char dsm[];
    const uint32_t sb = smem_u32(dsm);
    const int jt = blockIdx.x, h = blockIdx.y;
    const int i0 = jt * 64;
    const int tid = threadIdx.x;
    const int wid = tid >> 5, lane = tid & 31;
    const int g = lane >> 2, tg = lane & 3;
    const int wrow = wid * 16;

    auto stage = [&](int buf, int kc) {
        uint32_t base = sb + buf * WSM_BUF;
        const size_t xoff = (size_t)i0 * F_ + kc * 64;
        const size_t woff = (size_t)(h * 64) * F_ + kc * 64;
#pragma unroll
        for (int it = 0; it < 4; it++) {
            int q = tid + it * 128;
            int row = q >> 3, seg = q & 7;
            uint32_t d = (uint32_t)(row * 144 + seg * 16);
            cp16(base + d,         g_xh  + xoff + (size_t)row * F_ + seg * 8);
            cp16(base + 9216 + d,  g_xl  + xoff + (size_t)row * F_ + seg * 8);
            cp16(base + 18432 + d, g_wth + woff + (size_t)row * F_ + seg * 8);
            cp16(base + 27648 + d, g_wtl + woff + (size_t)row * F_ + seg * 8);
        }
        CP_COMMIT();
    };

    stage(0, 0);
    float acc[8][4] = {};

    int buf = 0;
    for (int kc = 0; kc < 8; kc++) {
        CP_WAIT0();
        __syncthreads();
        if (kc < 7) stage(buf ^ 1, kc + 1);
        const __half* sxh = (const __half*)(dsm + buf * WSM_BUF);
        const __half* sxl = sxh + 4608;
        const __half* swh = sxh + 9216;
        const __half* swl = sxh + 13824;
#pragma unroll
        for (int ks = 0; ks < 4; ks++) {
            const int c0 = ks * 16 + tg * 2, c1 = c0 + 8;
            const int r0 = (wrow + g) * 72, r1 = (wrow + g + 8) * 72;
            uint32_t ah[4], al[4];
            ah[0] = *(const uint32_t*)(sxh + r0 + c0);
            ah[1] = *(const uint32_t*)(sxh + r1 + c0);
            ah[2] = *(const uint32_t*)(sxh + r0 + c1);
            ah[3] = *(const uint32_t*)(sxh + r1 + c1);
            al[0] = *(const uint32_t*)(sxl + r0 + c0);
            al[1] = *(const uint32_t*)(sxl + r1 + c0);
            al[2] = *(const uint32_t*)(sxl + r0 + c1);
            al[3] = *(const uint32_t*)(sxl + r1 + c1);
#pragma unroll
            for (int nf = 0; nf < 8; nf++) {
                const int n = (nf * 8 + g) * 72;
                uint32_t bh0 = *(const uint32_t*)(swh + n + c0);
                uint32_t bh1 = *(const uint32_t*)(swh + n + c1);
                uint32_t bl0 = *(const uint32_t*)(swl + n + c0);
                uint32_t bl1 = *(const uint32_t*)(swl + n + c1);
                mma16816(acc[nf], ah, bh0, bh1);
                mma16816(acc[nf], ah, bl0, bl1);
                mma16816(acc[nf], al, bh0, bh1);
            }
        }
        buf ^= 1;
        __syncthreads();
    }

    const int rg = i0 + wrow + g;
#pragma unroll
    for (int nf = 0; nf < 8; nf++) {
        int c = nf * 8 + tg * 2;
        *(float2*)(g_Wh + ((size_t)h * N_ + rg) * D_ + c) =
            make_float2(acc[nf][0], acc[nf][1]);
        *(float2*)(g_Wh + ((size_t)h * N_ + rg + 8) * D_ + c) =
            make_float2(acc[nf][2], acc[nf][3]);
    }
    float* sC = (float*)dsm;
#pragma unroll
    for (int nf = 0; nf < 8; nf++) {
        int c = nf * 8 + tg * 2;
        int rr = wrow + g;
        sC[rr * 68 + c]           = acc[nf][0];
        sC[rr * 68 + c + 1]       = acc[nf][1];
        sC[(rr + 8) * 68 + c]     = acc[nf][2];
        sC[(rr + 8) * 68 + c + 1] = acc[nf][3];
    }
    float* a1s = (float*)(dsm + OFF_A1);
    float* a2s = (float*)(dsm + OFF_A2);
    if (tid < 64) {
        a1s[tid] = a1[h * D_ + tid];
        a2s[tid] = a2[h * D_ + tid];
    }
    __syncthreads();

    uint2* dst = g_Bf16 + ((size_t)(h * (N_ / 64) + jt)) * 1024;
#pragma unroll
    for (int it = 0; it < 8; it++) {
        int o = tid + it * 128;
        int frag = o >> 5, ln = o & 31;
        int ks = frag >> 3, nf = frag & 7;
        int g2 = ln >> 2, tg2 = ln & 3;
        int jlo = ks * 16 + tg2 * 2;
        int n = nf * 8 + g2;
        __half2 lo = __floats2half2_rn(sC[jlo * 68 + n],       sC[(jlo + 1) * 68 + n]);
        __half2 hi = __floats2half2_rn(sC[(jlo + 8) * 68 + n], sC[(jlo + 9) * 68 + n]);
        uint2 v;
        v.x = *reinterpret_cast<uint32_t*>(&lo);
        v.y = *reinterpret_cast<uint32_t*>(&hi);
        dst[o] = v;
    }

    // fused se: s1 per row, packed half2 exp table, s2 max
    {
        const int row  = tid >> 1;
        const int half = tid & 1;
        const float* rp = sC + row * 68 + half * 32;
        const float* ap1 = a1s + half * 32;
        const float* ap2 = a2s + half * 32;
        float p1 = 0.f, p2 = 0.f;
#pragma unroll
        for (int d = 0; d < 32; d++) {
            float v = rp[d];
            p1 += v * ap1[d];
            p2 += v * ap2[d];
        }
        p1 += __shfl_xor_sync(0xffffffffu, p1, 1);
        p2 += __shfl_xor_sync(0xffffffffu, p2, 1);
        if (half == 0) {
            int j = i0 + row;                    // this node acts as column j
            g_s1[h * N_ + j] = p1;
            int o = h * 2 * N_ + (j >> 1) * 4 + (j & 1);
            g_tblh[o]     = __float2half_rn(expf(p2));
            g_tblh[o + 2] = __float2half_rn(expf(ALPHA_ * p2));
        }
        float mx = p2;
#pragma unroll
        for (int o = 16; o; o >>= 1)
            mx = fmaxf(mx, __shfl_xor_sync(0xffffffffu, mx, o));
        if (lane == 0) atomicMax(&g_S2Mu[h], flipf(mx));
    }
}

// ============================================================
// Kernel 3: masked attention, mma.m16n8k16 fp16, j-split.
// 64-row i-tile, 6 CTAs/SM; packed table cp.async-staged.
// ============================================================
#define BPITCH   36
#define OFF_B    9216                 // bitmask: 64 * 36 * 4
#define OFF_TH   (OFF_B + 16384)      // B: 2 * 8KB
#define OFF_E    (OFF_TH + 4096)      // table: 1024 j * 4B
#define SMEM_ATT (OFF_E + 512)        // e1: 64 * float2

__global__ __launch_bounds__(128, 6) void att_mma() {
    extern __shared__ char dsm[];
    const uint32_t sb = smem_u32(dsm);

    const int i0 = blockIdx.x * 64;
    const int h  = blockIdx.y & (H_ - 1);
    const int js = blockIdx.y >> 2;
    const int m  = blockIdx.z;
    const int tid = threadIdx.x;
    const int wid = tid >> 5, lane = tid & 31;
    const int g = lane >> 2, tg = lane & 3;
    const int wbase = wid * 16;
    const int jb = js * (N_ / JS_);

    // stage bitmask slice + first B tile + packed j-table (one group)
    {
        const uint32_t* bsrc = g_adjbits + ((size_t)m * N_ + i0) * (N_ / 32) + js * 32;
#pragma unroll
        for (int it = 0; it < 4; it++) {
            int q = tid + it * 128;
            int row = q >> 3, w4 = q & 7;
            cp16(sb + row * (BPITCH * 4) + w4 * 16,
                 bsrc + (size_t)row * (N_ / 32) + w4 * 4);
        }
        const uint4* bs = (const uint4*)(g_Bf16 +
            ((size_t)(h * (N_ / 64) + js * JT_PER_)) * 1024);
#pragma unroll
        for (int r = 0; r < 4; r++)
            cp16(sb + OFF_B + (tid + r * 128) * 16, bs + tid + r * 128);
        // table: 1024 j = 4KB contiguous
        const __half* ts = g_tblh + (size_t)h * 2 * N_ + jb * 2;
#pragma unroll
        for (int r = 0; r < 2; r++)
            cp16(sb + OFF_TH + (tid + r * 128) * 16, ts + (tid + r * 128) * 8);
    }
    CP_COMMIT();

    // per-row e1/e1a with power-of-2 softmax-invariant scaling
    if (tid < 64) {
        float s1 = g_s1[h * N_ + i0 + tid];
        float s2m = unflipf(g_S2Mu[h]);
        float t = s1 + s2m;
        float b = t > 0.f ? t : ALPHA_ * t;
        float e = 9.f - floorf(b * L2E_);
        float2* se1 = (float2*)(dsm + OFF_E);
        se1[tid] = make_float2(exp2f(s1 * L2E_ + e), exp2f(ALPHA_ * s1 * L2E_ + e));
    }
    CP_WAIT0();
    __syncthreads();

    __half2 e1b[2], e1ab[2];
#pragma unroll
    for (int q = 0; q < 2; q++) {
        float2 v = ((const float2*)(dsm + OFF_E))[wbase + g + q * 8];
        e1b[q]  = __float2half2_rn(v.x);
        e1ab[q] = __float2half2_rn(v.y);
    }
    const uint32_t bones = (g == 0) ? 0x3C003C00u : 0u;

    float acc[9][4];
#pragma unroll
    for (int b = 0; b < 9; b++)
#pragma unroll
        for (int c = 0; c < 4; c++) acc[b][c] = 0.f;

    int buf = 0;
    for (int l = 0; l < JT_PER_; l++) {
        if (l) { CP_WAIT0(); __syncthreads(); }
        if (l + 1 < JT_PER_) {
            const int jt = js * JT_PER_ + l + 1;
            const uint4* bs = (const uint4*)(g_Bf16 + ((size_t)(h * (N_ / 64) + jt)) * 1024);
            uint32_t dB = sb + OFF_B + (buf ^ 1) * 8192;
#pragma unroll
            for (int r = 0; r < 4; r++) cp16(dB + (tid + r * 128) * 16, bs + tid + r * 128);
            CP_COMMIT();
        }

        const uint2*    Bp = (const uint2*)(dsm + OFF_B + buf * 8192);
        const uint2*    th = (const uint2*)(dsm + OFF_TH);
        const uint32_t* bt = (const uint32_t*)dsm;

        uint32_t v0[2], v1[2];
#pragma unroll
        for (int q = 0; q < 2; q++) {
            int rl = wbase + g + q * 8;
            v0[q] = bt[rl * BPITCH + l * 2]     >> (tg * 2);
            v1[q] = bt[rl * BPITCH + l * 2 + 1] >> (tg * 2);
        }
#pragma unroll
        for (int ks = 0; ks < 4; ks++) {
            uint2 Ta = th[l * 32 + ks * 8 + tg];
            uint2 Tb = th[l * 32 + ks * 8 + tg + 4];
            __half2 t0e2  = *reinterpret_cast<__half2*>(&Ta.x);
            __half2 t0e2a = *reinterpret_cast<__half2*>(&Ta.y);
            __half2 t1e2  = *reinterpret_cast<__half2*>(&Tb.x);
            __half2 t1e2a = *reinterpret_cast<__half2*>(&Tb.y);
            const uint32_t selLo = (ks & 1) ? 0xEEAAu : 0xCC88u;
            const uint32_t selHi = (ks & 1) ? 0xFFBBu : 0xDD99u;
            uint32_t A[4];
#pragma unroll
            for (int q = 0; q < 2; q++) {
                uint32_t vv0 = (ks < 2) ? v0[q] : v1[q];
                uint32_t uu = vv0 << 7, tt = vv0 << 6;
                uint32_t mlo = prmt_sign(uu, tt, selLo);
                uint32_t mhi = prmt_sign(uu, tt, selHi);
                __half2 wlo = __hmax2(__hmul2(e1b[q], t0e2), __hmul2(e1ab[q], t0e2a));
                __half2 whi = __hmax2(__hmul2(e1b[q], t1e2), __hmul2(e1ab[q], t1e2a));
                A[q]     = *reinterpret_cast<uint32_t*>(&wlo) & mlo;
                A[2 + q] = *reinterpret_cast<uint32_t*>(&whi) & mhi;
            }
#pragma unroll
            for (int nf = 0; nf < 8; nf++) {
                uint2 b = Bp[(ks * 8 + nf) * 32 + lane];
                mma16816(acc[nf], A, b.x, b.y);
            }
            mma16816(acc[8], A, bones, bones);
        }
        buf ^= 1;
    }

    // epilogue: raw partial num + den
    const size_t nbase = ((size_t)(js * M_ + m) * N_);
    {
        int r0 = i0 + wbase + g;
        int r1 = r0 + 8;
#pragma unroll
        for (int nf = 0; nf < 8; nf++) {
            int col = h * D_ + nf * 8 + tg * 2;
            *(float2*)(g_pnum + (nbase + r0) * (H_ * D_) + col) =
                make_float2(acc[nf][0], acc[nf][1]);
            *(float2*)(g_pnum + (nbase + r1) * (H_ * D_) + col) =
                make_float2(acc[nf][2], acc[nf][3]);
        }
        if (tg == 0) {
            float* dp = g_pden + ((size_t)(js * M_ + m) * H_ + h) * N_;
            dp[r0] = acc[8][0];
            dp[r1] = acc[8][2];
        }
    }
}

// ============================================================
// Kernel 4: combine splits (float4): num/den, elu, sum over m
// ============================================================
__device__ __forceinline__ float elu1(float v) { return v > 0.f ? v : expm1f(v); }
__global__ __launch_bounds__(256) void combine_kernel(float* __restrict__ out) {
    const int n  = blockIdx.x * 4 + (threadIdx.x >> 6);
    const int t4 = threadIdx.x & 63;          // float4 slot: cols t4*4..+3
    const int h  = t4 >> 4;
    float4 accv = make_float4(0.f, 0.f, 0.f, 0.f);
#pragma unroll
    for (int m = 0; m < M_; m++) {
        float4 num = make_float4(0.f, 0.f, 0.f, 0.f);
        float den = 0.f;
#pragma unroll
        for (int js = 0; js < JS_; js++) {
            int p = js * M_ + m;
            float4 v = *(const float4*)(g_pnum + ((size_t)p * N_ + n) * (H_ * D_) + t4 * 4);
            num.x += v.x; num.y += v.y; num.z += v.z; num.w += v.w;
            den += g_pden[((size_t)p * H_ + h) * N_ + n];
        }
        accv.x += elu1(num.x / den);
        accv.y += elu1(num.y / den);
        accv.z += elu1(num.z / den);
        accv.w += elu1(num.w / den);
    }
    *(float4*)(out + (size_t)n * (H_ * D_) + t4 * 4) = accv;
}

extern "C" void kernel_launch(void* const* d_in, const int* in_sizes, int n_in,
                              void* d_out, int out_size) {
    const float* x   = (const float*)d_in[0];
    const int*   adj = (const int*)d_in[1];
    const float* W   = (const float*)d_in[2];
    const float* a1  = (const float*)d_in[3];
    const float* a2  = (const float*)d_in[4];
    // d_in[5..7] (Ws, bs, q_sem) dead: softmax over singleton axis -> beta == 1
    float* out = (float*)d_out;

    cudaFuncSetAttribute(att_mma, cudaFuncAttributeMaxDynamicSharedMemorySize, SMEM_ATT);
    cudaFuncSetAttribute(whmm, cudaFuncAttributeMaxDynamicSharedMemorySize, SMEM_WH);

    prep<<<PREP_BLKS, 256>>>(adj, x, W);
    whmm<<<dim3(N_ / 64, H_), 128, SMEM_WH>>>(a1, a2);
    att_mma<<<dim3(N_ / 64, H_ * JS_, M_), 128, SMEM_ATT>>>();
    combine_kernel<<<N_ / 4, 256>>>(out);
}